// round 10
// baseline (speedup 1.0000x reference)
#include <cuda_runtime.h>
#include <cuda_bf16.h>
#include <cstdint>
#include <math.h>

// ---------------- problem constants ----------------
#define NB     2
#define TT     2048
#define BT     4096      // NB*TT tokens
#define DM     2048
#define NH     16
#define DH     128
#define CH     144       // NH + DH
#define RQ     6
#define RKV    4
#define NQ     864       // RQ*CH
#define NKV    576       // RKV*CH

// ---------------- scratch (device globals; no allocs allowed) ----------------
__device__ float g_abq [BT * NQ];
__device__ float g_abkv[BT * NKV];

// bf16 hi/lo split scratch
__device__ __nv_bfloat16 g_xh [BT * DM],  g_xl [BT * DM];
__device__ __nv_bfloat16 g_wqh[NQ * DM],  g_wql[NQ * DM];
__device__ __nv_bfloat16 g_wkh[NKV * DM], g_wkl[NKV * DM];
__device__ __nv_bfloat16 g_woh[DM * DM],  g_wol[DM * DM];
__device__ __nv_bfloat16 g_yh [BT * DM],  g_yl [BT * DM];

// q/k/v bf16 hi/lo, layout [b,h,t,d]
#define QKV_ELEMS (NB * NH * TT * DH)
__device__ __nv_bfloat16 g_qh[QKV_ELEMS], g_ql[QKV_ELEMS];
__device__ __nv_bfloat16 g_kh[QKV_ELEMS], g_kl[QKV_ELEMS];
__device__ __nv_bfloat16 g_vh[QKV_ELEMS], g_vl[QKV_ELEMS];

// ================= helpers =================
__device__ __forceinline__ uint32_t smem_u32(const void* p) {
    uint32_t a;
    asm("{ .reg .u64 t; cvta.to.shared.u64 t, %1; cvt.u32.u64 %0, t; }" : "=r"(a) : "l"(p));
    return a;
}
#define SWZ(o)  ((o) ^ (((o) >> 3) & 0x70))   // 128B-row swizzle (GEMM tiles)
#define ASW(o)  ((o) ^ (((o) >> 4) & 0x70))   // 256B-row swizzle (attn tiles)

__device__ __forceinline__ void ldsm4(uint32_t* r, uint32_t addr) {
    asm volatile("ldmatrix.sync.aligned.m8n8.x4.shared.b16 {%0,%1,%2,%3}, [%4];"
        : "=r"(r[0]), "=r"(r[1]), "=r"(r[2]), "=r"(r[3]) : "r"(addr));
}
__device__ __forceinline__ void ldsm4t(uint32_t* r, uint32_t addr) {
    asm volatile("ldmatrix.sync.aligned.m8n8.x4.trans.shared.b16 {%0,%1,%2,%3}, [%4];"
        : "=r"(r[0]), "=r"(r[1]), "=r"(r[2]), "=r"(r[3]) : "r"(addr));
}
__device__ __forceinline__ void mma_bf16(float* c, const uint32_t* a, const uint32_t* b) {
    asm volatile("mma.sync.aligned.m16n8k16.row.col.f32.bf16.bf16.f32 "
        "{%0,%1,%2,%3}, {%4,%5,%6,%7}, {%8,%9}, {%0,%1,%2,%3};"
        : "+f"(c[0]), "+f"(c[1]), "+f"(c[2]), "+f"(c[3])
        : "r"(a[0]), "r"(a[1]), "r"(a[2]), "r"(a[3]), "r"(b[0]), "r"(b[1]));
}
#define CP_ASYNC(dst, src, sz) \
    asm volatile("cp.async.cg.shared.global [%0], [%1], 16, %2;" \
        :: "r"(dst), "l"(src), "r"(sz) : "memory")
#define CP_COMMIT() asm volatile("cp.async.commit_group;" ::: "memory")
#define CP_WAIT(n)  asm volatile("cp.async.wait_group %0;" :: "n"(n) : "memory")

__device__ __forceinline__ uint32_t pack_bf2(__nv_bfloat16 lo, __nv_bfloat16 hi) {
    __nv_bfloat162 t; t.x = lo; t.y = hi;
    return *reinterpret_cast<uint32_t*>(&t);
}

// ======================================================================
// fused fp32 -> bf16 hi/lo split of all four tensors (one launch)
// ======================================================================
__global__ __launch_bounds__(256) void conv_all(
    const float* __restrict__ s0, __nv_bfloat16* __restrict__ h0, __nv_bfloat16* __restrict__ l0, int n0,
    const float* __restrict__ s1, __nv_bfloat16* __restrict__ h1, __nv_bfloat16* __restrict__ l1, int n1,
    const float* __restrict__ s2, __nv_bfloat16* __restrict__ h2, __nv_bfloat16* __restrict__ l2, int n2,
    const float* __restrict__ s3, __nv_bfloat16* __restrict__ h3, __nv_bfloat16* __restrict__ l3, int n3)
{
    int i = blockIdx.x * 256 + threadIdx.x;
    const float* s; __nv_bfloat16 *h, *l; int j;
    if (i < n0)                     { s = s0; h = h0; l = l0; j = i; }
    else if (i < n0 + n1)           { s = s1; h = h1; l = l1; j = i - n0; }
    else if (i < n0 + n1 + n2)      { s = s2; h = h2; l = l2; j = i - n0 - n1; }
    else if (i < n0 + n1 + n2 + n3) { s = s3; h = h3; l = l3; j = i - n0 - n1 - n2; }
    else return;
    float v = s[j];
    __nv_bfloat16 hi = __float2bfloat16(v);
    h[j] = hi;
    l[j] = __float2bfloat16(v - __bfloat162float(hi));
}

// ======================================================================
// mma.sync bf16-split NT GEMM body: 16 warps, 3-stage pipeline,
// pass-major MMA order (8 independent HMMAs per pass).
// ======================================================================
#define TILE_B   16384
#define BUF_B    (4 * TILE_B)
#define GEMM_SMEM (3 * BUF_B + 1024)

__device__ __forceinline__ void gemm_body(
    const __nv_bfloat16* __restrict__ Ah, const __nv_bfloat16* __restrict__ Al,
    const __nv_bfloat16* __restrict__ Bh, const __nv_bfloat16* __restrict__ Bl,
    float* __restrict__ C, int N, int K, int bm, int bn, uint32_t smem)
{
    const int tid  = threadIdx.x;
    const int wid  = tid >> 5, lane = tid & 31;
    const int wm   = (wid >> 2) * 32;
    const int wn   = (wid & 3) * 32;
    const int nchunk = K >> 6;

    auto load_chunk = [&](int c, int buf) {
        const uint32_t base = smem + buf * BUF_B;
        const int k0 = c * 64;
#pragma unroll
        for (int u = tid; u < 1024; u += 512) {
            int row = u >> 3, seg = u & 7;
            uint32_t so = SWZ((uint32_t)(row * 128 + seg * 16));
            size_t ga = (size_t)(bm + row) * K + k0 + seg * 8;
            CP_ASYNC(base + so,              Ah + ga, 16);
            CP_ASYNC(base + TILE_B + so,     Al + ga, 16);
            int n = bn + row;
            int sz = (n < N) ? 16 : 0;
            size_t gb = (size_t)(n < N ? n : 0) * K + k0 + seg * 8;
            CP_ASYNC(base + 2 * TILE_B + so, Bh + gb, sz);
            CP_ASYNC(base + 3 * TILE_B + so, Bl + gb, sz);
        }
        CP_COMMIT();
    };

    float acc[2][4][4];
#pragma unroll
    for (int i = 0; i < 2; i++)
#pragma unroll
        for (int j = 0; j < 4; j++)
#pragma unroll
            for (int q = 0; q < 4; q++) acc[i][j][q] = 0.f;

    load_chunk(0, 0);
    if (nchunk > 1) load_chunk(1, 1);
    if (nchunk > 2) load_chunk(2, 2);

    int buf = 0;
    for (int c = 0; c < nchunk; c++) {
        if (c + 2 < nchunk)      { CP_WAIT(2); }
        else if (c + 1 < nchunk) { CP_WAIT(1); }
        else                     { CP_WAIT(0); }
        __syncthreads();

        const uint32_t sa_h = smem + buf * BUF_B;
        const uint32_t sa_l = sa_h + TILE_B;
        const uint32_t sb_h = sa_h + 2 * TILE_B;
        const uint32_t sb_l = sa_h + 3 * TILE_B;

#pragma unroll
        for (int ks = 0; ks < 4; ks++) {
            const int kk = ks * 16;
            uint32_t ah[2][4], al[2][4], bh[2][4], bl[2][4];
            {
                int r = lane & 15, ck = lane >> 4;
#pragma unroll
                for (int mt = 0; mt < 2; mt++) {
                    uint32_t off = SWZ((uint32_t)((wm + mt * 16 + r) * 128 + (kk + ck * 8) * 2));
                    ldsm4(ah[mt], sa_h + off);
                    ldsm4(al[mt], sa_l + off);
                }
            }
            {
                int grp = lane >> 3, ln = lane & 7;
#pragma unroll
                for (int np = 0; np < 2; np++) {
                    int n = wn + np * 16 + (grp >> 1) * 8 + ln;
                    int kc = kk + (grp & 1) * 8;
                    uint32_t off = SWZ((uint32_t)(n * 128 + kc * 2));
                    ldsm4(bh[np], sb_h + off);
                    ldsm4(bl[np], sb_l + off);
                }
            }
            // pass-major: 8 independent HMMAs per pass
#pragma unroll
            for (int mt = 0; mt < 2; mt++)
#pragma unroll
                for (int nt = 0; nt < 4; nt++)
                    mma_bf16(acc[mt][nt], ah[mt], &bh[nt >> 1][(nt & 1) * 2]);
#pragma unroll
            for (int mt = 0; mt < 2; mt++)
#pragma unroll
                for (int nt = 0; nt < 4; nt++)
                    mma_bf16(acc[mt][nt], ah[mt], &bl[nt >> 1][(nt & 1) * 2]);
#pragma unroll
            for (int mt = 0; mt < 2; mt++)
#pragma unroll
                for (int nt = 0; nt < 4; nt++)
                    mma_bf16(acc[mt][nt], al[mt], &bh[nt >> 1][(nt & 1) * 2]);
        }
        __syncthreads();
        if (c + 3 < nchunk) load_chunk(c + 3, buf);
        buf = (buf == 2) ? 0 : buf + 1;
    }

#pragma unroll
    for (int mt = 0; mt < 2; mt++) {
        int r0 = bm + wm + mt * 16 + (lane >> 2);
#pragma unroll
        for (int nt = 0; nt < 4; nt++) {
            int col = bn + wn + nt * 8 + (lane & 3) * 2;
            if (col < N) {
                float* c0 = C + (size_t)r0 * N + col;
                float* c1 = C + (size_t)(r0 + 8) * N + col;
                c0[0] = acc[mt][nt][0]; c0[1] = acc[mt][nt][1];
                c1[0] = acc[mt][nt][2]; c1[1] = acc[mt][nt][3];
            }
        }
    }
}

__global__ __launch_bounds__(512) void gemm_mma512(
    const __nv_bfloat16* __restrict__ Ah, const __nv_bfloat16* __restrict__ Al,
    const __nv_bfloat16* __restrict__ Bh, const __nv_bfloat16* __restrict__ Bl,
    float* __restrict__ C, int N, int K)
{
    extern __shared__ char smraw[];
    const uint32_t smem0 = smem_u32(smraw);
    const uint32_t smem  = (smem0 + 1023) & ~1023u;
    gemm_body(Ah, Al, Bh, Bl, C, N, K, blockIdx.y * 128, blockIdx.x * 128, smem);
}

#define QTILES 7
__global__ __launch_bounds__(512) void gemm_qkv(
    const __nv_bfloat16* __restrict__ Ah, const __nv_bfloat16* __restrict__ Al)
{
    extern __shared__ char smraw[];
    const uint32_t smem0 = smem_u32(smraw);
    const uint32_t smem  = (smem0 + 1023) & ~1023u;
    const int bx = blockIdx.x;
    if (bx < QTILES)
        gemm_body(Ah, Al, g_wqh, g_wql, g_abq, NQ, DM,
                  blockIdx.y * 128, bx * 128, smem);
    else
        gemm_body(Ah, Al, g_wkh, g_wkl, g_abkv, NKV, DM,
                  blockIdx.y * 128, (bx - QTILES) * 128, smem);
}

// ======================================================================
// qkv: rank contraction + rotary (fp32 trig) -> bf16 hi/lo q,k,v [b,h,t,d]
// ======================================================================
__global__ __launch_bounds__(128) void qkv_kernel()
{
    const int m = blockIdx.x;
    const int b = m >> 11;
    const int t = m & (TT - 1);
    const int d = threadIdx.x;

    __shared__ float aq  [RQ][16];
    __shared__ float bq  [RQ][128];
    __shared__ float akv [RKV][16];
    __shared__ float braw[RKV][128];
    __shared__ float brot[RKV][128];

    const float* abq = g_abq + (size_t)m * NQ;
    for (int idx = d; idx < NQ; idx += 128) {
        int r = idx / CH, c = idx - r * CH;
        float v = abq[idx];
        if (c < 16) aq[r][c] = v; else bq[r][c - 16] = v;
    }
    const float* abkv = g_abkv + (size_t)m * NKV;
    for (int idx = d; idx < NKV; idx += 128) {
        int r = idx / CH, c = idx - r * CH;
        float v = abkv[idx];
        if (c < 16) akv[r][c] = v; else braw[r][c - 16] = v;
    }
    __syncthreads();

    {
        int j = d & 63;
        float inv = powf(1e-4f, (float)j * (1.f / 64.f));   // (1/10000)^(j/64)
        float sv, cv;
        sincosf((float)t * inv, &sv, &cv);
#pragma unroll
        for (int r = 0; r < RKV; r++) {
            float x1 = braw[r][j], x2 = braw[r][j + 64];
            brot[r][d] = (d < 64) ? (x1 * cv + x2 * sv) : (-x1 * sv + x2 * cv);
        }
    }

    const size_t base = (((size_t)b * NH) * TT + t) * DH + d;
#pragma unroll
    for (int h = 0; h < NH; h++) {
        float qv = 0.f;
#pragma unroll
        for (int r = 0; r < RQ; r++) qv += aq[r][h] * bq[r][d];
        qv *= (1.f / 6.f);
        float kv = (akv[0][h] * brot[0][d] + akv[1][h] * brot[1][d]) * 0.5f;
        float vv = (akv[2][h] * brot[2][d] + akv[3][h] * brot[3][d]) * 0.5f;
        size_t o = base + (size_t)h * TT * DH;
        __nv_bfloat16 qhh = __float2bfloat16(qv);
        __nv_bfloat16 khh = __float2bfloat16(kv);
        __nv_bfloat16 vhh = __float2bfloat16(vv);
        g_qh[o] = qhh; g_ql[o] = __float2bfloat16(qv - __bfloat162float(qhh));
        g_kh[o] = khh; g_kl[o] = __float2bfloat16(kv - __bfloat162float(khh));
        g_vh[o] = vhh; g_vl[o] = __float2bfloat16(vv - __bfloat162float(vhh));
    }
}

// ======================================================================
// flash attention, causal, mma.sync bf16 split.
// grid (T/128, NH, NB), 256 threads (8 warps x 16 q-rows), 2-stage K/V,
// Q in smem (re-ldsm per iter; low reg pressure), pass-major MMA order.
// ======================================================================
#define ATTN_SMEM (196608 + 1024)

__global__ __launch_bounds__(256) void attn_mma()
{
    extern __shared__ char smraw[];
    const uint32_t sb0 = smem_u32(smraw);
    const uint32_t sb = (sb0 + 1023) & ~1023u;

    const int tid = threadIdx.x, wid = tid >> 5, lane = tid & 31;
    const int qt = (int)gridDim.x - 1 - (int)blockIdx.x;   // heavy tiles first
    const int h = blockIdx.y, b = blockIdx.z;
    const size_t bh = ((size_t)b * NH + h) * TT;
    const int nkt = 2 * qt + 2;

    const uint32_t sQh = sb, sQl = sb + 32768;

    {
        const char* qh = (const char*)g_qh + (bh + (size_t)qt * 128) * 256;
        const char* ql = (const char*)g_ql + (bh + (size_t)qt * 128) * 256;
        for (int u = tid; u < 2048; u += 256) {
            int row = u >> 4, seg = u & 15;
            uint32_t off = ASW((uint32_t)(row * 256 + seg * 16));
            int go = row * 256 + seg * 16;
            CP_ASYNC(sQh + off, qh + go, 16);
            CP_ASYNC(sQl + off, ql + go, 16);
        }
    }
    auto load_kv = [&](int kt, int s) {
        uint32_t base = sb + 65536 + (uint32_t)s * 65536;
        const char* kh = (const char*)g_kh + (bh + (size_t)kt * 64) * 256;
        const char* kl = (const char*)g_kl + (bh + (size_t)kt * 64) * 256;
        const char* vh = (const char*)g_vh + (bh + (size_t)kt * 64) * 256;
        const char* vl = (const char*)g_vl + (bh + (size_t)kt * 64) * 256;
        for (int u = tid; u < 1024; u += 256) {
            int row = u >> 4, seg = u & 15;
            uint32_t off = ASW((uint32_t)(row * 256 + seg * 16));
            int go = row * 256 + seg * 16;
            CP_ASYNC(base + off,         kh + go, 16);
            CP_ASYNC(base + 16384 + off, kl + go, 16);
            CP_ASYNC(base + 32768 + off, vh + go, 16);
            CP_ASYNC(base + 49152 + off, vl + go, 16);
        }
        CP_COMMIT();
    };
    load_kv(0, 0);
    if (nkt > 1) load_kv(1, 1);

    float oacc[16][4];
#pragma unroll
    for (int dt = 0; dt < 16; dt++)
#pragma unroll
        for (int e = 0; e < 4; e++) oacc[dt][e] = 0.f;
    float rM0 = -1e30f, rM1 = -1e30f, rL0 = 0.f, rL1 = 0.f;

    const float scale = 0.08838834764831845f;
    const int r0g = qt * 128 + wid * 16 + (lane >> 2);

    for (int kt = 0; kt < nkt; kt++) {
        const int s = kt & 1;
        if (kt + 1 < nkt) { CP_WAIT(1); } else { CP_WAIT(0); }
        __syncthreads();
        const uint32_t base = sb + 65536 + (uint32_t)s * 65536;
        const uint32_t sKh = base, sKl = base + 16384;
        const uint32_t sVh = base + 32768, sVl = base + 49152;

        float sacc[8][4];
#pragma unroll
        for (int nt = 0; nt < 8; nt++)
#pragma unroll
            for (int e = 0; e < 4; e++) sacc[nt][e] = 0.f;

        // ---- S = Q K^T, pass-major (8 independent HMMAs per pass) ----
#pragma unroll
        for (int ks = 0; ks < 8; ks++) {
            uint32_t ah[4], al[4];
            {
                int r = lane & 15, ck = lane >> 4;
                uint32_t off = ASW((uint32_t)((wid * 16 + r) * 256 + (ks * 16 + ck * 8) * 2));
                ldsm4(ah, sQh + off);
                ldsm4(al, sQl + off);
            }
            uint32_t bh4[4][4], bl4[4][4];
            {
                int grp = lane >> 3, ln = lane & 7;
#pragma unroll
                for (int ng = 0; ng < 4; ng++) {
                    int n = ng * 16 + (grp >> 1) * 8 + ln;
                    int kc = ks * 16 + (grp & 1) * 8;
                    uint32_t off = ASW((uint32_t)(n * 256 + kc * 2));
                    ldsm4(bh4[ng], sKh + off);
                    ldsm4(bl4[ng], sKl + off);
                }
            }
#pragma unroll
            for (int ng = 0; ng < 4; ng++) {
                mma_bf16(sacc[ng * 2],     ah, bh4[ng]);
                mma_bf16(sacc[ng * 2 + 1], ah, bh4[ng] + 2);
            }
#pragma unroll
            for (int ng = 0; ng < 4; ng++) {
                mma_bf16(sacc[ng * 2],     ah, bl4[ng]);
                mma_bf16(sacc[ng * 2 + 1], ah, bl4[ng] + 2);
            }
#pragma unroll
            for (int ng = 0; ng < 4; ng++) {
                mma_bf16(sacc[ng * 2],     al, bh4[ng]);
                mma_bf16(sacc[ng * 2 + 1], al, bh4[ng] + 2);
            }
        }

        const bool domask = (kt >= 2 * qt);
        float mx0 = -1e30f, mx1 = -1e30f;
#pragma unroll
        for (int nt = 0; nt < 8; nt++) {
            int c0 = kt * 64 + nt * 8 + (lane & 3) * 2;
#pragma unroll
            for (int e = 0; e < 4; e++) {
                float v = sacc[nt][e] * scale;
                if (domask) {
                    int cc = c0 + (e & 1);
                    int rr = r0g + ((e >> 1) << 3);
                    if (cc > rr) v = -1e30f;
                }
                sacc[nt][e] = v;
            }
            mx0 = fmaxf(mx0, fmaxf(sacc[nt][0], sacc[nt][1]));
            mx1 = fmaxf(mx1, fmaxf(sacc[nt][2], sacc[nt][3]));
        }
        mx0 = fmaxf(mx0, __shfl_xor_sync(0xffffffffu, mx0, 1));
        mx0 = fmaxf(mx0, __shfl_xor_sync(0xffffffffu, mx0, 2));
        mx1 = fmaxf(mx1, __shfl_xor_sync(0xffffffffu, mx1, 1));
        mx1 = fmaxf(mx1, __shfl_xor_sync(0xffffffffu, mx1, 2));

        float nM0 = fmaxf(rM0, mx0), nM1 = fmaxf(rM1, mx1);
        float cor0 = __expf(rM0 - nM0), cor1 = __expf(rM1 - nM1);
        rM0 = nM0; rM1 = nM1;

        float sum0 = 0.f, sum1 = 0.f;
        uint32_t pH01[8], pH23[8], pL01[8], pL23[8];
#pragma unroll
        for (int nt = 0; nt < 8; nt++) {
            float p0 = __expf(sacc[nt][0] - nM0);
            float p1 = __expf(sacc[nt][1] - nM0);
            float p2 = __expf(sacc[nt][2] - nM1);
            float p3 = __expf(sacc[nt][3] - nM1);
            sum0 += p0 + p1; sum1 += p2 + p3;
            __nv_bfloat16 h0 = __float2bfloat16(p0), h1 = __float2bfloat16(p1);
            __nv_bfloat16 h2 = __float2bfloat16(p2), h3 = __float2bfloat16(p3);
            pH01[nt] = pack_bf2(h0, h1);
            pH23[nt] = pack_bf2(h2, h3);
            pL01[nt] = pack_bf2(__float2bfloat16(p0 - __bfloat162float(h0)),
                                __float2bfloat16(p1 - __bfloat162float(h1)));
            pL23[nt] = pack_bf2(__float2bfloat16(p2 - __bfloat162float(h2)),
                                __float2bfloat16(p3 - __bfloat162float(h3)));
        }
        sum0 += __shfl_xor_sync(0xffffffffu, sum0, 1);
        sum0 += __shfl_xor_sync(0xffffffffu, sum0, 2);
        sum1 += __shfl_xor_sync(0xffffffffu, sum1, 1);
        sum1 += __shfl_xor_sync(0xffffffffu, sum1, 2);
        rL0 = rL0 * cor0 + sum0;
        rL1 = rL1 * cor1 + sum1;

#pragma unroll
        for (int dt = 0; dt < 16; dt++) {
            oacc[dt][0] *= cor0; oacc[dt][1] *= cor0;
            oacc[dt][2] *= cor1; oacc[dt][3] *= cor1;
        }

        // ---- O += P V, pass-major over 4-dg groups ----
#pragma unroll
        for (int k2 = 0; k2 < 4; k2++) {
            uint32_t aH[4] = {pH01[2 * k2], pH23[2 * k2], pH01[2 * k2 + 1], pH23[2 * k2 + 1]};
            uint32_t aL[4] = {pL01[2 * k2], pL23[2 * k2], pL01[2 * k2 + 1], pL23[2 * k2 + 1]};
            int krow = k2 * 16 + ((lane >> 3) & 1) * 8 + (lane & 7);
#pragma unroll
            for (int dh2 = 0; dh2 < 2; dh2++) {
                uint32_t vh4[4][4], vl4[4][4];
#pragma unroll
                for (int dq = 0; dq < 4; dq++) {
                    int dcol = (dh2 * 4 + dq) * 16 + (lane >> 4) * 8;
                    uint32_t off = ASW((uint32_t)(krow * 256 + dcol * 2));
                    ldsm4t(vh4[dq], sVh + off);
                    ldsm4t(vl4[dq], sVl + off);
                }
#pragma unroll
                for (int dq = 0; dq < 4; dq++) {
                    int dg = dh2 * 4 + dq;
                    mma_bf16(oacc[dg * 2],     aH, vh4[dq]);
                    mma_bf16(oacc[dg * 2 + 1], aH, vh4[dq] + 2);
                }
#pragma unroll
                for (int dq = 0; dq < 4; dq++) {
                    int dg = dh2 * 4 + dq;
                    mma_bf16(oacc[dg * 2],     aH, vl4[dq]);
                    mma_bf16(oacc[dg * 2 + 1], aH, vl4[dq] + 2);
                }
#pragma unroll
                for (int dq = 0; dq < 4; dq++) {
                    int dg = dh2 * 4 + dq;
                    mma_bf16(oacc[dg * 2],     aL, vh4[dq]);
                    mma_bf16(oacc[dg * 2 + 1], aL, vh4[dq] + 2);
                }
            }
        }
        __syncthreads();
        if (kt + 2 < nkt) load_kv(kt + 2, s);
    }

    // ---- normalize + split + store bf16 hi/lo y ----
    float il0 = 1.f / rL0, il1 = 1.f / rL1;
    size_t row0 = ((size_t)b * TT + r0g) * DM + h * DH;
    size_t row1 = row0 + (size_t)8 * DM;
#pragma unroll
    for (int dt = 0; dt < 16; dt++) {
        int c = dt * 8 + (lane & 3) * 2;
        float v0 = oacc[dt][0] * il0, v1 = oacc[dt][1] * il0;
        float v2 = oacc[dt][2] * il1, v3 = oacc[dt][3] * il1;
        __nv_bfloat16 h0 = __float2bfloat16(v0), h1 = __float2bfloat16(v1);
        __nv_bfloat16 h2 = __float2bfloat16(v2), h3 = __float2bfloat16(v3);
        *(uint32_t*)(g_yh + row0 + c) = pack_bf2(h0, h1);
        *(uint32_t*)(g_yh + row1 + c) = pack_bf2(h2, h3);
        *(uint32_t*)(g_yl + row0 + c) = pack_bf2(__float2bfloat16(v0 - __bfloat162float(h0)),
                                                 __float2bfloat16(v1 - __bfloat162float(h1)));
        *(uint32_t*)(g_yl + row1 + c) = pack_bf2(__float2bfloat16(v2 - __bfloat162float(h2)),
                                                 __float2bfloat16(v3 - __bfloat162float(h3)));
    }
}

// ======================================================================
extern "C" void kernel_launch(void* const* d_in, const int* in_sizes, int n_in,
                              void* d_out, int out_size)
{
    const float* x   = (const float*)d_in[0];
    const float* Wq  = (const float*)d_in[1];
    const float* Wkv = (const float*)d_in[2];
    const float* Wo  = (const float*)d_in[3];
    float* out = (float*)d_out;

    __nv_bfloat16 *xh, *xl, *wqh, *wql, *wkh, *wkl, *woh, *wol, *yh, *yl;
    cudaGetSymbolAddress((void**)&xh,  g_xh);  cudaGetSymbolAddress((void**)&xl,  g_xl);
    cudaGetSymbolAddress((void**)&wqh, g_wqh); cudaGetSymbolAddress((void**)&wql, g_wql);
    cudaGetSymbolAddress((void**)&wkh, g_wkh); cudaGetSymbolAddress((void**)&wkl, g_wkl);
    cudaGetSymbolAddress((void**)&woh, g_woh); cudaGetSymbolAddress((void**)&wol, g_wol);
    cudaGetSymbolAddress((void**)&yh,  g_yh);  cudaGetSymbolAddress((void**)&yl,  g_yl);

    cudaFuncSetAttribute(gemm_mma512, cudaFuncAttributeMaxDynamicSharedMemorySize, GEMM_SMEM);
    cudaFuncSetAttribute(gemm_qkv,    cudaFuncAttributeMaxDynamicSharedMemorySize, GEMM_SMEM);
    cudaFuncSetAttribute(attn_mma,    cudaFuncAttributeMaxDynamicSharedMemorySize, ATTN_SMEM);

    // 0) fp32 -> bf16 hi/lo splits (x + all three weights, one launch)
    {
        int n0 = BT * DM, n1 = NQ * DM, n2 = NKV * DM, n3 = DM * DM;
        conv_all<<<(n0 + n1 + n2 + n3 + 255) / 256, 256>>>(
            x, xh, xl, n0, Wq, wqh, wql, n1, Wkv, wkh, wkl, n2, Wo, wol ? woh : woh, wol, n3);
    }
    // 1) fused ab_q / ab_kv projections (one launch, 384 CTAs)
    {
        dim3 g(QTILES + 5, BT / 128);
        gemm_qkv<<<g, 512, GEMM_SMEM>>>(xh, xl);
    }
    // 2) q,k,v (+rotary) -> bf16 hi/lo
    qkv_kernel<<<BT, 128>>>();
    // 3) causal attention (tensor cores) -> yh/yl directly   [profiled slot]
    {
        dim3 g(TT / 128, NH, NB);
        attn_mma<<<g, 256, ATTN_SMEM>>>();
    }
    // 4) out = y @ W_o^T (4096 x 2048)
    {
        dim3 g(DM / 128, BT / 128);
        gemm_mma512<<<g, 512, GEMM_SMEM>>>(yh, yl, woh, wol, out, DM, DM);
    }
}

// round 11
// speedup vs baseline: 1.0961x; 1.0961x over previous
#include <cuda_runtime.h>
#include <cuda_bf16.h>
#include <cstdint>
#include <math.h>

// ---------------- problem constants ----------------
#define NB     2
#define TT     2048
#define BT     4096      // NB*TT tokens
#define DM     2048
#define NH     16
#define DH     128
#define CH     144       // NH + DH
#define RQ     6
#define RKV    4
#define NQ     864       // RQ*CH
#define NKV    576       // RKV*CH

// ---------------- scratch (device globals; no allocs allowed) ----------------
__device__ float g_abq [BT * NQ];
__device__ float g_abkv[BT * NKV];

// bf16 hi/lo split scratch
__device__ __nv_bfloat16 g_xh [BT * DM],  g_xl [BT * DM];
__device__ __nv_bfloat16 g_wqh[NQ * DM],  g_wql[NQ * DM];
__device__ __nv_bfloat16 g_wkh[NKV * DM], g_wkl[NKV * DM];
__device__ __nv_bfloat16 g_woh[DM * DM],  g_wol[DM * DM];
__device__ __nv_bfloat16 g_yh [BT * DM],  g_yl [BT * DM];

// q/k/v bf16 hi/lo, layout [b,h,t,d]
#define QKV_ELEMS (NB * NH * TT * DH)
__device__ __nv_bfloat16 g_qh[QKV_ELEMS], g_ql[QKV_ELEMS];
__device__ __nv_bfloat16 g_kh[QKV_ELEMS], g_kl[QKV_ELEMS];
__device__ __nv_bfloat16 g_vh[QKV_ELEMS], g_vl[QKV_ELEMS];

// ================= helpers =================
__device__ __forceinline__ uint32_t smem_u32(const void* p) {
    uint32_t a;
    asm("{ .reg .u64 t; cvta.to.shared.u64 t, %1; cvt.u32.u64 %0, t; }" : "=r"(a) : "l"(p));
    return a;
}
#define SWZ(o)  ((o) ^ (((o) >> 3) & 0x70))   // 128B-row swizzle (GEMM tiles)
#define ASW(o)  ((o) ^ (((o) >> 4) & 0x70))   // 256B-row swizzle (attn tiles)

__device__ __forceinline__ void ldsm4(uint32_t* r, uint32_t addr) {
    asm volatile("ldmatrix.sync.aligned.m8n8.x4.shared.b16 {%0,%1,%2,%3}, [%4];"
        : "=r"(r[0]), "=r"(r[1]), "=r"(r[2]), "=r"(r[3]) : "r"(addr));
}
__device__ __forceinline__ void ldsm4t(uint32_t* r, uint32_t addr) {
    asm volatile("ldmatrix.sync.aligned.m8n8.x4.trans.shared.b16 {%0,%1,%2,%3}, [%4];"
        : "=r"(r[0]), "=r"(r[1]), "=r"(r[2]), "=r"(r[3]) : "r"(addr));
}
__device__ __forceinline__ void mma_bf16(float* c, const uint32_t* a, const uint32_t* b) {
    asm volatile("mma.sync.aligned.m16n8k16.row.col.f32.bf16.bf16.f32 "
        "{%0,%1,%2,%3}, {%4,%5,%6,%7}, {%8,%9}, {%0,%1,%2,%3};"
        : "+f"(c[0]), "+f"(c[1]), "+f"(c[2]), "+f"(c[3])
        : "r"(a[0]), "r"(a[1]), "r"(a[2]), "r"(a[3]), "r"(b[0]), "r"(b[1]));
}
#define CP_ASYNC(dst, src, sz) \
    asm volatile("cp.async.cg.shared.global [%0], [%1], 16, %2;" \
        :: "r"(dst), "l"(src), "r"(sz) : "memory")
#define CP_COMMIT() asm volatile("cp.async.commit_group;" ::: "memory")
#define CP_WAIT(n)  asm volatile("cp.async.wait_group %0;" :: "n"(n) : "memory")

__device__ __forceinline__ uint32_t pack_bf2(__nv_bfloat16 lo, __nv_bfloat16 hi) {
    __nv_bfloat162 t; t.x = lo; t.y = hi;
    return *reinterpret_cast<uint32_t*>(&t);
}

// ======================================================================
// fused fp32 -> bf16 hi/lo split of all four tensors (one launch)
// ======================================================================
__global__ __launch_bounds__(256) void conv_all(
    const float* __restrict__ s0, __nv_bfloat16* __restrict__ h0, __nv_bfloat16* __restrict__ l0, int n0,
    const float* __restrict__ s1, __nv_bfloat16* __restrict__ h1, __nv_bfloat16* __restrict__ l1, int n1,
    const float* __restrict__ s2, __nv_bfloat16* __restrict__ h2, __nv_bfloat16* __restrict__ l2, int n2,
    const float* __restrict__ s3, __nv_bfloat16* __restrict__ h3, __nv_bfloat16* __restrict__ l3, int n3)
{
    int i = blockIdx.x * 256 + threadIdx.x;
    const float* s; __nv_bfloat16 *h, *l; int j;
    if (i < n0)                     { s = s0; h = h0; l = l0; j = i; }
    else if (i < n0 + n1)           { s = s1; h = h1; l = l1; j = i - n0; }
    else if (i < n0 + n1 + n2)      { s = s2; h = h2; l = l2; j = i - n0 - n1; }
    else if (i < n0 + n1 + n2 + n3) { s = s3; h = h3; l = l3; j = i - n0 - n1 - n2; }
    else return;
    float v = s[j];
    __nv_bfloat16 hi = __float2bfloat16(v);
    h[j] = hi;
    l[j] = __float2bfloat16(v - __bfloat162float(hi));
}

// ======================================================================
// mma.sync bf16-split NT GEMM: 128x64 block tile, 128 threads (4 warps,
// each 64x32), 2-stage pipeline, 48KB/stage -> 2 CTAs/SM.
// ======================================================================
#define GBM      128
#define GBN      64
#define A_ST     16384                        // 128 rows x 64 bf16
#define B_ST     8192                         // 64 rows x 64 bf16
#define STAGE_B  (2 * A_ST + 2 * B_ST)        // Ah, Al, Bh, Bl = 48KB
#define GEMM_SMEM (2 * STAGE_B + 1024)

__device__ __forceinline__ void gemm_body(
    const __nv_bfloat16* __restrict__ Ah, const __nv_bfloat16* __restrict__ Al,
    const __nv_bfloat16* __restrict__ Bh, const __nv_bfloat16* __restrict__ Bl,
    float* __restrict__ C, int N, int K, int bm, int bn, uint32_t smem)
{
    const int tid  = threadIdx.x;
    const int wid  = tid >> 5, lane = tid & 31;
    const int wm   = (wid >> 1) * 64;      // 2 warp rows
    const int wn   = (wid & 1) * 32;       // 2 warp cols
    const int nchunk = K >> 6;

    auto load_chunk = [&](int c, int buf) {
        const uint32_t base = smem + buf * STAGE_B;
        const int k0 = c * 64;
        // A: 128 rows x 8 segs of 16B (hi + lo)
#pragma unroll
        for (int u = tid; u < 1024; u += 128) {
            int row = u >> 3, seg = u & 7;
            uint32_t so = SWZ((uint32_t)(row * 128 + seg * 16));
            size_t ga = (size_t)(bm + row) * K + k0 + seg * 8;
            CP_ASYNC(base + so,        Ah + ga, 16);
            CP_ASYNC(base + A_ST + so, Al + ga, 16);
        }
        // B: 64 rows x 8 segs (hi + lo), N guard
#pragma unroll
        for (int u = tid; u < 512; u += 128) {
            int row = u >> 3, seg = u & 7;
            uint32_t so = SWZ((uint32_t)(row * 128 + seg * 16));
            int n = bn + row;
            int sz = (n < N) ? 16 : 0;
            size_t gb = (size_t)(n < N ? n : 0) * K + k0 + seg * 8;
            CP_ASYNC(base + 2 * A_ST + so,        Bh + gb, sz);
            CP_ASYNC(base + 2 * A_ST + B_ST + so, Bl + gb, sz);
        }
        CP_COMMIT();
    };

    float acc[4][4][4];
#pragma unroll
    for (int i = 0; i < 4; i++)
#pragma unroll
        for (int j = 0; j < 4; j++)
#pragma unroll
            for (int q = 0; q < 4; q++) acc[i][j][q] = 0.f;

    load_chunk(0, 0);

    for (int c = 0; c < nchunk; c++) {
        const int buf = c & 1;
        if (c + 1 < nchunk) {
            load_chunk(c + 1, buf ^ 1);
            CP_WAIT(1);
        } else {
            CP_WAIT(0);
        }
        __syncthreads();

        const uint32_t sa_h = smem + buf * STAGE_B;
        const uint32_t sa_l = sa_h + A_ST;
        const uint32_t sb_h = sa_h + 2 * A_ST;
        const uint32_t sb_l = sb_h + B_ST;

#pragma unroll
        for (int ks = 0; ks < 4; ks++) {
            const int kk = ks * 16;
            uint32_t ah[4][4], al[4][4], bh[2][4], bl[2][4];
            {
                int r = lane & 15, ck = lane >> 4;
#pragma unroll
                for (int mt = 0; mt < 4; mt++) {
                    uint32_t off = SWZ((uint32_t)((wm + mt * 16 + r) * 128 + (kk + ck * 8) * 2));
                    ldsm4(ah[mt], sa_h + off);
                    ldsm4(al[mt], sa_l + off);
                }
            }
            {
                int grp = lane >> 3, ln = lane & 7;
#pragma unroll
                for (int np = 0; np < 2; np++) {
                    int n = wn + np * 16 + (grp >> 1) * 8 + ln;
                    int kc = kk + (grp & 1) * 8;
                    uint32_t off = SWZ((uint32_t)(n * 128 + kc * 2));
                    ldsm4(bh[np], sb_h + off);
                    ldsm4(bl[np], sb_l + off);
                }
            }
            // pass-major: 16 independent HMMAs per pass
#pragma unroll
            for (int mt = 0; mt < 4; mt++)
#pragma unroll
                for (int nt = 0; nt < 4; nt++)
                    mma_bf16(acc[mt][nt], ah[mt], &bh[nt >> 1][(nt & 1) * 2]);
#pragma unroll
            for (int mt = 0; mt < 4; mt++)
#pragma unroll
                for (int nt = 0; nt < 4; nt++)
                    mma_bf16(acc[mt][nt], ah[mt], &bl[nt >> 1][(nt & 1) * 2]);
#pragma unroll
            for (int mt = 0; mt < 4; mt++)
#pragma unroll
                for (int nt = 0; nt < 4; nt++)
                    mma_bf16(acc[mt][nt], al[mt], &bh[nt >> 1][(nt & 1) * 2]);
        }
        __syncthreads();
    }

#pragma unroll
    for (int mt = 0; mt < 4; mt++) {
        int r0 = bm + wm + mt * 16 + (lane >> 2);
#pragma unroll
        for (int nt = 0; nt < 4; nt++) {
            int col = bn + wn + nt * 8 + (lane & 3) * 2;
            if (col < N) {
                float* c0 = C + (size_t)r0 * N + col;
                float* c1 = C + (size_t)(r0 + 8) * N + col;
                c0[0] = acc[mt][nt][0]; c0[1] = acc[mt][nt][1];
                c1[0] = acc[mt][nt][2]; c1[1] = acc[mt][nt][3];
            }
        }
    }
}

__global__ __launch_bounds__(128) void gemm_mma128(
    const __nv_bfloat16* __restrict__ Ah, const __nv_bfloat16* __restrict__ Al,
    const __nv_bfloat16* __restrict__ Bh, const __nv_bfloat16* __restrict__ Bl,
    float* __restrict__ C, int N, int K)
{
    extern __shared__ char smraw[];
    const uint32_t smem0 = smem_u32(smraw);
    const uint32_t smem  = (smem0 + 1023) & ~1023u;
    gemm_body(Ah, Al, Bh, Bl, C, N, K, blockIdx.y * GBM, blockIdx.x * GBN, smem);
}

// fused q+kv projection: x tiles [0,QTILES) -> Q, [QTILES, QTILES+KVTILES) -> KV
#define QTILES  14                             // ceil(864/64)
#define KVTILES 9                              // 576/64
__global__ __launch_bounds__(128) void gemm_qkv(
    const __nv_bfloat16* __restrict__ Ah, const __nv_bfloat16* __restrict__ Al)
{
    extern __shared__ char smraw[];
    const uint32_t smem0 = smem_u32(smraw);
    const uint32_t smem  = (smem0 + 1023) & ~1023u;
    const int bx = blockIdx.x;
    if (bx < QTILES)
        gemm_body(Ah, Al, g_wqh, g_wql, g_abq, NQ, DM,
                  blockIdx.y * GBM, bx * GBN, smem);
    else
        gemm_body(Ah, Al, g_wkh, g_wkl, g_abkv, NKV, DM,
                  blockIdx.y * GBM, (bx - QTILES) * GBN, smem);
}

// ======================================================================
// qkv: rank contraction + rotary (fp32 trig) -> bf16 hi/lo q,k,v [b,h,t,d]
// ======================================================================
__global__ __launch_bounds__(128) void qkv_kernel()
{
    const int m = blockIdx.x;
    const int b = m >> 11;
    const int t = m & (TT - 1);
    const int d = threadIdx.x;

    __shared__ float aq  [RQ][16];
    __shared__ float bq  [RQ][128];
    __shared__ float akv [RKV][16];
    __shared__ float braw[RKV][128];
    __shared__ float brot[RKV][128];

    const float* abq = g_abq + (size_t)m * NQ;
    for (int idx = d; idx < NQ; idx += 128) {
        int r = idx / CH, c = idx - r * CH;
        float v = abq[idx];
        if (c < 16) aq[r][c] = v; else bq[r][c - 16] = v;
    }
    const float* abkv = g_abkv + (size_t)m * NKV;
    for (int idx = d; idx < NKV; idx += 128) {
        int r = idx / CH, c = idx - r * CH;
        float v = abkv[idx];
        if (c < 16) akv[r][c] = v; else braw[r][c - 16] = v;
    }
    __syncthreads();

    {
        int j = d & 63;
        float inv = powf(1e-4f, (float)j * (1.f / 64.f));   // (1/10000)^(j/64)
        float sv, cv;
        sincosf((float)t * inv, &sv, &cv);
#pragma unroll
        for (int r = 0; r < RKV; r++) {
            float x1 = braw[r][j], x2 = braw[r][j + 64];
            brot[r][d] = (d < 64) ? (x1 * cv + x2 * sv) : (-x1 * sv + x2 * cv);
        }
    }

    const size_t base = (((size_t)b * NH) * TT + t) * DH + d;
#pragma unroll
    for (int h = 0; h < NH; h++) {
        float qv = 0.f;
#pragma unroll
        for (int r = 0; r < RQ; r++) qv += aq[r][h] * bq[r][d];
        qv *= (1.f / 6.f);
        float kv = (akv[0][h] * brot[0][d] + akv[1][h] * brot[1][d]) * 0.5f;
        float vv = (akv[2][h] * brot[2][d] + akv[3][h] * brot[3][d]) * 0.5f;
        size_t o = base + (size_t)h * TT * DH;
        __nv_bfloat16 qhh = __float2bfloat16(qv);
        __nv_bfloat16 khh = __float2bfloat16(kv);
        __nv_bfloat16 vhh = __float2bfloat16(vv);
        g_qh[o] = qhh; g_ql[o] = __float2bfloat16(qv - __bfloat162float(qhh));
        g_kh[o] = khh; g_kl[o] = __float2bfloat16(kv - __bfloat162float(khh));
        g_vh[o] = vhh; g_vl[o] = __float2bfloat16(vv - __bfloat162float(vhh));
    }
}

// ======================================================================
// flash attention, causal, mma.sync bf16 split (unchanged from R10 best).
// grid (T/128, NH, NB), 256 threads (8 warps x 16 q-rows), 2-stage K/V.
// ======================================================================
#define ATTN_SMEM (196608 + 1024)

__global__ __launch_bounds__(256) void attn_mma()
{
    extern __shared__ char smraw[];
    const uint32_t sb0 = smem_u32(smraw);
    const uint32_t sb = (sb0 + 1023) & ~1023u;

    const int tid = threadIdx.x, wid = tid >> 5, lane = tid & 31;
    const int qt = (int)gridDim.x - 1 - (int)blockIdx.x;   // heavy tiles first
    const int h = blockIdx.y, b = blockIdx.z;
    const size_t bh = ((size_t)b * NH + h) * TT;
    const int nkt = 2 * qt + 2;

    const uint32_t sQh = sb, sQl = sb + 32768;

    {
        const char* qh = (const char*)g_qh + (bh + (size_t)qt * 128) * 256;
        const char* ql = (const char*)g_ql + (bh + (size_t)qt * 128) * 256;
        for (int u = tid; u < 2048; u += 256) {
            int row = u >> 4, seg = u & 15;
            uint32_t off = ASW((uint32_t)(row * 256 + seg * 16));
            int go = row * 256 + seg * 16;
            CP_ASYNC(sQh + off, qh + go, 16);
            CP_ASYNC(sQl + off, ql + go, 16);
        }
    }
    auto load_kv = [&](int kt, int s) {
        uint32_t base = sb + 65536 + (uint32_t)s * 65536;
        const char* kh = (const char*)g_kh + (bh + (size_t)kt * 64) * 256;
        const char* kl = (const char*)g_kl + (bh + (size_t)kt * 64) * 256;
        const char* vh = (const char*)g_vh + (bh + (size_t)kt * 64) * 256;
        const char* vl = (const char*)g_vl + (bh + (size_t)kt * 64) * 256;
        for (int u = tid; u < 1024; u += 256) {
            int row = u >> 4, seg = u & 15;
            uint32_t off = ASW((uint32_t)(row * 256 + seg * 16));
            int go = row * 256 + seg * 16;
            CP_ASYNC(base + off,         kh + go, 16);
            CP_ASYNC(base + 16384 + off, kl + go, 16);
            CP_ASYNC(base + 32768 + off, vh + go, 16);
            CP_ASYNC(base + 49152 + off, vl + go, 16);
        }
        CP_COMMIT();
    };
    load_kv(0, 0);
    if (nkt > 1) load_kv(1, 1);

    float oacc[16][4];
#pragma unroll
    for (int dt = 0; dt < 16; dt++)
#pragma unroll
        for (int e = 0; e < 4; e++) oacc[dt][e] = 0.f;
    float rM0 = -1e30f, rM1 = -1e30f, rL0 = 0.f, rL1 = 0.f;

    const float scale = 0.08838834764831845f;
    const int r0g = qt * 128 + wid * 16 + (lane >> 2);

    for (int kt = 0; kt < nkt; kt++) {
        const int s = kt & 1;
        if (kt + 1 < nkt) { CP_WAIT(1); } else { CP_WAIT(0); }
        __syncthreads();
        const uint32_t base = sb + 65536 + (uint32_t)s * 65536;
        const uint32_t sKh = base, sKl = base + 16384;
        const uint32_t sVh = base + 32768, sVl = base + 49152;

        float sacc[8][4];
#pragma unroll
        for (int nt = 0; nt < 8; nt++)
#pragma unroll
            for (int e = 0; e < 4; e++) sacc[nt][e] = 0.f;

        // ---- S = Q K^T, pass-major ----
#pragma unroll
        for (int ks = 0; ks < 8; ks++) {
            uint32_t ah[4], al[4];
            {
                int r = lane & 15, ck = lane >> 4;
                uint32_t off = ASW((uint32_t)((wid * 16 + r) * 256 + (ks * 16 + ck * 8) * 2));
                ldsm4(ah, sQh + off);
                ldsm4(al, sQl + off);
            }
            uint32_t bh4[4][4], bl4[4][4];
            {
                int grp = lane >> 3, ln = lane & 7;
#pragma unroll
                for (int ng = 0; ng < 4; ng++) {
                    int n = ng * 16 + (grp >> 1) * 8 + ln;
                    int kc = ks * 16 + (grp & 1) * 8;
                    uint32_t off = ASW((uint32_t)(n * 256 + kc * 2));
                    ldsm4(bh4[ng], sKh + off);
                    ldsm4(bl4[ng], sKl + off);
                }
            }
#pragma unroll
            for (int ng = 0; ng < 4; ng++) {
                mma_bf16(sacc[ng * 2],     ah, bh4[ng]);
                mma_bf16(sacc[ng * 2 + 1], ah, bh4[ng] + 2);
            }
#pragma unroll
            for (int ng = 0; ng < 4; ng++) {
                mma_bf16(sacc[ng * 2],     ah, bl4[ng]);
                mma_bf16(sacc[ng * 2 + 1], ah, bl4[ng] + 2);
            }
#pragma unroll
            for (int ng = 0; ng < 4; ng++) {
                mma_bf16(sacc[ng * 2],     al, bh4[ng]);
                mma_bf16(sacc[ng * 2 + 1], al, bh4[ng] + 2);
            }
        }

        const bool domask = (kt >= 2 * qt);
        float mx0 = -1e30f, mx1 = -1e30f;
#pragma unroll
        for (int nt = 0; nt < 8; nt++) {
            int c0 = kt * 64 + nt * 8 + (lane & 3) * 2;
#pragma unroll
            for (int e = 0; e < 4; e++) {
                float v = sacc[nt][e] * scale;
                if (domask) {
                    int cc = c0 + (e & 1);
                    int rr = r0g + ((e >> 1) << 3);
                    if (cc > rr) v = -1e30f;
                }
                sacc[nt][e] = v;
            }
            mx0 = fmaxf(mx0, fmaxf(sacc[nt][0], sacc[nt][1]));
            mx1 = fmaxf(mx1, fmaxf(sacc[nt][2], sacc[nt][3]));
        }
        mx0 = fmaxf(mx0, __shfl_xor_sync(0xffffffffu, mx0, 1));
        mx0 = fmaxf(mx0, __shfl_xor_sync(0xffffffffu, mx0, 2));
        mx1 = fmaxf(mx1, __shfl_xor_sync(0xffffffffu, mx1, 1));
        mx1 = fmaxf(mx1, __shfl_xor_sync(0xffffffffu, mx1, 2));

        float nM0 = fmaxf(rM0, mx0), nM1 = fmaxf(rM1, mx1);
        float cor0 = __expf(rM0 - nM0), cor1 = __expf(rM1 - nM1);
        rM0 = nM0; rM1 = nM1;

        float sum0 = 0.f, sum1 = 0.f;
        uint32_t pH01[8], pH23[8], pL01[8], pL23[8];
#pragma unroll
        for (int nt = 0; nt < 8; nt++) {
            float p0 = __expf(sacc[nt][0] - nM0);
            float p1 = __expf(sacc[nt][1] - nM0);
            float p2 = __expf(sacc[nt][2] - nM1);
            float p3 = __expf(sacc[nt][3] - nM1);
            sum0 += p0 + p1; sum1 += p2 + p3;
            __nv_bfloat16 h0 = __float2bfloat16(p0), h1 = __float2bfloat16(p1);
            __nv_bfloat16 h2 = __float2bfloat16(p2), h3 = __float2bfloat16(p3);
            pH01[nt] = pack_bf2(h0, h1);
            pH23[nt] = pack_bf2(h2, h3);
            pL01[nt] = pack_bf2(__float2bfloat16(p0 - __bfloat162float(h0)),
                                __float2bfloat16(p1 - __bfloat162float(h1)));
            pL23[nt] = pack_bf2(__float2bfloat16(p2 - __bfloat162float(h2)),
                                __float2bfloat16(p3 - __bfloat162float(h3)));
        }
        sum0 += __shfl_xor_sync(0xffffffffu, sum0, 1);
        sum0 += __shfl_xor_sync(0xffffffffu, sum0, 2);
        sum1 += __shfl_xor_sync(0xffffffffu, sum1, 1);
        sum1 += __shfl_xor_sync(0xffffffffu, sum1, 2);
        rL0 = rL0 * cor0 + sum0;
        rL1 = rL1 * cor1 + sum1;

#pragma unroll
        for (int dt = 0; dt < 16; dt++) {
            oacc[dt][0] *= cor0; oacc[dt][1] *= cor0;
            oacc[dt][2] *= cor1; oacc[dt][3] *= cor1;
        }

        // ---- O += P V, pass-major over 4-dg groups ----
#pragma unroll
        for (int k2 = 0; k2 < 4; k2++) {
            uint32_t aH[4] = {pH01[2 * k2], pH23[2 * k2], pH01[2 * k2 + 1], pH23[2 * k2 + 1]};
            uint32_t aL[4] = {pL01[2 * k2], pL23[2 * k2], pL01[2 * k2 + 1], pL23[2 * k2 + 1]};
            int krow = k2 * 16 + ((lane >> 3) & 1) * 8 + (lane & 7);
#pragma unroll
            for (int dh2 = 0; dh2 < 2; dh2++) {
                uint32_t vh4[4][4], vl4[4][4];
#pragma unroll
                for (int dq = 0; dq < 4; dq++) {
                    int dcol = (dh2 * 4 + dq) * 16 + (lane >> 4) * 8;
                    uint32_t off = ASW((uint32_t)(krow * 256 + dcol * 2));
                    ldsm4t(vh4[dq], sVh + off);
                    ldsm4t(vl4[dq], sVl + off);
                }
#pragma unroll
                for (int dq = 0; dq < 4; dq++) {
                    int dg = dh2 * 4 + dq;
                    mma_bf16(oacc[dg * 2],     aH, vh4[dq]);
                    mma_bf16(oacc[dg * 2 + 1], aH, vh4[dq] + 2);
                }
#pragma unroll
                for (int dq = 0; dq < 4; dq++) {
                    int dg = dh2 * 4 + dq;
                    mma_bf16(oacc[dg * 2],     aH, vl4[dq]);
                    mma_bf16(oacc[dg * 2 + 1], aH, vl4[dq] + 2);
                }
#pragma unroll
                for (int dq = 0; dq < 4; dq++) {
                    int dg = dh2 * 4 + dq;
                    mma_bf16(oacc[dg * 2],     aL, vh4[dq]);
                    mma_bf16(oacc[dg * 2 + 1], aL, vh4[dq] + 2);
                }
            }
        }
        __syncthreads();
        if (kt + 2 < nkt) load_kv(kt + 2, s);
    }

    // ---- normalize + split + store bf16 hi/lo y ----
    float il0 = 1.f / rL0, il1 = 1.f / rL1;
    size_t row0 = ((size_t)b * TT + r0g) * DM + h * DH;
    size_t row1 = row0 + (size_t)8 * DM;
#pragma unroll
    for (int dt = 0; dt < 16; dt++) {
        int c = dt * 8 + (lane & 3) * 2;
        float v0 = oacc[dt][0] * il0, v1 = oacc[dt][1] * il0;
        float v2 = oacc[dt][2] * il1, v3 = oacc[dt][3] * il1;
        __nv_bfloat16 h0 = __float2bfloat16(v0), h1 = __float2bfloat16(v1);
        __nv_bfloat16 h2 = __float2bfloat16(v2), h3 = __float2bfloat16(v3);
        *(uint32_t*)(g_yh + row0 + c) = pack_bf2(h0, h1);
        *(uint32_t*)(g_yh + row1 + c) = pack_bf2(h2, h3);
        *(uint32_t*)(g_yl + row0 + c) = pack_bf2(__float2bfloat16(v0 - __bfloat162float(h0)),
                                                 __float2bfloat16(v1 - __bfloat162float(h1)));
        *(uint32_t*)(g_yl + row1 + c) = pack_bf2(__float2bfloat16(v2 - __bfloat162float(h2)),
                                                 __float2bfloat16(v3 - __bfloat162float(h3)));
    }
}

// ======================================================================
extern "C" void kernel_launch(void* const* d_in, const int* in_sizes, int n_in,
                              void* d_out, int out_size)
{
    const float* x   = (const float*)d_in[0];
    const float* Wq  = (const float*)d_in[1];
    const float* Wkv = (const float*)d_in[2];
    const float* Wo  = (const float*)d_in[3];
    float* out = (float*)d_out;

    __nv_bfloat16 *xh, *xl, *wqh, *wql, *wkh, *wkl, *woh, *wol, *yh, *yl;
    cudaGetSymbolAddress((void**)&xh,  g_xh);  cudaGetSymbolAddress((void**)&xl,  g_xl);
    cudaGetSymbolAddress((void**)&wqh, g_wqh); cudaGetSymbolAddress((void**)&wql, g_wql);
    cudaGetSymbolAddress((void**)&wkh, g_wkh); cudaGetSymbolAddress((void**)&wkl, g_wkl);
    cudaGetSymbolAddress((void**)&woh, g_woh); cudaGetSymbolAddress((void**)&wol, g_wol);
    cudaGetSymbolAddress((void**)&yh,  g_yh);  cudaGetSymbolAddress((void**)&yl,  g_yl);

    cudaFuncSetAttribute(gemm_mma128, cudaFuncAttributeMaxDynamicSharedMemorySize, GEMM_SMEM);
    cudaFuncSetAttribute(gemm_qkv,    cudaFuncAttributeMaxDynamicSharedMemorySize, GEMM_SMEM);
    cudaFuncSetAttribute(attn_mma,    cudaFuncAttributeMaxDynamicSharedMemorySize, ATTN_SMEM);

    // 0) fp32 -> bf16 hi/lo splits (x + all three weights, one launch)
    {
        int n0 = BT * DM, n1 = NQ * DM, n2 = NKV * DM, n3 = DM * DM;
        conv_all<<<(n0 + n1 + n2 + n3 + 255) / 256, 256>>>(
            x, xh, xl, n0, Wq, wqh, wql, n1, Wkv, wkh, wkl, n2, Wo, woh, wol, n3);
    }
    // 1) fused ab_q / ab_kv projections (one launch, 736 CTAs, 2/SM)
    {
        dim3 g(QTILES + KVTILES, BT / GBM);
        gemm_qkv<<<g, 128, GEMM_SMEM>>>(xh, xl);
    }
    // 2) q,k,v (+rotary) -> bf16 hi/lo
    qkv_kernel<<<BT, 128>>>();
    // 3) causal attention (tensor cores) -> yh/yl directly   [profiled slot]
    {
        dim3 g(TT / 128, NH, NB);
        attn_mma<<<g, 256, ATTN_SMEM>>>();
    }
    // 4) out = y @ W_o^T (4096 x 2048), 1024 CTAs, 2/SM
    {
        dim3 g(DM / GBN, BT / GBM);
        gemm_mma128<<<g, 128, GEMM_SMEM>>>(yh, yl, woh, wol, out, DM, DM);
    }
}

// round 12
// speedup vs baseline: 1.1298x; 1.0308x over previous
#include <cuda_runtime.h>
#include <cuda_bf16.h>
#include <cstdint>
#include <math.h>

// ---------------- problem constants ----------------
#define NB     2
#define TT     2048
#define BT     4096      // NB*TT tokens
#define DM     2048
#define NH     16
#define DH     128
#define CH     144       // NH + DH
#define RQ     6
#define RKV    4
#define NQ     864       // RQ*CH
#define NKV    576       // RKV*CH

// ---------------- scratch (device globals; no allocs allowed) ----------------
__device__ float g_abq [BT * NQ];
__device__ float g_abkv[BT * NKV];

// bf16 hi/lo split scratch
__device__ __nv_bfloat16 g_xh [BT * DM],  g_xl [BT * DM];
__device__ __nv_bfloat16 g_wqh[NQ * DM],  g_wql[NQ * DM];
__device__ __nv_bfloat16 g_wkh[NKV * DM], g_wkl[NKV * DM];
__device__ __nv_bfloat16 g_woh[DM * DM],  g_wol[DM * DM];
__device__ __nv_bfloat16 g_yh [BT * DM],  g_yl [BT * DM];

// q/k/v bf16 hi/lo, layout [b,h,t,d]
#define QKV_ELEMS (NB * NH * TT * DH)
__device__ __nv_bfloat16 g_qh[QKV_ELEMS], g_ql[QKV_ELEMS];
__device__ __nv_bfloat16 g_kh[QKV_ELEMS], g_kl[QKV_ELEMS];
__device__ __nv_bfloat16 g_vh[QKV_ELEMS], g_vl[QKV_ELEMS];

// ================= helpers =================
__device__ __forceinline__ uint32_t smem_u32(const void* p) {
    uint32_t a;
    asm("{ .reg .u64 t; cvta.to.shared.u64 t, %1; cvt.u32.u64 %0, t; }" : "=r"(a) : "l"(p));
    return a;
}
#define SWZ(o)  ((o) ^ (((o) >> 3) & 0x70))   // 128B-row swizzle (GEMM tiles)
#define ASW(o)  ((o) ^ (((o) >> 4) & 0x70))   // 256B-row swizzle (attn tiles)

__device__ __forceinline__ void ldsm4(uint32_t* r, uint32_t addr) {
    asm volatile("ldmatrix.sync.aligned.m8n8.x4.shared.b16 {%0,%1,%2,%3}, [%4];"
        : "=r"(r[0]), "=r"(r[1]), "=r"(r[2]), "=r"(r[3]) : "r"(addr));
}
__device__ __forceinline__ void ldsm4t(uint32_t* r, uint32_t addr) {
    asm volatile("ldmatrix.sync.aligned.m8n8.x4.trans.shared.b16 {%0,%1,%2,%3}, [%4];"
        : "=r"(r[0]), "=r"(r[1]), "=r"(r[2]), "=r"(r[3]) : "r"(addr));
}
__device__ __forceinline__ void mma_bf16(float* c, const uint32_t* a, const uint32_t* b) {
    asm volatile("mma.sync.aligned.m16n8k16.row.col.f32.bf16.bf16.f32 "
        "{%0,%1,%2,%3}, {%4,%5,%6,%7}, {%8,%9}, {%0,%1,%2,%3};"
        : "+f"(c[0]), "+f"(c[1]), "+f"(c[2]), "+f"(c[3])
        : "r"(a[0]), "r"(a[1]), "r"(a[2]), "r"(a[3]), "r"(b[0]), "r"(b[1]));
}
#define CP_ASYNC(dst, src, sz) \
    asm volatile("cp.async.cg.shared.global [%0], [%1], 16, %2;" \
        :: "r"(dst), "l"(src), "r"(sz) : "memory")
#define CP_COMMIT() asm volatile("cp.async.commit_group;" ::: "memory")
#define CP_WAIT(n)  asm volatile("cp.async.wait_group %0;" :: "n"(n) : "memory")

__device__ __forceinline__ uint32_t pack_bf2(__nv_bfloat16 lo, __nv_bfloat16 hi) {
    __nv_bfloat162 t; t.x = lo; t.y = hi;
    return *reinterpret_cast<uint32_t*>(&t);
}

// ======================================================================
// fused fp32 -> bf16 hi/lo split of all four tensors (one launch)
// ======================================================================
__global__ __launch_bounds__(256) void conv_all(
    const float* __restrict__ s0, __nv_bfloat16* __restrict__ h0, __nv_bfloat16* __restrict__ l0, int n0,
    const float* __restrict__ s1, __nv_bfloat16* __restrict__ h1, __nv_bfloat16* __restrict__ l1, int n1,
    const float* __restrict__ s2, __nv_bfloat16* __restrict__ h2, __nv_bfloat16* __restrict__ l2, int n2,
    const float* __restrict__ s3, __nv_bfloat16* __restrict__ h3, __nv_bfloat16* __restrict__ l3, int n3)
{
    int i = blockIdx.x * 256 + threadIdx.x;
    const float* s; __nv_bfloat16 *h, *l; int j;
    if (i < n0)                     { s = s0; h = h0; l = l0; j = i; }
    else if (i < n0 + n1)           { s = s1; h = h1; l = l1; j = i - n0; }
    else if (i < n0 + n1 + n2)      { s = s2; h = h2; l = l2; j = i - n0 - n1; }
    else if (i < n0 + n1 + n2 + n3) { s = s3; h = h3; l = l3; j = i - n0 - n1 - n2; }
    else return;
    float v = s[j];
    __nv_bfloat16 hi = __float2bfloat16(v);
    h[j] = hi;
    l[j] = __float2bfloat16(v - __bfloat162float(hi));
}

// ======================================================================
// mma.sync bf16-split NT GEMM: 128x64 block tile, 128 threads (4 warps,
// each 64x32), 2-stage pipeline, 48KB/stage -> 2 CTAs/SM. (R11 winner)
// ======================================================================
#define GBM      128
#define GBN      64
#define A_ST     16384
#define B_ST     8192
#define STAGE_B  (2 * A_ST + 2 * B_ST)
#define GEMM_SMEM (2 * STAGE_B + 1024)

__device__ __forceinline__ void gemm_body(
    const __nv_bfloat16* __restrict__ Ah, const __nv_bfloat16* __restrict__ Al,
    const __nv_bfloat16* __restrict__ Bh, const __nv_bfloat16* __restrict__ Bl,
    float* __restrict__ C, int N, int K, int bm, int bn, uint32_t smem)
{
    const int tid  = threadIdx.x;
    const int wid  = tid >> 5, lane = tid & 31;
    const int wm   = (wid >> 1) * 64;
    const int wn   = (wid & 1) * 32;
    const int nchunk = K >> 6;

    auto load_chunk = [&](int c, int buf) {
        const uint32_t base = smem + buf * STAGE_B;
        const int k0 = c * 64;
#pragma unroll
        for (int u = tid; u < 1024; u += 128) {
            int row = u >> 3, seg = u & 7;
            uint32_t so = SWZ((uint32_t)(row * 128 + seg * 16));
            size_t ga = (size_t)(bm + row) * K + k0 + seg * 8;
            CP_ASYNC(base + so,        Ah + ga, 16);
            CP_ASYNC(base + A_ST + so, Al + ga, 16);
        }
#pragma unroll
        for (int u = tid; u < 512; u += 128) {
            int row = u >> 3, seg = u & 7;
            uint32_t so = SWZ((uint32_t)(row * 128 + seg * 16));
            int n = bn + row;
            int sz = (n < N) ? 16 : 0;
            size_t gb = (size_t)(n < N ? n : 0) * K + k0 + seg * 8;
            CP_ASYNC(base + 2 * A_ST + so,        Bh + gb, sz);
            CP_ASYNC(base + 2 * A_ST + B_ST + so, Bl + gb, sz);
        }
        CP_COMMIT();
    };

    float acc[4][4][4];
#pragma unroll
    for (int i = 0; i < 4; i++)
#pragma unroll
        for (int j = 0; j < 4; j++)
#pragma unroll
            for (int q = 0; q < 4; q++) acc[i][j][q] = 0.f;

    load_chunk(0, 0);

    for (int c = 0; c < nchunk; c++) {
        const int buf = c & 1;
        if (c + 1 < nchunk) {
            load_chunk(c + 1, buf ^ 1);
            CP_WAIT(1);
        } else {
            CP_WAIT(0);
        }
        __syncthreads();

        const uint32_t sa_h = smem + buf * STAGE_B;
        const uint32_t sa_l = sa_h + A_ST;
        const uint32_t sb_h = sa_h + 2 * A_ST;
        const uint32_t sb_l = sb_h + B_ST;

#pragma unroll
        for (int ks = 0; ks < 4; ks++) {
            const int kk = ks * 16;
            uint32_t ah[4][4], al[4][4], bh[2][4], bl[2][4];
            {
                int r = lane & 15, ck = lane >> 4;
#pragma unroll
                for (int mt = 0; mt < 4; mt++) {
                    uint32_t off = SWZ((uint32_t)((wm + mt * 16 + r) * 128 + (kk + ck * 8) * 2));
                    ldsm4(ah[mt], sa_h + off);
                    ldsm4(al[mt], sa_l + off);
                }
            }
            {
                int grp = lane >> 3, ln = lane & 7;
#pragma unroll
                for (int np = 0; np < 2; np++) {
                    int n = wn + np * 16 + (grp >> 1) * 8 + ln;
                    int kc = kk + (grp & 1) * 8;
                    uint32_t off = SWZ((uint32_t)(n * 128 + kc * 2));
                    ldsm4(bh[np], sb_h + off);
                    ldsm4(bl[np], sb_l + off);
                }
            }
#pragma unroll
            for (int mt = 0; mt < 4; mt++)
#pragma unroll
                for (int nt = 0; nt < 4; nt++)
                    mma_bf16(acc[mt][nt], ah[mt], &bh[nt >> 1][(nt & 1) * 2]);
#pragma unroll
            for (int mt = 0; mt < 4; mt++)
#pragma unroll
                for (int nt = 0; nt < 4; nt++)
                    mma_bf16(acc[mt][nt], ah[mt], &bl[nt >> 1][(nt & 1) * 2]);
#pragma unroll
            for (int mt = 0; mt < 4; mt++)
#pragma unroll
                for (int nt = 0; nt < 4; nt++)
                    mma_bf16(acc[mt][nt], al[mt], &bh[nt >> 1][(nt & 1) * 2]);
        }
        __syncthreads();
    }

#pragma unroll
    for (int mt = 0; mt < 4; mt++) {
        int r0 = bm + wm + mt * 16 + (lane >> 2);
#pragma unroll
        for (int nt = 0; nt < 4; nt++) {
            int col = bn + wn + nt * 8 + (lane & 3) * 2;
            if (col < N) {
                float* c0 = C + (size_t)r0 * N + col;
                float* c1 = C + (size_t)(r0 + 8) * N + col;
                c0[0] = acc[mt][nt][0]; c0[1] = acc[mt][nt][1];
                c1[0] = acc[mt][nt][2]; c1[1] = acc[mt][nt][3];
            }
        }
    }
}

__global__ __launch_bounds__(128) void gemm_mma128(
    const __nv_bfloat16* __restrict__ Ah, const __nv_bfloat16* __restrict__ Al,
    const __nv_bfloat16* __restrict__ Bh, const __nv_bfloat16* __restrict__ Bl,
    float* __restrict__ C, int N, int K)
{
    extern __shared__ char smraw[];
    const uint32_t smem0 = smem_u32(smraw);
    const uint32_t smem  = (smem0 + 1023) & ~1023u;
    gemm_body(Ah, Al, Bh, Bl, C, N, K, blockIdx.y * GBM, blockIdx.x * GBN, smem);
}

#define QTILES  14
#define KVTILES 9
__global__ __launch_bounds__(128) void gemm_qkv(
    const __nv_bfloat16* __restrict__ Ah, const __nv_bfloat16* __restrict__ Al)
{
    extern __shared__ char smraw[];
    const uint32_t smem0 = smem_u32(smraw);
    const uint32_t smem  = (smem0 + 1023) & ~1023u;
    const int bx = blockIdx.x;
    if (bx < QTILES)
        gemm_body(Ah, Al, g_wqh, g_wql, g_abq, NQ, DM,
                  blockIdx.y * GBM, bx * GBN, smem);
    else
        gemm_body(Ah, Al, g_wkh, g_wkl, g_abkv, NKV, DM,
                  blockIdx.y * GBM, (bx - QTILES) * GBN, smem);
}

// ======================================================================
// qkv: rank contraction + rotary (fp32 trig) -> bf16 hi/lo q,k,v [b,h,t,d]
// ======================================================================
__global__ __launch_bounds__(128) void qkv_kernel()
{
    const int m = blockIdx.x;
    const int b = m >> 11;
    const int t = m & (TT - 1);
    const int d = threadIdx.x;

    __shared__ float aq  [RQ][16];
    __shared__ float bq  [RQ][128];
    __shared__ float akv [RKV][16];
    __shared__ float braw[RKV][128];
    __shared__ float brot[RKV][128];

    const float* abq = g_abq + (size_t)m * NQ;
    for (int idx = d; idx < NQ; idx += 128) {
        int r = idx / CH, c = idx - r * CH;
        float v = abq[idx];
        if (c < 16) aq[r][c] = v; else bq[r][c - 16] = v;
    }
    const float* abkv = g_abkv + (size_t)m * NKV;
    for (int idx = d; idx < NKV; idx += 128) {
        int r = idx / CH, c = idx - r * CH;
        float v = abkv[idx];
        if (c < 16) akv[r][c] = v; else braw[r][c - 16] = v;
    }
    __syncthreads();

    {
        int j = d & 63;
        float inv = powf(1e-4f, (float)j * (1.f / 64.f));
        float sv, cv;
        sincosf((float)t * inv, &sv, &cv);
#pragma unroll
        for (int r = 0; r < RKV; r++) {
            float x1 = braw[r][j], x2 = braw[r][j + 64];
            brot[r][d] = (d < 64) ? (x1 * cv + x2 * sv) : (-x1 * sv + x2 * cv);
        }
    }

    const size_t base = (((size_t)b * NH) * TT + t) * DH + d;
#pragma unroll
    for (int h = 0; h < NH; h++) {
        float qv = 0.f;
#pragma unroll
        for (int r = 0; r < RQ; r++) qv += aq[r][h] * bq[r][d];
        qv *= (1.f / 6.f);
        float kv = (akv[0][h] * brot[0][d] + akv[1][h] * brot[1][d]) * 0.5f;
        float vv = (akv[2][h] * brot[2][d] + akv[3][h] * brot[3][d]) * 0.5f;
        size_t o = base + (size_t)h * TT * DH;
        __nv_bfloat16 qhh = __float2bfloat16(qv);
        __nv_bfloat16 khh = __float2bfloat16(kv);
        __nv_bfloat16 vhh = __float2bfloat16(vv);
        g_qh[o] = qhh; g_ql[o] = __float2bfloat16(qv - __bfloat162float(qhh));
        g_kh[o] = khh; g_kl[o] = __float2bfloat16(kv - __bfloat162float(khh));
        g_vh[o] = vhh; g_vl[o] = __float2bfloat16(vv - __bfloat162float(vhh));
    }
}

// ======================================================================
// flash attention, causal, mma.sync bf16 split.
// NEW: 128 threads (4 warps x 16 q-rows = 64-row Q tile), 32-row KV
// stages, 2-stage double buffer -> 97KB smem -> 2 CTAs/SM.
// grid (T/64, NH, NB) = 1024 CTAs, descending qt.
// ======================================================================
#define ATTN_SMEM (98304 + 1024)

__global__ __launch_bounds__(128) void attn_mma()
{
    extern __shared__ char smraw[];
    const uint32_t sb0 = smem_u32(smraw);
    const uint32_t sb = (sb0 + 1023) & ~1023u;

    const int tid = threadIdx.x, wid = tid >> 5, lane = tid & 31;
    const int qt = (int)gridDim.x - 1 - (int)blockIdx.x;   // heavy tiles first
    const int h = blockIdx.y, b = blockIdx.z;
    const size_t bh = ((size_t)b * NH + h) * TT;
    const int nkt = 2 * qt + 2;                            // 32-row kv tiles

    const uint32_t sQh = sb, sQl = sb + 16384;

    // Q tile: 64 rows hi/lo (bundled into stage-0 commit group)
    {
        const char* qh = (const char*)g_qh + (bh + (size_t)qt * 64) * 256;
        const char* ql = (const char*)g_ql + (bh + (size_t)qt * 64) * 256;
        for (int u = tid; u < 1024; u += 128) {
            int row = u >> 4, seg = u & 15;
            uint32_t off = ASW((uint32_t)(row * 256 + seg * 16));
            int go = row * 256 + seg * 16;
            CP_ASYNC(sQh + off, qh + go, 16);
            CP_ASYNC(sQl + off, ql + go, 16);
        }
    }
    auto load_kv = [&](int kt, int s) {
        uint32_t base = sb + 32768 + (uint32_t)s * 32768;
        const char* kh = (const char*)g_kh + (bh + (size_t)kt * 32) * 256;
        const char* kl = (const char*)g_kl + (bh + (size_t)kt * 32) * 256;
        const char* vh = (const char*)g_vh + (bh + (size_t)kt * 32) * 256;
        const char* vl = (const char*)g_vl + (bh + (size_t)kt * 32) * 256;
        for (int u = tid; u < 512; u += 128) {
            int row = u >> 4, seg = u & 15;
            uint32_t off = ASW((uint32_t)(row * 256 + seg * 16));
            int go = row * 256 + seg * 16;
            CP_ASYNC(base + off,         kh + go, 16);
            CP_ASYNC(base + 8192 + off,  kl + go, 16);
            CP_ASYNC(base + 16384 + off, vh + go, 16);
            CP_ASYNC(base + 24576 + off, vl + go, 16);
        }
        CP_COMMIT();
    };
    load_kv(0, 0);
    if (nkt > 1) load_kv(1, 1);

    float oacc[16][4];
#pragma unroll
    for (int dt = 0; dt < 16; dt++)
#pragma unroll
        for (int e = 0; e < 4; e++) oacc[dt][e] = 0.f;
    float rM0 = -1e30f, rM1 = -1e30f, rL0 = 0.f, rL1 = 0.f;

    const float scale = 0.08838834764831845f;
    const int r0g = qt * 64 + wid * 16 + (lane >> 2);

    for (int kt = 0; kt < nkt; kt++) {
        const int s = kt & 1;
        if (kt + 1 < nkt) { CP_WAIT(1); } else { CP_WAIT(0); }
        __syncthreads();
        const uint32_t base = sb + 32768 + (uint32_t)s * 32768;
        const uint32_t sKh = base, sKl = base + 8192;
        const uint32_t sVh = base + 16384, sVl = base + 24576;

        float sacc[4][4];
#pragma unroll
        for (int nt = 0; nt < 4; nt++)
#pragma unroll
            for (int e = 0; e < 4; e++) sacc[nt][e] = 0.f;

        // ---- S = Q K^T (64x32), pass-major ----
#pragma unroll
        for (int ks = 0; ks < 8; ks++) {
            uint32_t ah[4], al[4];
            {
                int r = lane & 15, ck = lane >> 4;
                uint32_t off = ASW((uint32_t)((wid * 16 + r) * 256 + (ks * 16 + ck * 8) * 2));
                ldsm4(ah, sQh + off);
                ldsm4(al, sQl + off);
            }
            uint32_t bh4[2][4], bl4[2][4];
            {
                int grp = lane >> 3, ln = lane & 7;
#pragma unroll
                for (int ng = 0; ng < 2; ng++) {
                    int n = ng * 16 + (grp >> 1) * 8 + ln;
                    int kc = ks * 16 + (grp & 1) * 8;
                    uint32_t off = ASW((uint32_t)(n * 256 + kc * 2));
                    ldsm4(bh4[ng], sKh + off);
                    ldsm4(bl4[ng], sKl + off);
                }
            }
#pragma unroll
            for (int ng = 0; ng < 2; ng++) {
                mma_bf16(sacc[ng * 2],     ah, bh4[ng]);
                mma_bf16(sacc[ng * 2 + 1], ah, bh4[ng] + 2);
            }
#pragma unroll
            for (int ng = 0; ng < 2; ng++) {
                mma_bf16(sacc[ng * 2],     ah, bl4[ng]);
                mma_bf16(sacc[ng * 2 + 1], ah, bl4[ng] + 2);
            }
#pragma unroll
            for (int ng = 0; ng < 2; ng++) {
                mma_bf16(sacc[ng * 2],     al, bh4[ng]);
                mma_bf16(sacc[ng * 2 + 1], al, bh4[ng] + 2);
            }
        }

        const bool domask = (kt >= 2 * qt);
        float mx0 = -1e30f, mx1 = -1e30f;
#pragma unroll
        for (int nt = 0; nt < 4; nt++) {
            int c0 = kt * 32 + nt * 8 + (lane & 3) * 2;
#pragma unroll
            for (int e = 0; e < 4; e++) {
                float v = sacc[nt][e] * scale;
                if (domask) {
                    int cc = c0 + (e & 1);
                    int rr = r0g + ((e >> 1) << 3);
                    if (cc > rr) v = -1e30f;
                }
                sacc[nt][e] = v;
            }
            mx0 = fmaxf(mx0, fmaxf(sacc[nt][0], sacc[nt][1]));
            mx1 = fmaxf(mx1, fmaxf(sacc[nt][2], sacc[nt][3]));
        }
        mx0 = fmaxf(mx0, __shfl_xor_sync(0xffffffffu, mx0, 1));
        mx0 = fmaxf(mx0, __shfl_xor_sync(0xffffffffu, mx0, 2));
        mx1 = fmaxf(mx1, __shfl_xor_sync(0xffffffffu, mx1, 1));
        mx1 = fmaxf(mx1, __shfl_xor_sync(0xffffffffu, mx1, 2));

        float nM0 = fmaxf(rM0, mx0), nM1 = fmaxf(rM1, mx1);
        float cor0 = __expf(rM0 - nM0), cor1 = __expf(rM1 - nM1);
        rM0 = nM0; rM1 = nM1;

        float sum0 = 0.f, sum1 = 0.f;
        uint32_t pH01[4], pH23[4], pL01[4], pL23[4];
#pragma unroll
        for (int nt = 0; nt < 4; nt++) {
            float p0 = __expf(sacc[nt][0] - nM0);
            float p1 = __expf(sacc[nt][1] - nM0);
            float p2 = __expf(sacc[nt][2] - nM1);
            float p3 = __expf(sacc[nt][3] - nM1);
            sum0 += p0 + p1; sum1 += p2 + p3;
            __nv_bfloat16 h0 = __float2bfloat16(p0), h1 = __float2bfloat16(p1);
            __nv_bfloat16 h2 = __float2bfloat16(p2), h3 = __float2bfloat16(p3);
            pH01[nt] = pack_bf2(h0, h1);
            pH23[nt] = pack_bf2(h2, h3);
            pL01[nt] = pack_bf2(__float2bfloat16(p0 - __bfloat162float(h0)),
                                __float2bfloat16(p1 - __bfloat162float(h1)));
            pL23[nt] = pack_bf2(__float2bfloat16(p2 - __bfloat162float(h2)),
                                __float2bfloat16(p3 - __bfloat162float(h3)));
        }
        sum0 += __shfl_xor_sync(0xffffffffu, sum0, 1);
        sum0 += __shfl_xor_sync(0xffffffffu, sum0, 2);
        sum1 += __shfl_xor_sync(0xffffffffu, sum1, 1);
        sum1 += __shfl_xor_sync(0xffffffffu, sum1, 2);
        rL0 = rL0 * cor0 + sum0;
        rL1 = rL1 * cor1 + sum1;

#pragma unroll
        for (int dt = 0; dt < 16; dt++) {
            oacc[dt][0] *= cor0; oacc[dt][1] *= cor0;
            oacc[dt][2] *= cor1; oacc[dt][3] *= cor1;
        }

        // ---- O += P V (P 64x32, V 32x128), pass-major ----
#pragma unroll
        for (int k2 = 0; k2 < 2; k2++) {
            uint32_t aH[4] = {pH01[2 * k2], pH23[2 * k2], pH01[2 * k2 + 1], pH23[2 * k2 + 1]};
            uint32_t aL[4] = {pL01[2 * k2], pL23[2 * k2], pL01[2 * k2 + 1], pL23[2 * k2 + 1]};
            int krow = k2 * 16 + ((lane >> 3) & 1) * 8 + (lane & 7);
#pragma unroll
            for (int dh2 = 0; dh2 < 2; dh2++) {
                uint32_t vh4[4][4], vl4[4][4];
#pragma unroll
                for (int dq = 0; dq < 4; dq++) {
                    int dcol = (dh2 * 4 + dq) * 16 + (lane >> 4) * 8;
                    uint32_t off = ASW((uint32_t)(krow * 256 + dcol * 2));
                    ldsm4t(vh4[dq], sVh + off);
                    ldsm4t(vl4[dq], sVl + off);
                }
#pragma unroll
                for (int dq = 0; dq < 4; dq++) {
                    int dg = dh2 * 4 + dq;
                    mma_bf16(oacc[dg * 2],     aH, vh4[dq]);
                    mma_bf16(oacc[dg * 2 + 1], aH, vh4[dq] + 2);
                }
#pragma unroll
                for (int dq = 0; dq < 4; dq++) {
                    int dg = dh2 * 4 + dq;
                    mma_bf16(oacc[dg * 2],     aH, vl4[dq]);
                    mma_bf16(oacc[dg * 2 + 1], aH, vl4[dq] + 2);
                }
#pragma unroll
                for (int dq = 0; dq < 4; dq++) {
                    int dg = dh2 * 4 + dq;
                    mma_bf16(oacc[dg * 2],     aL, vh4[dq]);
                    mma_bf16(oacc[dg * 2 + 1], aL, vh4[dq] + 2);
                }
            }
        }
        __syncthreads();
        if (kt + 2 < nkt) load_kv(kt + 2, s);
    }

    // ---- normalize + split + store bf16 hi/lo y ----
    float il0 = 1.f / rL0, il1 = 1.f / rL1;
    size_t row0 = ((size_t)b * TT + r0g) * DM + h * DH;
    size_t row1 = row0 + (size_t)8 * DM;
#pragma unroll
    for (int dt = 0; dt < 16; dt++) {
        int c = dt * 8 + (lane & 3) * 2;
        float v0 = oacc[dt][0] * il0, v1 = oacc[dt][1] * il0;
        float v2 = oacc[dt][2] * il1, v3 = oacc[dt][3] * il1;
        __nv_bfloat16 h0 = __float2bfloat16(v0), h1 = __float2bfloat16(v1);
        __nv_bfloat16 h2 = __float2bfloat16(v2), h3 = __float2bfloat16(v3);
        *(uint32_t*)(g_yh + row0 + c) = pack_bf2(h0, h1);
        *(uint32_t*)(g_yh + row1 + c) = pack_bf2(h2, h3);
        *(uint32_t*)(g_yl + row0 + c) = pack_bf2(__float2bfloat16(v0 - __bfloat162float(h0)),
                                                 __float2bfloat16(v1 - __bfloat162float(h1)));
        *(uint32_t*)(g_yl + row1 + c) = pack_bf2(__float2bfloat16(v2 - __bfloat162float(h2)),
                                                 __float2bfloat16(v3 - __bfloat162float(h3)));
    }
}

// ======================================================================
extern "C" void kernel_launch(void* const* d_in, const int* in_sizes, int n_in,
                              void* d_out, int out_size)
{
    const float* x   = (const float*)d_in[0];
    const float* Wq  = (const float*)d_in[1];
    const float* Wkv = (const float*)d_in[2];
    const float* Wo  = (const float*)d_in[3];
    float* out = (float*)d_out;

    __nv_bfloat16 *xh, *xl, *wqh, *wql, *wkh, *wkl, *woh, *wol, *yh, *yl;
    cudaGetSymbolAddress((void**)&xh,  g_xh);  cudaGetSymbolAddress((void**)&xl,  g_xl);
    cudaGetSymbolAddress((void**)&wqh, g_wqh); cudaGetSymbolAddress((void**)&wql, g_wql);
    cudaGetSymbolAddress((void**)&wkh, g_wkh); cudaGetSymbolAddress((void**)&wkl, g_wkl);
    cudaGetSymbolAddress((void**)&woh, g_woh); cudaGetSymbolAddress((void**)&wol, g_wol);
    cudaGetSymbolAddress((void**)&yh,  g_yh);  cudaGetSymbolAddress((void**)&yl,  g_yl);

    cudaFuncSetAttribute(gemm_mma128, cudaFuncAttributeMaxDynamicSharedMemorySize, GEMM_SMEM);
    cudaFuncSetAttribute(gemm_qkv,    cudaFuncAttributeMaxDynamicSharedMemorySize, GEMM_SMEM);
    cudaFuncSetAttribute(attn_mma,    cudaFuncAttributeMaxDynamicSharedMemorySize, ATTN_SMEM);

    // 0) fp32 -> bf16 hi/lo splits (x + all three weights, one launch)
    {
        int n0 = BT * DM, n1 = NQ * DM, n2 = NKV * DM, n3 = DM * DM;
        conv_all<<<(n0 + n1 + n2 + n3 + 255) / 256, 256>>>(
            x, xh, xl, n0, Wq, wqh, wql, n1, Wkv, wkh, wkl, n2, Wo, woh, wol, n3);
    }
    // 1) fused ab_q / ab_kv projections (one launch, 736 CTAs, 2/SM)
    {
        dim3 g(QTILES + KVTILES, BT / GBM);
        gemm_qkv<<<g, 128, GEMM_SMEM>>>(xh, xl);
    }
    // 2) q,k,v (+rotary) -> bf16 hi/lo
    qkv_kernel<<<BT, 128>>>();
    // 3) causal attention (tensor cores, 2 CTAs/SM) -> yh/yl   [profiled slot]
    {
        dim3 g(TT / 64, NH, NB);
        attn_mma<<<g, 128, ATTN_SMEM>>>();
    }
    // 4) out = y @ W_o^T (4096 x 2048), 1024 CTAs, 2/SM
    {
        dim3 g(DM / GBN, BT / GBM);
        gemm_mma128<<<g, 128, GEMM_SMEM>>>(yh, yl, woh, wol, out, DM, DM);
    }
}

// round 13
// speedup vs baseline: 1.2030x; 1.0648x over previous
#include <cuda_runtime.h>
#include <cuda_bf16.h>
#include <cuda_fp16.h>
#include <cstdint>
#include <math.h>

// ---------------- problem constants ----------------
#define NB     2
#define TT     2048
#define BT     4096      // NB*TT tokens
#define DM     2048
#define NH     16
#define DH     128
#define CH     144       // NH + DH
#define RQ     6
#define RKV    4
#define NQ     864       // RQ*CH
#define NKV    576       // RKV*CH

// ---------------- scratch (device globals; no allocs allowed) ----------------
__device__ float g_abq [BT * NQ];
__device__ float g_abkv[BT * NKV];

// bf16 hi/lo split scratch (GEMM path)
__device__ __nv_bfloat16 g_xh [BT * DM],  g_xl [BT * DM];
__device__ __nv_bfloat16 g_wqh[NQ * DM],  g_wql[NQ * DM];
__device__ __nv_bfloat16 g_wkh[NKV * DM], g_wkl[NKV * DM];
__device__ __nv_bfloat16 g_woh[DM * DM],  g_wol[DM * DM];
__device__ __nv_bfloat16 g_yh [BT * DM],  g_yl [BT * DM];

// q/k/v fp16 hi/lo, layout [b,h,t,d]
#define QKV_ELEMS (NB * NH * TT * DH)
__device__ __half g_qh[QKV_ELEMS], g_ql[QKV_ELEMS];
__device__ __half g_kh[QKV_ELEMS], g_kl[QKV_ELEMS];
__device__ __half g_vh[QKV_ELEMS], g_vl[QKV_ELEMS];

// ================= helpers =================
__device__ __forceinline__ uint32_t smem_u32(const void* p) {
    uint32_t a;
    asm("{ .reg .u64 t; cvta.to.shared.u64 t, %1; cvt.u32.u64 %0, t; }" : "=r"(a) : "l"(p));
    return a;
}
#define SWZ(o)  ((o) ^ (((o) >> 3) & 0x70))   // 128B-row swizzle (GEMM tiles)
#define ASW(o)  ((o) ^ (((o) >> 4) & 0x70))   // 256B-row swizzle (attn tiles)

__device__ __forceinline__ void ldsm4(uint32_t* r, uint32_t addr) {
    asm volatile("ldmatrix.sync.aligned.m8n8.x4.shared.b16 {%0,%1,%2,%3}, [%4];"
        : "=r"(r[0]), "=r"(r[1]), "=r"(r[2]), "=r"(r[3]) : "r"(addr));
}
__device__ __forceinline__ void ldsm4t(uint32_t* r, uint32_t addr) {
    asm volatile("ldmatrix.sync.aligned.m8n8.x4.trans.shared.b16 {%0,%1,%2,%3}, [%4];"
        : "=r"(r[0]), "=r"(r[1]), "=r"(r[2]), "=r"(r[3]) : "r"(addr));
}
__device__ __forceinline__ void mma_bf16(float* c, const uint32_t* a, const uint32_t* b) {
    asm volatile("mma.sync.aligned.m16n8k16.row.col.f32.bf16.bf16.f32 "
        "{%0,%1,%2,%3}, {%4,%5,%6,%7}, {%8,%9}, {%0,%1,%2,%3};"
        : "+f"(c[0]), "+f"(c[1]), "+f"(c[2]), "+f"(c[3])
        : "r"(a[0]), "r"(a[1]), "r"(a[2]), "r"(a[3]), "r"(b[0]), "r"(b[1]));
}
__device__ __forceinline__ void mma_f16(float* c, const uint32_t* a, const uint32_t* b) {
    asm volatile("mma.sync.aligned.m16n8k16.row.col.f32.f16.f16.f32 "
        "{%0,%1,%2,%3}, {%4,%5,%6,%7}, {%8,%9}, {%0,%1,%2,%3};"
        : "+f"(c[0]), "+f"(c[1]), "+f"(c[2]), "+f"(c[3])
        : "r"(a[0]), "r"(a[1]), "r"(a[2]), "r"(a[3]), "r"(b[0]), "r"(b[1]));
}
#define CP_ASYNC(dst, src, sz) \
    asm volatile("cp.async.cg.shared.global [%0], [%1], 16, %2;" \
        :: "r"(dst), "l"(src), "r"(sz) : "memory")
#define CP_COMMIT() asm volatile("cp.async.commit_group;" ::: "memory")
#define CP_WAIT(n)  asm volatile("cp.async.wait_group %0;" :: "n"(n) : "memory")

__device__ __forceinline__ uint32_t pack_bf2(__nv_bfloat16 lo, __nv_bfloat16 hi) {
    __nv_bfloat162 t; t.x = lo; t.y = hi;
    return *reinterpret_cast<uint32_t*>(&t);
}
__device__ __forceinline__ uint32_t pack_h2(__half lo, __half hi) {
    __half2 t; t.x = lo; t.y = hi;
    return *reinterpret_cast<uint32_t*>(&t);
}

// ======================================================================
// fused fp32 -> bf16 hi/lo split of all four tensors (one launch)
// ======================================================================
__global__ __launch_bounds__(256) void conv_all(
    const float* __restrict__ s0, __nv_bfloat16* __restrict__ h0, __nv_bfloat16* __restrict__ l0, int n0,
    const float* __restrict__ s1, __nv_bfloat16* __restrict__ h1, __nv_bfloat16* __restrict__ l1, int n1,
    const float* __restrict__ s2, __nv_bfloat16* __restrict__ h2, __nv_bfloat16* __restrict__ l2, int n2,
    const float* __restrict__ s3, __nv_bfloat16* __restrict__ h3, __nv_bfloat16* __restrict__ l3, int n3)
{
    int i = blockIdx.x * 256 + threadIdx.x;
    const float* s; __nv_bfloat16 *h, *l; int j;
    if (i < n0)                     { s = s0; h = h0; l = l0; j = i; }
    else if (i < n0 + n1)           { s = s1; h = h1; l = l1; j = i - n0; }
    else if (i < n0 + n1 + n2)      { s = s2; h = h2; l = l2; j = i - n0 - n1; }
    else if (i < n0 + n1 + n2 + n3) { s = s3; h = h3; l = l3; j = i - n0 - n1 - n2; }
    else return;
    float v = s[j];
    __nv_bfloat16 hi = __float2bfloat16(v);
    h[j] = hi;
    l[j] = __float2bfloat16(v - __bfloat162float(hi));
}

// ======================================================================
// mma.sync bf16-split NT GEMM: 128x64 block tile, 128 threads (4 warps,
// each 64x32), 2-stage pipeline, 48KB/stage -> 2 CTAs/SM. (R11 winner)
// ======================================================================
#define GBM      128
#define GBN      64
#define A_ST     16384
#define B_ST     8192
#define STAGE_B  (2 * A_ST + 2 * B_ST)
#define GEMM_SMEM (2 * STAGE_B + 1024)

__device__ __forceinline__ void gemm_body(
    const __nv_bfloat16* __restrict__ Ah, const __nv_bfloat16* __restrict__ Al,
    const __nv_bfloat16* __restrict__ Bh, const __nv_bfloat16* __restrict__ Bl,
    float* __restrict__ C, int N, int K, int bm, int bn, uint32_t smem)
{
    const int tid  = threadIdx.x;
    const int wid  = tid >> 5, lane = tid & 31;
    const int wm   = (wid >> 1) * 64;
    const int wn   = (wid & 1) * 32;
    const int nchunk = K >> 6;

    auto load_chunk = [&](int c, int buf) {
        const uint32_t base = smem + buf * STAGE_B;
        const int k0 = c * 64;
#pragma unroll
        for (int u = tid; u < 1024; u += 128) {
            int row = u >> 3, seg = u & 7;
            uint32_t so = SWZ((uint32_t)(row * 128 + seg * 16));
            size_t ga = (size_t)(bm + row) * K + k0 + seg * 8;
            CP_ASYNC(base + so,        Ah + ga, 16);
            CP_ASYNC(base + A_ST + so, Al + ga, 16);
        }
#pragma unroll
        for (int u = tid; u < 512; u += 128) {
            int row = u >> 3, seg = u & 7;
            uint32_t so = SWZ((uint32_t)(row * 128 + seg * 16));
            int n = bn + row;
            int sz = (n < N) ? 16 : 0;
            size_t gb = (size_t)(n < N ? n : 0) * K + k0 + seg * 8;
            CP_ASYNC(base + 2 * A_ST + so,        Bh + gb, sz);
            CP_ASYNC(base + 2 * A_ST + B_ST + so, Bl + gb, sz);
        }
        CP_COMMIT();
    };

    float acc[4][4][4];
#pragma unroll
    for (int i = 0; i < 4; i++)
#pragma unroll
        for (int j = 0; j < 4; j++)
#pragma unroll
            for (int q = 0; q < 4; q++) acc[i][j][q] = 0.f;

    load_chunk(0, 0);

    for (int c = 0; c < nchunk; c++) {
        const int buf = c & 1;
        if (c + 1 < nchunk) {
            load_chunk(c + 1, buf ^ 1);
            CP_WAIT(1);
        } else {
            CP_WAIT(0);
        }
        __syncthreads();

        const uint32_t sa_h = smem + buf * STAGE_B;
        const uint32_t sa_l = sa_h + A_ST;
        const uint32_t sb_h = sa_h + 2 * A_ST;
        const uint32_t sb_l = sb_h + B_ST;

#pragma unroll
        for (int ks = 0; ks < 4; ks++) {
            const int kk = ks * 16;
            uint32_t ah[4][4], al[4][4], bh[2][4], bl[2][4];
            {
                int r = lane & 15, ck = lane >> 4;
#pragma unroll
                for (int mt = 0; mt < 4; mt++) {
                    uint32_t off = SWZ((uint32_t)((wm + mt * 16 + r) * 128 + (kk + ck * 8) * 2));
                    ldsm4(ah[mt], sa_h + off);
                    ldsm4(al[mt], sa_l + off);
                }
            }
            {
                int grp = lane >> 3, ln = lane & 7;
#pragma unroll
                for (int np = 0; np < 2; np++) {
                    int n = wn + np * 16 + (grp >> 1) * 8 + ln;
                    int kc = kk + (grp & 1) * 8;
                    uint32_t off = SWZ((uint32_t)(n * 128 + kc * 2));
                    ldsm4(bh[np], sb_h + off);
                    ldsm4(bl[np], sb_l + off);
                }
            }
#pragma unroll
            for (int mt = 0; mt < 4; mt++)
#pragma unroll
                for (int nt = 0; nt < 4; nt++)
                    mma_bf16(acc[mt][nt], ah[mt], &bh[nt >> 1][(nt & 1) * 2]);
#pragma unroll
            for (int mt = 0; mt < 4; mt++)
#pragma unroll
                for (int nt = 0; nt < 4; nt++)
                    mma_bf16(acc[mt][nt], ah[mt], &bl[nt >> 1][(nt & 1) * 2]);
#pragma unroll
            for (int mt = 0; mt < 4; mt++)
#pragma unroll
                for (int nt = 0; nt < 4; nt++)
                    mma_bf16(acc[mt][nt], al[mt], &bh[nt >> 1][(nt & 1) * 2]);
        }
        __syncthreads();
    }

#pragma unroll
    for (int mt = 0; mt < 4; mt++) {
        int r0 = bm + wm + mt * 16 + (lane >> 2);
#pragma unroll
        for (int nt = 0; nt < 4; nt++) {
            int col = bn + wn + nt * 8 + (lane & 3) * 2;
            if (col < N) {
                float* c0 = C + (size_t)r0 * N + col;
                float* c1 = C + (size_t)(r0 + 8) * N + col;
                c0[0] = acc[mt][nt][0]; c0[1] = acc[mt][nt][1];
                c1[0] = acc[mt][nt][2]; c1[1] = acc[mt][nt][3];
            }
        }
    }
}

__global__ __launch_bounds__(128) void gemm_mma128(
    const __nv_bfloat16* __restrict__ Ah, const __nv_bfloat16* __restrict__ Al,
    const __nv_bfloat16* __restrict__ Bh, const __nv_bfloat16* __restrict__ Bl,
    float* __restrict__ C, int N, int K)
{
    extern __shared__ char smraw[];
    const uint32_t smem0 = smem_u32(smraw);
    const uint32_t smem  = (smem0 + 1023) & ~1023u;
    gemm_body(Ah, Al, Bh, Bl, C, N, K, blockIdx.y * GBM, blockIdx.x * GBN, smem);
}

#define QTILES  14
#define KVTILES 9
__global__ __launch_bounds__(128) void gemm_qkv(
    const __nv_bfloat16* __restrict__ Ah, const __nv_bfloat16* __restrict__ Al)
{
    extern __shared__ char smraw[];
    const uint32_t smem0 = smem_u32(smraw);
    const uint32_t smem  = (smem0 + 1023) & ~1023u;
    const int bx = blockIdx.x;
    if (bx < QTILES)
        gemm_body(Ah, Al, g_wqh, g_wql, g_abq, NQ, DM,
                  blockIdx.y * GBM, bx * GBN, smem);
    else
        gemm_body(Ah, Al, g_wkh, g_wkl, g_abkv, NKV, DM,
                  blockIdx.y * GBM, (bx - QTILES) * GBN, smem);
}

// ======================================================================
// qkv: rank contraction + rotary (fp32 trig) -> fp16 hi/lo q,k,v [b,h,t,d]
// ======================================================================
__global__ __launch_bounds__(128) void qkv_kernel()
{
    const int m = blockIdx.x;
    const int b = m >> 11;
    const int t = m & (TT - 1);
    const int d = threadIdx.x;

    __shared__ float aq  [RQ][16];
    __shared__ float bq  [RQ][128];
    __shared__ float akv [RKV][16];
    __shared__ float braw[RKV][128];
    __shared__ float brot[RKV][128];

    const float* abq = g_abq + (size_t)m * NQ;
    for (int idx = d; idx < NQ; idx += 128) {
        int r = idx / CH, c = idx - r * CH;
        float v = abq[idx];
        if (c < 16) aq[r][c] = v; else bq[r][c - 16] = v;
    }
    const float* abkv = g_abkv + (size_t)m * NKV;
    for (int idx = d; idx < NKV; idx += 128) {
        int r = idx / CH, c = idx - r * CH;
        float v = abkv[idx];
        if (c < 16) akv[r][c] = v; else braw[r][c - 16] = v;
    }
    __syncthreads();

    {
        int j = d & 63;
        float inv = powf(1e-4f, (float)j * (1.f / 64.f));
        float sv, cv;
        sincosf((float)t * inv, &sv, &cv);
#pragma unroll
        for (int r = 0; r < RKV; r++) {
            float x1 = braw[r][j], x2 = braw[r][j + 64];
            brot[r][d] = (d < 64) ? (x1 * cv + x2 * sv) : (-x1 * sv + x2 * cv);
        }
    }

    const size_t base = (((size_t)b * NH) * TT + t) * DH + d;
#pragma unroll
    for (int h = 0; h < NH; h++) {
        float qv = 0.f;
#pragma unroll
        for (int r = 0; r < RQ; r++) qv += aq[r][h] * bq[r][d];
        qv *= (1.f / 6.f);
        float kv = (akv[0][h] * brot[0][d] + akv[1][h] * brot[1][d]) * 0.5f;
        float vv = (akv[2][h] * brot[2][d] + akv[3][h] * brot[3][d]) * 0.5f;
        size_t o = base + (size_t)h * TT * DH;
        __half qhh = __float2half(qv);
        __half khh = __float2half(kv);
        __half vhh = __float2half(vv);
        g_qh[o] = qhh; g_ql[o] = __float2half(qv - __half2float(qhh));
        g_kh[o] = khh; g_kl[o] = __float2half(kv - __half2float(khh));
        g_vh[o] = vhh; g_vl[o] = __float2half(vv - __half2float(vhh));
    }
}

// ======================================================================
// flash attention, causal, mma.sync fp16 split.
// 128 threads (4 warps x 16 q-rows = 64-row Q tile), 32-row KV stages,
// 2-stage double buffer -> 97KB smem -> 2 CTAs/SM.
// QK: 3 passes (err 2^-22). PV: P single fp16 x V hi/lo (2 passes).
// ======================================================================
#define ATTN_SMEM (98304 + 1024)

__global__ __launch_bounds__(128) void attn_mma()
{
    extern __shared__ char smraw[];
    const uint32_t sb0 = smem_u32(smraw);
    const uint32_t sb = (sb0 + 1023) & ~1023u;

    const int tid = threadIdx.x, wid = tid >> 5, lane = tid & 31;
    const int qt = (int)gridDim.x - 1 - (int)blockIdx.x;   // heavy tiles first
    const int h = blockIdx.y, b = blockIdx.z;
    const size_t bh = ((size_t)b * NH + h) * TT;
    const int nkt = 2 * qt + 2;                            // 32-row kv tiles

    const uint32_t sQh = sb, sQl = sb + 16384;

    {
        const char* qh = (const char*)g_qh + (bh + (size_t)qt * 64) * 256;
        const char* ql = (const char*)g_ql + (bh + (size_t)qt * 64) * 256;
        for (int u = tid; u < 1024; u += 128) {
            int row = u >> 4, seg = u & 15;
            uint32_t off = ASW((uint32_t)(row * 256 + seg * 16));
            int go = row * 256 + seg * 16;
            CP_ASYNC(sQh + off, qh + go, 16);
            CP_ASYNC(sQl + off, ql + go, 16);
        }
    }
    auto load_kv = [&](int kt, int s) {
        uint32_t base = sb + 32768 + (uint32_t)s * 32768;
        const char* kh = (const char*)g_kh + (bh + (size_t)kt * 32) * 256;
        const char* kl = (const char*)g_kl + (bh + (size_t)kt * 32) * 256;
        const char* vh = (const char*)g_vh + (bh + (size_t)kt * 32) * 256;
        const char* vl = (const char*)g_vl + (bh + (size_t)kt * 32) * 256;
        for (int u = tid; u < 512; u += 128) {
            int row = u >> 4, seg = u & 15;
            uint32_t off = ASW((uint32_t)(row * 256 + seg * 16));
            int go = row * 256 + seg * 16;
            CP_ASYNC(base + off,         kh + go, 16);
            CP_ASYNC(base + 8192 + off,  kl + go, 16);
            CP_ASYNC(base + 16384 + off, vh + go, 16);
            CP_ASYNC(base + 24576 + off, vl + go, 16);
        }
        CP_COMMIT();
    };
    load_kv(0, 0);
    if (nkt > 1) load_kv(1, 1);

    float oacc[16][4];
#pragma unroll
    for (int dt = 0; dt < 16; dt++)
#pragma unroll
        for (int e = 0; e < 4; e++) oacc[dt][e] = 0.f;
    float rM0 = -1e30f, rM1 = -1e30f, rL0 = 0.f, rL1 = 0.f;

    const float scale = 0.08838834764831845f;
    const int r0g = qt * 64 + wid * 16 + (lane >> 2);

    for (int kt = 0; kt < nkt; kt++) {
        const int s = kt & 1;
        if (kt + 1 < nkt) { CP_WAIT(1); } else { CP_WAIT(0); }
        __syncthreads();
        const uint32_t base = sb + 32768 + (uint32_t)s * 32768;
        const uint32_t sKh = base, sKl = base + 8192;
        const uint32_t sVh = base + 16384, sVl = base + 24576;

        float sacc[4][4];
#pragma unroll
        for (int nt = 0; nt < 4; nt++)
#pragma unroll
            for (int e = 0; e < 4; e++) sacc[nt][e] = 0.f;

        // ---- S = Q K^T (64x32), 3 fp16 split passes, pass-major ----
#pragma unroll
        for (int ks = 0; ks < 8; ks++) {
            uint32_t ah[4], al[4];
            {
                int r = lane & 15, ck = lane >> 4;
                uint32_t off = ASW((uint32_t)((wid * 16 + r) * 256 + (ks * 16 + ck * 8) * 2));
                ldsm4(ah, sQh + off);
                ldsm4(al, sQl + off);
            }
            uint32_t bh4[2][4], bl4[2][4];
            {
                int grp = lane >> 3, ln = lane & 7;
#pragma unroll
                for (int ng = 0; ng < 2; ng++) {
                    int n = ng * 16 + (grp >> 1) * 8 + ln;
                    int kc = ks * 16 + (grp & 1) * 8;
                    uint32_t off = ASW((uint32_t)(n * 256 + kc * 2));
                    ldsm4(bh4[ng], sKh + off);
                    ldsm4(bl4[ng], sKl + off);
                }
            }
#pragma unroll
            for (int ng = 0; ng < 2; ng++) {
                mma_f16(sacc[ng * 2],     ah, bh4[ng]);
                mma_f16(sacc[ng * 2 + 1], ah, bh4[ng] + 2);
            }
#pragma unroll
            for (int ng = 0; ng < 2; ng++) {
                mma_f16(sacc[ng * 2],     ah, bl4[ng]);
                mma_f16(sacc[ng * 2 + 1], ah, bl4[ng] + 2);
            }
#pragma unroll
            for (int ng = 0; ng < 2; ng++) {
                mma_f16(sacc[ng * 2],     al, bh4[ng]);
                mma_f16(sacc[ng * 2 + 1], al, bh4[ng] + 2);
            }
        }

        const bool domask = (kt >= 2 * qt);
        float mx0 = -1e30f, mx1 = -1e30f;
#pragma unroll
        for (int nt = 0; nt < 4; nt++) {
            int c0 = kt * 32 + nt * 8 + (lane & 3) * 2;
#pragma unroll
            for (int e = 0; e < 4; e++) {
                float v = sacc[nt][e] * scale;
                if (domask) {
                    int cc = c0 + (e & 1);
                    int rr = r0g + ((e >> 1) << 3);
                    if (cc > rr) v = -1e30f;
                }
                sacc[nt][e] = v;
            }
            mx0 = fmaxf(mx0, fmaxf(sacc[nt][0], sacc[nt][1]));
            mx1 = fmaxf(mx1, fmaxf(sacc[nt][2], sacc[nt][3]));
        }
        mx0 = fmaxf(mx0, __shfl_xor_sync(0xffffffffu, mx0, 1));
        mx0 = fmaxf(mx0, __shfl_xor_sync(0xffffffffu, mx0, 2));
        mx1 = fmaxf(mx1, __shfl_xor_sync(0xffffffffu, mx1, 1));
        mx1 = fmaxf(mx1, __shfl_xor_sync(0xffffffffu, mx1, 2));

        float nM0 = fmaxf(rM0, mx0), nM1 = fmaxf(rM1, mx1);
        float cor0 = __expf(rM0 - nM0), cor1 = __expf(rM1 - nM1);
        rM0 = nM0; rM1 = nM1;

        float sum0 = 0.f, sum1 = 0.f;
        uint32_t pH01[4], pH23[4];
#pragma unroll
        for (int nt = 0; nt < 4; nt++) {
            float p0 = __expf(sacc[nt][0] - nM0);
            float p1 = __expf(sacc[nt][1] - nM0);
            float p2 = __expf(sacc[nt][2] - nM1);
            float p3 = __expf(sacc[nt][3] - nM1);
            sum0 += p0 + p1; sum1 += p2 + p3;
            pH01[nt] = pack_h2(__float2half(p0), __float2half(p1));
            pH23[nt] = pack_h2(__float2half(p2), __float2half(p3));
        }
        sum0 += __shfl_xor_sync(0xffffffffu, sum0, 1);
        sum0 += __shfl_xor_sync(0xffffffffu, sum0, 2);
        sum1 += __shfl_xor_sync(0xffffffffu, sum1, 1);
        sum1 += __shfl_xor_sync(0xffffffffu, sum1, 2);
        rL0 = rL0 * cor0 + sum0;
        rL1 = rL1 * cor1 + sum1;

#pragma unroll
        for (int dt = 0; dt < 16; dt++) {
            oacc[dt][0] *= cor0; oacc[dt][1] *= cor0;
            oacc[dt][2] *= cor1; oacc[dt][3] *= cor1;
        }

        // ---- O += P V: P single fp16 x (Vh, Vl) = 2 passes ----
#pragma unroll
        for (int k2 = 0; k2 < 2; k2++) {
            uint32_t aH[4] = {pH01[2 * k2], pH23[2 * k2], pH01[2 * k2 + 1], pH23[2 * k2 + 1]};
            int krow = k2 * 16 + ((lane >> 3) & 1) * 8 + (lane & 7);
#pragma unroll
            for (int dh2 = 0; dh2 < 2; dh2++) {
                uint32_t vh4[4][4], vl4[4][4];
#pragma unroll
                for (int dq = 0; dq < 4; dq++) {
                    int dcol = (dh2 * 4 + dq) * 16 + (lane >> 4) * 8;
                    uint32_t off = ASW((uint32_t)(krow * 256 + dcol * 2));
                    ldsm4t(vh4[dq], sVh + off);
                    ldsm4t(vl4[dq], sVl + off);
                }
#pragma unroll
                for (int dq = 0; dq < 4; dq++) {
                    int dg = dh2 * 4 + dq;
                    mma_f16(oacc[dg * 2],     aH, vh4[dq]);
                    mma_f16(oacc[dg * 2 + 1], aH, vh4[dq] + 2);
                }
#pragma unroll
                for (int dq = 0; dq < 4; dq++) {
                    int dg = dh2 * 4 + dq;
                    mma_f16(oacc[dg * 2],     aH, vl4[dq]);
                    mma_f16(oacc[dg * 2 + 1], aH, vl4[dq] + 2);
                }
            }
        }
        __syncthreads();
        if (kt + 2 < nkt) load_kv(kt + 2, s);
    }

    // ---- normalize + split + store bf16 hi/lo y ----
    float il0 = 1.f / rL0, il1 = 1.f / rL1;
    size_t row0 = ((size_t)b * TT + r0g) * DM + h * DH;
    size_t row1 = row0 + (size_t)8 * DM;
#pragma unroll
    for (int dt = 0; dt < 16; dt++) {
        int c = dt * 8 + (lane & 3) * 2;
        float v0 = oacc[dt][0] * il0, v1 = oacc[dt][1] * il0;
        float v2 = oacc[dt][2] * il1, v3 = oacc[dt][3] * il1;
        __nv_bfloat16 h0 = __float2bfloat16(v0), h1 = __float2bfloat16(v1);
        __nv_bfloat16 h2 = __float2bfloat16(v2), h3 = __float2bfloat16(v3);
        *(uint32_t*)(g_yh + row0 + c) = pack_bf2(h0, h1);
        *(uint32_t*)(g_yh + row1 + c) = pack_bf2(h2, h3);
        *(uint32_t*)(g_yl + row0 + c) = pack_bf2(__float2bfloat16(v0 - __bfloat162float(h0)),
                                                 __float2bfloat16(v1 - __bfloat162float(h1)));
        *(uint32_t*)(g_yl + row1 + c) = pack_bf2(__float2bfloat16(v2 - __bfloat162float(h2)),
                                                 __float2bfloat16(v3 - __bfloat162float(h3)));
    }
}

// ======================================================================
extern "C" void kernel_launch(void* const* d_in, const int* in_sizes, int n_in,
                              void* d_out, int out_size)
{
    const float* x   = (const float*)d_in[0];
    const float* Wq  = (const float*)d_in[1];
    const float* Wkv = (const float*)d_in[2];
    const float* Wo  = (const float*)d_in[3];
    float* out = (float*)d_out;

    __nv_bfloat16 *xh, *xl, *wqh, *wql, *wkh, *wkl, *woh, *wol, *yh, *yl;
    cudaGetSymbolAddress((void**)&xh,  g_xh);  cudaGetSymbolAddress((void**)&xl,  g_xl);
    cudaGetSymbolAddress((void**)&wqh, g_wqh); cudaGetSymbolAddress((void**)&wql, g_wql);
    cudaGetSymbolAddress((void**)&wkh, g_wkh); cudaGetSymbolAddress((void**)&wkl, g_wkl);
    cudaGetSymbolAddress((void**)&woh, g_woh); cudaGetSymbolAddress((void**)&wol, g_wol);
    cudaGetSymbolAddress((void**)&yh,  g_yh);  cudaGetSymbolAddress((void**)&yl,  g_yl);

    cudaFuncSetAttribute(gemm_mma128, cudaFuncAttributeMaxDynamicSharedMemorySize, GEMM_SMEM);
    cudaFuncSetAttribute(gemm_qkv,    cudaFuncAttributeMaxDynamicSharedMemorySize, GEMM_SMEM);
    cudaFuncSetAttribute(attn_mma,    cudaFuncAttributeMaxDynamicSharedMemorySize, ATTN_SMEM);

    // 0) fp32 -> bf16 hi/lo splits (x + all three weights, one launch)
    {
        int n0 = BT * DM, n1 = NQ * DM, n2 = NKV * DM, n3 = DM * DM;
        conv_all<<<(n0 + n1 + n2 + n3 + 255) / 256, 256>>>(
            x, xh, xl, n0, Wq, wqh, wql, n1, Wkv, wkh, wkl, n2, Wo, woh, wol, n3);
    }
    // 1) fused ab_q / ab_kv projections (one launch, 736 CTAs, 2/SM)
    {
        dim3 g(QTILES + KVTILES, BT / GBM);
        gemm_qkv<<<g, 128, GEMM_SMEM>>>(xh, xl);
    }
    // 2) q,k,v (+rotary) -> fp16 hi/lo
    qkv_kernel<<<BT, 128>>>();
    // 3) causal attention (fp16 tensor cores, 2 CTAs/SM) -> yh/yl
    {
        dim3 g(TT / 64, NH, NB);
        attn_mma<<<g, 128, ATTN_SMEM>>>();
    }
    // 4) out = y @ W_o^T (4096 x 2048), 1024 CTAs, 2/SM
    {
        dim3 g(DM / GBN, BT / GBM);
        gemm_mma128<<<g, 128, GEMM_SMEM>>>(yh, yl, woh, wol, out, DM, DM);
    }
}

// round 14
// speedup vs baseline: 1.5193x; 1.2629x over previous
#include <cuda_runtime.h>
#include <cuda_bf16.h>
#include <cuda_fp16.h>
#include <cstdint>
#include <math.h>

// ---------------- problem constants ----------------
#define NB     2
#define TT     2048
#define BT     4096      // NB*TT tokens
#define DM     2048
#define NH     16
#define DH     128
#define CH     144       // NH + DH
#define RQ     6
#define RKV    4
#define NQ     864       // RQ*CH
#define NKV    576       // RKV*CH

// ---------------- scratch (device globals; no allocs allowed) ----------------
__device__ float g_abq [BT * NQ];
__device__ float g_abkv[BT * NKV];

// bf16 hi/lo split scratch (projection GEMM path)
__device__ __nv_bfloat16 g_xh [BT * DM],  g_xl [BT * DM];
__device__ __nv_bfloat16 g_wqh[NQ * DM],  g_wql[NQ * DM];
__device__ __nv_bfloat16 g_wkh[NKV * DM], g_wkl[NKV * DM];

// fp16 single-precision path for output GEMM
__device__ __half g_wo16[DM * DM];
__device__ __half g_y16 [BT * DM];

// q/k/v fp16 hi/lo, layout [b,h,t,d]
#define QKV_ELEMS (NB * NH * TT * DH)
__device__ __half g_qh[QKV_ELEMS], g_ql[QKV_ELEMS];
__device__ __half g_kh[QKV_ELEMS], g_kl[QKV_ELEMS];
__device__ __half g_vh[QKV_ELEMS], g_vl[QKV_ELEMS];

// ================= helpers =================
__device__ __forceinline__ uint32_t smem_u32(const void* p) {
    uint32_t a;
    asm("{ .reg .u64 t; cvta.to.shared.u64 t, %1; cvt.u32.u64 %0, t; }" : "=r"(a) : "l"(p));
    return a;
}
#define SWZ(o)  ((o) ^ (((o) >> 3) & 0x70))   // 128B-row swizzle (GEMM tiles)
#define ASW(o)  ((o) ^ (((o) >> 4) & 0x70))   // 256B-row swizzle (attn tiles)

__device__ __forceinline__ void ldsm4(uint32_t* r, uint32_t addr) {
    asm volatile("ldmatrix.sync.aligned.m8n8.x4.shared.b16 {%0,%1,%2,%3}, [%4];"
        : "=r"(r[0]), "=r"(r[1]), "=r"(r[2]), "=r"(r[3]) : "r"(addr));
}
__device__ __forceinline__ void ldsm4t(uint32_t* r, uint32_t addr) {
    asm volatile("ldmatrix.sync.aligned.m8n8.x4.trans.shared.b16 {%0,%1,%2,%3}, [%4];"
        : "=r"(r[0]), "=r"(r[1]), "=r"(r[2]), "=r"(r[3]) : "r"(addr));
}
__device__ __forceinline__ void mma_bf16(float* c, const uint32_t* a, const uint32_t* b) {
    asm volatile("mma.sync.aligned.m16n8k16.row.col.f32.bf16.bf16.f32 "
        "{%0,%1,%2,%3}, {%4,%5,%6,%7}, {%8,%9}, {%0,%1,%2,%3};"
        : "+f"(c[0]), "+f"(c[1]), "+f"(c[2]), "+f"(c[3])
        : "r"(a[0]), "r"(a[1]), "r"(a[2]), "r"(a[3]), "r"(b[0]), "r"(b[1]));
}
__device__ __forceinline__ void mma_f16(float* c, const uint32_t* a, const uint32_t* b) {
    asm volatile("mma.sync.aligned.m16n8k16.row.col.f32.f16.f16.f32 "
        "{%0,%1,%2,%3}, {%4,%5,%6,%7}, {%8,%9}, {%0,%1,%2,%3};"
        : "+f"(c[0]), "+f"(c[1]), "+f"(c[2]), "+f"(c[3])
        : "r"(a[0]), "r"(a[1]), "r"(a[2]), "r"(a[3]), "r"(b[0]), "r"(b[1]));
}
#define CP_ASYNC(dst, src, sz) \
    asm volatile("cp.async.cg.shared.global [%0], [%1], 16, %2;" \
        :: "r"(dst), "l"(src), "r"(sz) : "memory")
#define CP_COMMIT() asm volatile("cp.async.commit_group;" ::: "memory")
#define CP_WAIT(n)  asm volatile("cp.async.wait_group %0;" :: "n"(n) : "memory")

__device__ __forceinline__ uint32_t pack_h2(__half lo, __half hi) {
    __half2 t; t.x = lo; t.y = hi;
    return *reinterpret_cast<uint32_t*>(&t);
}

// ======================================================================
// fused fp32 -> split conversions:
//   x, Wq, Wkv -> bf16 hi/lo;  Wo -> single fp16
// ======================================================================
__global__ __launch_bounds__(256) void conv_all(
    const float* __restrict__ s0, __nv_bfloat16* __restrict__ h0, __nv_bfloat16* __restrict__ l0, int n0,
    const float* __restrict__ s1, __nv_bfloat16* __restrict__ h1, __nv_bfloat16* __restrict__ l1, int n1,
    const float* __restrict__ s2, __nv_bfloat16* __restrict__ h2, __nv_bfloat16* __restrict__ l2, int n2,
    const float* __restrict__ s3, __half* __restrict__ h3, int n3)
{
    int i = blockIdx.x * 256 + threadIdx.x;
    if (i < n0) {
        float v = s0[i];
        __nv_bfloat16 hi = __float2bfloat16(v);
        h0[i] = hi; l0[i] = __float2bfloat16(v - __bfloat162float(hi));
    } else if (i < n0 + n1) {
        int j = i - n0;
        float v = s1[j];
        __nv_bfloat16 hi = __float2bfloat16(v);
        h1[j] = hi; l1[j] = __float2bfloat16(v - __bfloat162float(hi));
    } else if (i < n0 + n1 + n2) {
        int j = i - n0 - n1;
        float v = s2[j];
        __nv_bfloat16 hi = __float2bfloat16(v);
        h2[j] = hi; l2[j] = __float2bfloat16(v - __bfloat162float(hi));
    } else if (i < n0 + n1 + n2 + n3) {
        int j = i - n0 - n1 - n2;
        h3[j] = __float2half(s3[j]);
    }
}

// ======================================================================
// bf16-split projection GEMM: 128x64 tile, 128 threads, 2-stage,
// 48KB/stage -> 2 CTAs/SM.  (R11/R12 winner, unchanged)
// ======================================================================
#define GBM      128
#define GBN      64
#define A_ST     16384
#define B_ST     8192
#define STAGE_B  (2 * A_ST + 2 * B_ST)
#define GEMM_SMEM (2 * STAGE_B + 1024)

__device__ __forceinline__ void gemm_body(
    const __nv_bfloat16* __restrict__ Ah, const __nv_bfloat16* __restrict__ Al,
    const __nv_bfloat16* __restrict__ Bh, const __nv_bfloat16* __restrict__ Bl,
    float* __restrict__ C, int N, int K, int bm, int bn, uint32_t smem)
{
    const int tid  = threadIdx.x;
    const int wid  = tid >> 5, lane = tid & 31;
    const int wm   = (wid >> 1) * 64;
    const int wn   = (wid & 1) * 32;
    const int nchunk = K >> 6;

    auto load_chunk = [&](int c, int buf) {
        const uint32_t base = smem + buf * STAGE_B;
        const int k0 = c * 64;
#pragma unroll
        for (int u = tid; u < 1024; u += 128) {
            int row = u >> 3, seg = u & 7;
            uint32_t so = SWZ((uint32_t)(row * 128 + seg * 16));
            size_t ga = (size_t)(bm + row) * K + k0 + seg * 8;
            CP_ASYNC(base + so,        Ah + ga, 16);
            CP_ASYNC(base + A_ST + so, Al + ga, 16);
        }
#pragma unroll
        for (int u = tid; u < 512; u += 128) {
            int row = u >> 3, seg = u & 7;
            uint32_t so = SWZ((uint32_t)(row * 128 + seg * 16));
            int n = bn + row;
            int sz = (n < N) ? 16 : 0;
            size_t gb = (size_t)(n < N ? n : 0) * K + k0 + seg * 8;
            CP_ASYNC(base + 2 * A_ST + so,        Bh + gb, sz);
            CP_ASYNC(base + 2 * A_ST + B_ST + so, Bl + gb, sz);
        }
        CP_COMMIT();
    };

    float acc[4][4][4];
#pragma unroll
    for (int i = 0; i < 4; i++)
#pragma unroll
        for (int j = 0; j < 4; j++)
#pragma unroll
            for (int q = 0; q < 4; q++) acc[i][j][q] = 0.f;

    load_chunk(0, 0);

    for (int c = 0; c < nchunk; c++) {
        const int buf = c & 1;
        if (c + 1 < nchunk) {
            load_chunk(c + 1, buf ^ 1);
            CP_WAIT(1);
        } else {
            CP_WAIT(0);
        }
        __syncthreads();

        const uint32_t sa_h = smem + buf * STAGE_B;
        const uint32_t sa_l = sa_h + A_ST;
        const uint32_t sb_h = sa_h + 2 * A_ST;
        const uint32_t sb_l = sb_h + B_ST;

#pragma unroll
        for (int ks = 0; ks < 4; ks++) {
            const int kk = ks * 16;
            uint32_t ah[4][4], al[4][4], bh[2][4], bl[2][4];
            {
                int r = lane & 15, ck = lane >> 4;
#pragma unroll
                for (int mt = 0; mt < 4; mt++) {
                    uint32_t off = SWZ((uint32_t)((wm + mt * 16 + r) * 128 + (kk + ck * 8) * 2));
                    ldsm4(ah[mt], sa_h + off);
                    ldsm4(al[mt], sa_l + off);
                }
            }
            {
                int grp = lane >> 3, ln = lane & 7;
#pragma unroll
                for (int np = 0; np < 2; np++) {
                    int n = wn + np * 16 + (grp >> 1) * 8 + ln;
                    int kc = kk + (grp & 1) * 8;
                    uint32_t off = SWZ((uint32_t)(n * 128 + kc * 2));
                    ldsm4(bh[np], sb_h + off);
                    ldsm4(bl[np], sb_l + off);
                }
            }
#pragma unroll
            for (int mt = 0; mt < 4; mt++)
#pragma unroll
                for (int nt = 0; nt < 4; nt++)
                    mma_bf16(acc[mt][nt], ah[mt], &bh[nt >> 1][(nt & 1) * 2]);
#pragma unroll
            for (int mt = 0; mt < 4; mt++)
#pragma unroll
                for (int nt = 0; nt < 4; nt++)
                    mma_bf16(acc[mt][nt], ah[mt], &bl[nt >> 1][(nt & 1) * 2]);
#pragma unroll
            for (int mt = 0; mt < 4; mt++)
#pragma unroll
                for (int nt = 0; nt < 4; nt++)
                    mma_bf16(acc[mt][nt], al[mt], &bh[nt >> 1][(nt & 1) * 2]);
        }
        __syncthreads();
    }

#pragma unroll
    for (int mt = 0; mt < 4; mt++) {
        int r0 = bm + wm + mt * 16 + (lane >> 2);
#pragma unroll
        for (int nt = 0; nt < 4; nt++) {
            int col = bn + wn + nt * 8 + (lane & 3) * 2;
            if (col < N) {
                float* c0 = C + (size_t)r0 * N + col;
                float* c1 = C + (size_t)(r0 + 8) * N + col;
                c0[0] = acc[mt][nt][0]; c0[1] = acc[mt][nt][1];
                c1[0] = acc[mt][nt][2]; c1[1] = acc[mt][nt][3];
            }
        }
    }
}

#define QTILES  14
#define KVTILES 9
__global__ __launch_bounds__(128) void gemm_qkv(
    const __nv_bfloat16* __restrict__ Ah, const __nv_bfloat16* __restrict__ Al)
{
    extern __shared__ char smraw[];
    const uint32_t smem0 = smem_u32(smraw);
    const uint32_t smem  = (smem0 + 1023) & ~1023u;
    const int bx = blockIdx.x;
    if (bx < QTILES)
        gemm_body(Ah, Al, g_wqh, g_wql, g_abq, NQ, DM,
                  blockIdx.y * GBM, bx * GBN, smem);
    else
        gemm_body(Ah, Al, g_wkh, g_wkl, g_abkv, NKV, DM,
                  blockIdx.y * GBM, (bx - QTILES) * GBN, smem);
}

// ======================================================================
// single-pass fp16 output GEMM: out = y16 @ Wo16^T  (post-softmax path)
// 128x64 tile, 128 threads (4 warps, 64x32 each), 2-stage, 24KB/stage.
// ======================================================================
#define OA_ST   16384                 // 128 x 64 fp16
#define OB_ST   8192                  // 64 x 64 fp16
#define OSTAGE  (OA_ST + OB_ST)       // 24KB
#define GEMM_OUT_SMEM (2 * OSTAGE + 1024)

__global__ __launch_bounds__(128) void gemm_out(
    const __half* __restrict__ A, const __half* __restrict__ B,
    float* __restrict__ C)
{
    extern __shared__ char smraw[];
    const uint32_t smem0 = smem_u32(smraw);
    const uint32_t smem  = (smem0 + 1023) & ~1023u;

    const int tid  = threadIdx.x;
    const int wid  = tid >> 5, lane = tid & 31;
    const int wm   = (wid >> 1) * 64;
    const int wn   = (wid & 1) * 32;
    const int bm   = blockIdx.y * 128;
    const int bn   = blockIdx.x * 64;
    const int nchunk = DM >> 6;      // 32

    auto load_chunk = [&](int c, int buf) {
        const uint32_t base = smem + buf * OSTAGE;
        const int k0 = c * 64;
#pragma unroll
        for (int u = tid; u < 1024; u += 128) {
            int row = u >> 3, seg = u & 7;
            uint32_t so = SWZ((uint32_t)(row * 128 + seg * 16));
            CP_ASYNC(base + so, A + (size_t)(bm + row) * DM + k0 + seg * 8, 16);
        }
#pragma unroll
        for (int u = tid; u < 512; u += 128) {
            int row = u >> 3, seg = u & 7;
            uint32_t so = SWZ((uint32_t)(row * 128 + seg * 16));
            CP_ASYNC(base + OA_ST + so, B + (size_t)(bn + row) * DM + k0 + seg * 8, 16);
        }
        CP_COMMIT();
    };

    float acc[4][4][4];
#pragma unroll
    for (int i = 0; i < 4; i++)
#pragma unroll
        for (int j = 0; j < 4; j++)
#pragma unroll
            for (int q = 0; q < 4; q++) acc[i][j][q] = 0.f;

    load_chunk(0, 0);

    for (int c = 0; c < nchunk; c++) {
        const int buf = c & 1;
        if (c + 1 < nchunk) {
            load_chunk(c + 1, buf ^ 1);
            CP_WAIT(1);
        } else {
            CP_WAIT(0);
        }
        __syncthreads();

        const uint32_t sa = smem + buf * OSTAGE;
        const uint32_t sbb = sa + OA_ST;

#pragma unroll
        for (int ks = 0; ks < 4; ks++) {
            const int kk = ks * 16;
            uint32_t ah[4][4], bh[2][4];
            {
                int r = lane & 15, ck = lane >> 4;
#pragma unroll
                for (int mt = 0; mt < 4; mt++) {
                    uint32_t off = SWZ((uint32_t)((wm + mt * 16 + r) * 128 + (kk + ck * 8) * 2));
                    ldsm4(ah[mt], sa + off);
                }
            }
            {
                int grp = lane >> 3, ln = lane & 7;
#pragma unroll
                for (int np = 0; np < 2; np++) {
                    int n = wn + np * 16 + (grp >> 1) * 8 + ln;
                    int kc = kk + (grp & 1) * 8;
                    uint32_t off = SWZ((uint32_t)(n * 128 + kc * 2));
                    ldsm4(bh[np], sbb + off);
                }
            }
#pragma unroll
            for (int mt = 0; mt < 4; mt++)
#pragma unroll
                for (int nt = 0; nt < 4; nt++)
                    mma_f16(acc[mt][nt], ah[mt], &bh[nt >> 1][(nt & 1) * 2]);
        }
        __syncthreads();
    }

#pragma unroll
    for (int mt = 0; mt < 4; mt++) {
        int r0 = bm + wm + mt * 16 + (lane >> 2);
#pragma unroll
        for (int nt = 0; nt < 4; nt++) {
            int col = bn + wn + nt * 8 + (lane & 3) * 2;
            float* c0 = C + (size_t)r0 * DM + col;
            float* c1 = C + (size_t)(r0 + 8) * DM + col;
            c0[0] = acc[mt][nt][0]; c0[1] = acc[mt][nt][1];
            c1[0] = acc[mt][nt][2]; c1[1] = acc[mt][nt][3];
        }
    }
}

// ======================================================================
// qkv: rank contraction + rotary (fp32 trig) -> fp16 hi/lo q,k,v [b,h,t,d]
// ======================================================================
__global__ __launch_bounds__(128) void qkv_kernel()
{
    const int m = blockIdx.x;
    const int b = m >> 11;
    const int t = m & (TT - 1);
    const int d = threadIdx.x;

    __shared__ float aq  [RQ][16];
    __shared__ float bq  [RQ][128];
    __shared__ float akv [RKV][16];
    __shared__ float braw[RKV][128];
    __shared__ float brot[RKV][128];

    const float* abq = g_abq + (size_t)m * NQ;
    for (int idx = d; idx < NQ; idx += 128) {
        int r = idx / CH, c = idx - r * CH;
        float v = abq[idx];
        if (c < 16) aq[r][c] = v; else bq[r][c - 16] = v;
    }
    const float* abkv = g_abkv + (size_t)m * NKV;
    for (int idx = d; idx < NKV; idx += 128) {
        int r = idx / CH, c = idx - r * CH;
        float v = abkv[idx];
        if (c < 16) akv[r][c] = v; else braw[r][c - 16] = v;
    }
    __syncthreads();

    {
        int j = d & 63;
        float inv = powf(1e-4f, (float)j * (1.f / 64.f));
        float sv, cv;
        sincosf((float)t * inv, &sv, &cv);
#pragma unroll
        for (int r = 0; r < RKV; r++) {
            float x1 = braw[r][j], x2 = braw[r][j + 64];
            brot[r][d] = (d < 64) ? (x1 * cv + x2 * sv) : (-x1 * sv + x2 * cv);
        }
    }

    const size_t base = (((size_t)b * NH) * TT + t) * DH + d;
#pragma unroll
    for (int h = 0; h < NH; h++) {
        float qv = 0.f;
#pragma unroll
        for (int r = 0; r < RQ; r++) qv += aq[r][h] * bq[r][d];
        qv *= (1.f / 6.f);
        float kv = (akv[0][h] * brot[0][d] + akv[1][h] * brot[1][d]) * 0.5f;
        float vv = (akv[2][h] * brot[2][d] + akv[3][h] * brot[3][d]) * 0.5f;
        size_t o = base + (size_t)h * TT * DH;
        __half qhh = __float2half(qv);
        __half khh = __float2half(kv);
        __half vhh = __float2half(vv);
        g_qh[o] = qhh; g_ql[o] = __float2half(qv - __half2float(qhh));
        g_kh[o] = khh; g_kl[o] = __float2half(kv - __half2float(khh));
        g_vh[o] = vhh; g_vl[o] = __float2half(vv - __half2float(vhh));
    }
}

// ======================================================================
// flash attention, causal, mma.sync fp16 split (R13 winner).
// 128 threads (4 warps x 16 q-rows = 64-row Q tile), 32-row KV stages,
// 2-stage double buffer -> 97KB smem -> 2 CTAs/SM.
// Epilogue writes y as single fp16.
// ======================================================================
#define ATTN_SMEM (98304 + 1024)

__global__ __launch_bounds__(128) void attn_mma()
{
    extern __shared__ char smraw[];
    const uint32_t sb0 = smem_u32(smraw);
    const uint32_t sb = (sb0 + 1023) & ~1023u;

    const int tid = threadIdx.x, wid = tid >> 5, lane = tid & 31;
    const int qt = (int)gridDim.x - 1 - (int)blockIdx.x;   // heavy tiles first
    const int h = blockIdx.y, b = blockIdx.z;
    const size_t bh = ((size_t)b * NH + h) * TT;
    const int nkt = 2 * qt + 2;                            // 32-row kv tiles

    const uint32_t sQh = sb, sQl = sb + 16384;

    {
        const char* qh = (const char*)g_qh + (bh + (size_t)qt * 64) * 256;
        const char* ql = (const char*)g_ql + (bh + (size_t)qt * 64) * 256;
        for (int u = tid; u < 1024; u += 128) {
            int row = u >> 4, seg = u & 15;
            uint32_t off = ASW((uint32_t)(row * 256 + seg * 16));
            int go = row * 256 + seg * 16;
            CP_ASYNC(sQh + off, qh + go, 16);
            CP_ASYNC(sQl + off, ql + go, 16);
        }
    }
    auto load_kv = [&](int kt, int s) {
        uint32_t base = sb + 32768 + (uint32_t)s * 32768;
        const char* kh = (const char*)g_kh + (bh + (size_t)kt * 32) * 256;
        const char* kl = (const char*)g_kl + (bh + (size_t)kt * 32) * 256;
        const char* vh = (const char*)g_vh + (bh + (size_t)kt * 32) * 256;
        const char* vl = (const char*)g_vl + (bh + (size_t)kt * 32) * 256;
        for (int u = tid; u < 512; u += 128) {
            int row = u >> 4, seg = u & 15;
            uint32_t off = ASW((uint32_t)(row * 256 + seg * 16));
            int go = row * 256 + seg * 16;
            CP_ASYNC(base + off,         kh + go, 16);
            CP_ASYNC(base + 8192 + off,  kl + go, 16);
            CP_ASYNC(base + 16384 + off, vh + go, 16);
            CP_ASYNC(base + 24576 + off, vl + go, 16);
        }
        CP_COMMIT();
    };
    load_kv(0, 0);
    if (nkt > 1) load_kv(1, 1);

    float oacc[16][4];
#pragma unroll
    for (int dt = 0; dt < 16; dt++)
#pragma unroll
        for (int e = 0; e < 4; e++) oacc[dt][e] = 0.f;
    float rM0 = -1e30f, rM1 = -1e30f, rL0 = 0.f, rL1 = 0.f;

    const float scale = 0.08838834764831845f;
    const int r0g = qt * 64 + wid * 16 + (lane >> 2);

    for (int kt = 0; kt < nkt; kt++) {
        const int s = kt & 1;
        if (kt + 1 < nkt) { CP_WAIT(1); } else { CP_WAIT(0); }
        __syncthreads();
        const uint32_t base = sb + 32768 + (uint32_t)s * 32768;
        const uint32_t sKh = base, sKl = base + 8192;
        const uint32_t sVh = base + 16384, sVl = base + 24576;

        float sacc[4][4];
#pragma unroll
        for (int nt = 0; nt < 4; nt++)
#pragma unroll
            for (int e = 0; e < 4; e++) sacc[nt][e] = 0.f;

        // ---- S = Q K^T (64x32), 3 fp16 split passes, pass-major ----
#pragma unroll
        for (int ks = 0; ks < 8; ks++) {
            uint32_t ah[4], al[4];
            {
                int r = lane & 15, ck = lane >> 4;
                uint32_t off = ASW((uint32_t)((wid * 16 + r) * 256 + (ks * 16 + ck * 8) * 2));
                ldsm4(ah, sQh + off);
                ldsm4(al, sQl + off);
            }
            uint32_t bh4[2][4], bl4[2][4];
            {
                int grp = lane >> 3, ln = lane & 7;
#pragma unroll
                for (int ng = 0; ng < 2; ng++) {
                    int n = ng * 16 + (grp >> 1) * 8 + ln;
                    int kc = ks * 16 + (grp & 1) * 8;
                    uint32_t off = ASW((uint32_t)(n * 256 + kc * 2));
                    ldsm4(bh4[ng], sKh + off);
                    ldsm4(bl4[ng], sKl + off);
                }
            }
#pragma unroll
            for (int ng = 0; ng < 2; ng++) {
                mma_f16(sacc[ng * 2],     ah, bh4[ng]);
                mma_f16(sacc[ng * 2 + 1], ah, bh4[ng] + 2);
            }
#pragma unroll
            for (int ng = 0; ng < 2; ng++) {
                mma_f16(sacc[ng * 2],     ah, bl4[ng]);
                mma_f16(sacc[ng * 2 + 1], ah, bl4[ng] + 2);
            }
#pragma unroll
            for (int ng = 0; ng < 2; ng++) {
                mma_f16(sacc[ng * 2],     al, bh4[ng]);
                mma_f16(sacc[ng * 2 + 1], al, bh4[ng] + 2);
            }
        }

        const bool domask = (kt >= 2 * qt);
        float mx0 = -1e30f, mx1 = -1e30f;
#pragma unroll
        for (int nt = 0; nt < 4; nt++) {
            int c0 = kt * 32 + nt * 8 + (lane & 3) * 2;
#pragma unroll
            for (int e = 0; e < 4; e++) {
                float v = sacc[nt][e] * scale;
                if (domask) {
                    int cc = c0 + (e & 1);
                    int rr = r0g + ((e >> 1) << 3);
                    if (cc > rr) v = -1e30f;
                }
                sacc[nt][e] = v;
            }
            mx0 = fmaxf(mx0, fmaxf(sacc[nt][0], sacc[nt][1]));
            mx1 = fmaxf(mx1, fmaxf(sacc[nt][2], sacc[nt][3]));
        }
        mx0 = fmaxf(mx0, __shfl_xor_sync(0xffffffffu, mx0, 1));
        mx0 = fmaxf(mx0, __shfl_xor_sync(0xffffffffu, mx0, 2));
        mx1 = fmaxf(mx1, __shfl_xor_sync(0xffffffffu, mx1, 1));
        mx1 = fmaxf(mx1, __shfl_xor_sync(0xffffffffu, mx1, 2));

        float nM0 = fmaxf(rM0, mx0), nM1 = fmaxf(rM1, mx1);
        float cor0 = __expf(rM0 - nM0), cor1 = __expf(rM1 - nM1);
        rM0 = nM0; rM1 = nM1;

        float sum0 = 0.f, sum1 = 0.f;
        uint32_t pH01[4], pH23[4];
#pragma unroll
        for (int nt = 0; nt < 4; nt++) {
            float p0 = __expf(sacc[nt][0] - nM0);
            float p1 = __expf(sacc[nt][1] - nM0);
            float p2 = __expf(sacc[nt][2] - nM1);
            float p3 = __expf(sacc[nt][3] - nM1);
            sum0 += p0 + p1; sum1 += p2 + p3;
            pH01[nt] = pack_h2(__float2half(p0), __float2half(p1));
            pH23[nt] = pack_h2(__float2half(p2), __float2half(p3));
        }
        sum0 += __shfl_xor_sync(0xffffffffu, sum0, 1);
        sum0 += __shfl_xor_sync(0xffffffffu, sum0, 2);
        sum1 += __shfl_xor_sync(0xffffffffu, sum1, 1);
        sum1 += __shfl_xor_sync(0xffffffffu, sum1, 2);
        rL0 = rL0 * cor0 + sum0;
        rL1 = rL1 * cor1 + sum1;

#pragma unroll
        for (int dt = 0; dt < 16; dt++) {
            oacc[dt][0] *= cor0; oacc[dt][1] *= cor0;
            oacc[dt][2] *= cor1; oacc[dt][3] *= cor1;
        }

        // ---- O += P V: P single fp16 x (Vh, Vl) = 2 passes ----
#pragma unroll
        for (int k2 = 0; k2 < 2; k2++) {
            uint32_t aH[4] = {pH01[2 * k2], pH23[2 * k2], pH01[2 * k2 + 1], pH23[2 * k2 + 1]};
            int krow = k2 * 16 + ((lane >> 3) & 1) * 8 + (lane & 7);
#pragma unroll
            for (int dh2 = 0; dh2 < 2; dh2++) {
                uint32_t vh4[4][4], vl4[4][4];
#pragma unroll
                for (int dq = 0; dq < 4; dq++) {
                    int dcol = (dh2 * 4 + dq) * 16 + (lane >> 4) * 8;
                    uint32_t off = ASW((uint32_t)(krow * 256 + dcol * 2));
                    ldsm4t(vh4[dq], sVh + off);
                    ldsm4t(vl4[dq], sVl + off);
                }
#pragma unroll
                for (int dq = 0; dq < 4; dq++) {
                    int dg = dh2 * 4 + dq;
                    mma_f16(oacc[dg * 2],     aH, vh4[dq]);
                    mma_f16(oacc[dg * 2 + 1], aH, vh4[dq] + 2);
                }
#pragma unroll
                for (int dq = 0; dq < 4; dq++) {
                    int dg = dh2 * 4 + dq;
                    mma_f16(oacc[dg * 2],     aH, vl4[dq]);
                    mma_f16(oacc[dg * 2 + 1], aH, vl4[dq] + 2);
                }
            }
        }
        __syncthreads();
        if (kt + 2 < nkt) load_kv(kt + 2, s);
    }

    // ---- normalize + store single-fp16 y ----
    float il0 = 1.f / rL0, il1 = 1.f / rL1;
    size_t row0 = ((size_t)b * TT + r0g) * DM + h * DH;
    size_t row1 = row0 + (size_t)8 * DM;
#pragma unroll
    for (int dt = 0; dt < 16; dt++) {
        int c = dt * 8 + (lane & 3) * 2;
        *(uint32_t*)(g_y16 + row0 + c) = pack_h2(__float2half(oacc[dt][0] * il0),
                                                 __float2half(oacc[dt][1] * il0));
        *(uint32_t*)(g_y16 + row1 + c) = pack_h2(__float2half(oacc[dt][2] * il1),
                                                 __float2half(oacc[dt][3] * il1));
    }
}

// ======================================================================
extern "C" void kernel_launch(void* const* d_in, const int* in_sizes, int n_in,
                              void* d_out, int out_size)
{
    const float* x   = (const float*)d_in[0];
    const float* Wq  = (const float*)d_in[1];
    const float* Wkv = (const float*)d_in[2];
    const float* Wo  = (const float*)d_in[3];
    float* out = (float*)d_out;

    __nv_bfloat16 *xh, *xl, *wqh, *wql, *wkh, *wkl;
    __half *wo16, *y16;
    cudaGetSymbolAddress((void**)&xh,  g_xh);  cudaGetSymbolAddress((void**)&xl,  g_xl);
    cudaGetSymbolAddress((void**)&wqh, g_wqh); cudaGetSymbolAddress((void**)&wql, g_wql);
    cudaGetSymbolAddress((void**)&wkh, g_wkh); cudaGetSymbolAddress((void**)&wkl, g_wkl);
    cudaGetSymbolAddress((void**)&wo16, g_wo16);
    cudaGetSymbolAddress((void**)&y16,  g_y16);

    cudaFuncSetAttribute(gemm_qkv, cudaFuncAttributeMaxDynamicSharedMemorySize, GEMM_SMEM);
    cudaFuncSetAttribute(gemm_out, cudaFuncAttributeMaxDynamicSharedMemorySize, GEMM_OUT_SMEM);
    cudaFuncSetAttribute(attn_mma, cudaFuncAttributeMaxDynamicSharedMemorySize, ATTN_SMEM);

    // 0) conversions: x/Wq/Wkv -> bf16 hi/lo, Wo -> fp16 (one launch)
    {
        int n0 = BT * DM, n1 = NQ * DM, n2 = NKV * DM, n3 = DM * DM;
        conv_all<<<(n0 + n1 + n2 + n3 + 255) / 256, 256>>>(
            x, xh, xl, n0, Wq, wqh, wql, n1, Wkv, wkh, wkl, n2, Wo, wo16, n3);
    }
    // 1) fused ab_q / ab_kv projections (one launch, 736 CTAs, 2/SM)
    {
        dim3 g(QTILES + KVTILES, BT / GBM);
        gemm_qkv<<<g, 128, GEMM_SMEM>>>(xh, xl);
    }
    // 2) q,k,v (+rotary) -> fp16 hi/lo
    qkv_kernel<<<BT, 128>>>();
    // 3) causal attention (fp16 tensor cores, 2 CTAs/SM) -> y16
    {
        dim3 g(TT / 64, NH, NB);
        attn_mma<<<g, 128, ATTN_SMEM>>>();
    }
    // 4) out = y16 @ Wo16^T, single fp16 pass, 1024 CTAs
    {
        dim3 g(DM / GBN, BT / GBM);
        gemm_out<<<g, 128, GEMM_OUT_SMEM>>>(y16, wo16, out);
    }
}

// round 15
// speedup vs baseline: 1.6206x; 1.0667x over previous
#include <cuda_runtime.h>
#include <cuda_bf16.h>
#include <cuda_fp16.h>
#include <cstdint>
#include <math.h>

// ---------------- problem constants ----------------
#define NB     2
#define TT     2048
#define BT     4096      // NB*TT tokens
#define DM     2048
#define NH     16
#define DH     128
#define CH     144       // NH + DH
#define RQ     6
#define RKV    4
#define NQ     864       // RQ*CH
#define NKV    576       // RKV*CH

// ---------------- scratch (device globals; no allocs allowed) ----------------
__device__ float g_abq [BT * NQ];
__device__ float g_abkv[BT * NKV];

// bf16 hi/lo split scratch (projection GEMM path)
__device__ __nv_bfloat16 g_xh [BT * DM],  g_xl [BT * DM];
__device__ __nv_bfloat16 g_wqh[NQ * DM],  g_wql[NQ * DM];
__device__ __nv_bfloat16 g_wkh[NKV * DM], g_wkl[NKV * DM];

// fp16 single-precision path for output GEMM
__device__ __half g_wo16[DM * DM];
__device__ __half g_y16 [BT * DM];

// q/k fp16 hi/lo, v single fp16, layout [b,h,t,d]
#define QKV_ELEMS (NB * NH * TT * DH)
__device__ __half g_qh[QKV_ELEMS], g_ql[QKV_ELEMS];
__device__ __half g_kh[QKV_ELEMS], g_kl[QKV_ELEMS];
__device__ __half g_v16[QKV_ELEMS];

// ================= helpers =================
__device__ __forceinline__ uint32_t smem_u32(const void* p) {
    uint32_t a;
    asm("{ .reg .u64 t; cvta.to.shared.u64 t, %1; cvt.u32.u64 %0, t; }" : "=r"(a) : "l"(p));
    return a;
}
#define SWZ(o)  ((o) ^ (((o) >> 3) & 0x70))   // 128B-row swizzle (GEMM tiles)
#define ASW(o)  ((o) ^ (((o) >> 4) & 0x70))   // 256B-row swizzle (attn tiles)

__device__ __forceinline__ void ldsm4(uint32_t* r, uint32_t addr) {
    asm volatile("ldmatrix.sync.aligned.m8n8.x4.shared.b16 {%0,%1,%2,%3}, [%4];"
        : "=r"(r[0]), "=r"(r[1]), "=r"(r[2]), "=r"(r[3]) : "r"(addr));
}
__device__ __forceinline__ void ldsm4t(uint32_t* r, uint32_t addr) {
    asm volatile("ldmatrix.sync.aligned.m8n8.x4.trans.shared.b16 {%0,%1,%2,%3}, [%4];"
        : "=r"(r[0]), "=r"(r[1]), "=r"(r[2]), "=r"(r[3]) : "r"(addr));
}
__device__ __forceinline__ void mma_bf16(float* c, const uint32_t* a, const uint32_t* b) {
    asm volatile("mma.sync.aligned.m16n8k16.row.col.f32.bf16.bf16.f32 "
        "{%0,%1,%2,%3}, {%4,%5,%6,%7}, {%8,%9}, {%0,%1,%2,%3};"
        : "+f"(c[0]), "+f"(c[1]), "+f"(c[2]), "+f"(c[3])
        : "r"(a[0]), "r"(a[1]), "r"(a[2]), "r"(a[3]), "r"(b[0]), "r"(b[1]));
}
__device__ __forceinline__ void mma_f16(float* c, const uint32_t* a, const uint32_t* b) {
    asm volatile("mma.sync.aligned.m16n8k16.row.col.f32.f16.f16.f32 "
        "{%0,%1,%2,%3}, {%4,%5,%6,%7}, {%8,%9}, {%0,%1,%2,%3};"
        : "+f"(c[0]), "+f"(c[1]), "+f"(c[2]), "+f"(c[3])
        : "r"(a[0]), "r"(a[1]), "r"(a[2]), "r"(a[3]), "r"(b[0]), "r"(b[1]));
}
#define CP_ASYNC(dst, src, sz) \
    asm volatile("cp.async.cg.shared.global [%0], [%1], 16, %2;" \
        :: "r"(dst), "l"(src), "r"(sz) : "memory")
#define CP_COMMIT() asm volatile("cp.async.commit_group;" ::: "memory")
#define CP_WAIT(n)  asm volatile("cp.async.wait_group %0;" :: "n"(n) : "memory")

__device__ __forceinline__ uint32_t pack_h2(__half lo, __half hi) {
    __half2 t; t.x = lo; t.y = hi;
    return *reinterpret_cast<uint32_t*>(&t);
}

// ======================================================================
// fused fp32 -> split conversions:
//   x, Wq, Wkv -> bf16 hi/lo;  Wo -> single fp16
// ======================================================================
__global__ __launch_bounds__(256) void conv_all(
    const float* __restrict__ s0, __nv_bfloat16* __restrict__ h0, __nv_bfloat16* __restrict__ l0, int n0,
    const float* __restrict__ s1, __nv_bfloat16* __restrict__ h1, __nv_bfloat16* __restrict__ l1, int n1,
    const float* __restrict__ s2, __nv_bfloat16* __restrict__ h2, __nv_bfloat16* __restrict__ l2, int n2,
    const float* __restrict__ s3, __half* __restrict__ h3, int n3)
{
    int i = blockIdx.x * 256 + threadIdx.x;
    if (i < n0) {
        float v = s0[i];
        __nv_bfloat16 hi = __float2bfloat16(v);
        h0[i] = hi; l0[i] = __float2bfloat16(v - __bfloat162float(hi));
    } else if (i < n0 + n1) {
        int j = i - n0;
        float v = s1[j];
        __nv_bfloat16 hi = __float2bfloat16(v);
        h1[j] = hi; l1[j] = __float2bfloat16(v - __bfloat162float(hi));
    } else if (i < n0 + n1 + n2) {
        int j = i - n0 - n1;
        float v = s2[j];
        __nv_bfloat16 hi = __float2bfloat16(v);
        h2[j] = hi; l2[j] = __float2bfloat16(v - __bfloat162float(hi));
    } else if (i < n0 + n1 + n2 + n3) {
        int j = i - n0 - n1 - n2;
        h3[j] = __float2half(s3[j]);
    }
}

// ======================================================================
// bf16-split projection GEMM: 128x64 tile, 128 threads, 2-stage,
// 48KB/stage -> 2 CTAs/SM.  (R11/R12 winner, unchanged)
// ======================================================================
#define GBM      128
#define GBN      64
#define A_ST     16384
#define B_ST     8192
#define STAGE_B  (2 * A_ST + 2 * B_ST)
#define GEMM_SMEM (2 * STAGE_B + 1024)

__device__ __forceinline__ void gemm_body(
    const __nv_bfloat16* __restrict__ Ah, const __nv_bfloat16* __restrict__ Al,
    const __nv_bfloat16* __restrict__ Bh, const __nv_bfloat16* __restrict__ Bl,
    float* __restrict__ C, int N, int K, int bm, int bn, uint32_t smem)
{
    const int tid  = threadIdx.x;
    const int wid  = tid >> 5, lane = tid & 31;
    const int wm   = (wid >> 1) * 64;
    const int wn   = (wid & 1) * 32;
    const int nchunk = K >> 6;

    auto load_chunk = [&](int c, int buf) {
        const uint32_t base = smem + buf * STAGE_B;
        const int k0 = c * 64;
#pragma unroll
        for (int u = tid; u < 1024; u += 128) {
            int row = u >> 3, seg = u & 7;
            uint32_t so = SWZ((uint32_t)(row * 128 + seg * 16));
            size_t ga = (size_t)(bm + row) * K + k0 + seg * 8;
            CP_ASYNC(base + so,        Ah + ga, 16);
            CP_ASYNC(base + A_ST + so, Al + ga, 16);
        }
#pragma unroll
        for (int u = tid; u < 512; u += 128) {
            int row = u >> 3, seg = u & 7;
            uint32_t so = SWZ((uint32_t)(row * 128 + seg * 16));
            int n = bn + row;
            int sz = (n < N) ? 16 : 0;
            size_t gb = (size_t)(n < N ? n : 0) * K + k0 + seg * 8;
            CP_ASYNC(base + 2 * A_ST + so,        Bh + gb, sz);
            CP_ASYNC(base + 2 * A_ST + B_ST + so, Bl + gb, sz);
        }
        CP_COMMIT();
    };

    float acc[4][4][4];
#pragma unroll
    for (int i = 0; i < 4; i++)
#pragma unroll
        for (int j = 0; j < 4; j++)
#pragma unroll
            for (int q = 0; q < 4; q++) acc[i][j][q] = 0.f;

    load_chunk(0, 0);

    for (int c = 0; c < nchunk; c++) {
        const int buf = c & 1;
        if (c + 1 < nchunk) {
            load_chunk(c + 1, buf ^ 1);
            CP_WAIT(1);
        } else {
            CP_WAIT(0);
        }
        __syncthreads();

        const uint32_t sa_h = smem + buf * STAGE_B;
        const uint32_t sa_l = sa_h + A_ST;
        const uint32_t sb_h = sa_h + 2 * A_ST;
        const uint32_t sb_l = sb_h + B_ST;

#pragma unroll
        for (int ks = 0; ks < 4; ks++) {
            const int kk = ks * 16;
            uint32_t ah[4][4], al[4][4], bh[2][4], bl[2][4];
            {
                int r = lane & 15, ck = lane >> 4;
#pragma unroll
                for (int mt = 0; mt < 4; mt++) {
                    uint32_t off = SWZ((uint32_t)((wm + mt * 16 + r) * 128 + (kk + ck * 8) * 2));
                    ldsm4(ah[mt], sa_h + off);
                    ldsm4(al[mt], sa_l + off);
                }
            }
            {
                int grp = lane >> 3, ln = lane & 7;
#pragma unroll
                for (int np = 0; np < 2; np++) {
                    int n = wn + np * 16 + (grp >> 1) * 8 + ln;
                    int kc = kk + (grp & 1) * 8;
                    uint32_t off = SWZ((uint32_t)(n * 128 + kc * 2));
                    ldsm4(bh[np], sb_h + off);
                    ldsm4(bl[np], sb_l + off);
                }
            }
#pragma unroll
            for (int mt = 0; mt < 4; mt++)
#pragma unroll
                for (int nt = 0; nt < 4; nt++)
                    mma_bf16(acc[mt][nt], ah[mt], &bh[nt >> 1][(nt & 1) * 2]);
#pragma unroll
            for (int mt = 0; mt < 4; mt++)
#pragma unroll
                for (int nt = 0; nt < 4; nt++)
                    mma_bf16(acc[mt][nt], ah[mt], &bl[nt >> 1][(nt & 1) * 2]);
#pragma unroll
            for (int mt = 0; mt < 4; mt++)
#pragma unroll
                for (int nt = 0; nt < 4; nt++)
                    mma_bf16(acc[mt][nt], al[mt], &bh[nt >> 1][(nt & 1) * 2]);
        }
        __syncthreads();
    }

#pragma unroll
    for (int mt = 0; mt < 4; mt++) {
        int r0 = bm + wm + mt * 16 + (lane >> 2);
#pragma unroll
        for (int nt = 0; nt < 4; nt++) {
            int col = bn + wn + nt * 8 + (lane & 3) * 2;
            if (col < N) {
                float* c0 = C + (size_t)r0 * N + col;
                float* c1 = C + (size_t)(r0 + 8) * N + col;
                c0[0] = acc[mt][nt][0]; c0[1] = acc[mt][nt][1];
                c1[0] = acc[mt][nt][2]; c1[1] = acc[mt][nt][3];
            }
        }
    }
}

#define QTILES  14
#define KVTILES 9
__global__ __launch_bounds__(128) void gemm_qkv(
    const __nv_bfloat16* __restrict__ Ah, const __nv_bfloat16* __restrict__ Al)
{
    extern __shared__ char smraw[];
    const uint32_t smem0 = smem_u32(smraw);
    const uint32_t smem  = (smem0 + 1023) & ~1023u;
    const int bx = blockIdx.x;
    if (bx < QTILES)
        gemm_body(Ah, Al, g_wqh, g_wql, g_abq, NQ, DM,
                  blockIdx.y * GBM, bx * GBN, smem);
    else
        gemm_body(Ah, Al, g_wkh, g_wkl, g_abkv, NKV, DM,
                  blockIdx.y * GBM, (bx - QTILES) * GBN, smem);
}

// ======================================================================
// single-pass fp16 output GEMM: out = y16 @ Wo16^T (R14 winner, unchanged)
// ======================================================================
#define OA_ST   16384
#define OB_ST   8192
#define OSTAGE  (OA_ST + OB_ST)
#define GEMM_OUT_SMEM (2 * OSTAGE + 1024)

__global__ __launch_bounds__(128) void gemm_out(
    const __half* __restrict__ A, const __half* __restrict__ B,
    float* __restrict__ C)
{
    extern __shared__ char smraw[];
    const uint32_t smem0 = smem_u32(smraw);
    const uint32_t smem  = (smem0 + 1023) & ~1023u;

    const int tid  = threadIdx.x;
    const int wid  = tid >> 5, lane = tid & 31;
    const int wm   = (wid >> 1) * 64;
    const int wn   = (wid & 1) * 32;
    const int bm   = blockIdx.y * 128;
    const int bn   = blockIdx.x * 64;
    const int nchunk = DM >> 6;

    auto load_chunk = [&](int c, int buf) {
        const uint32_t base = smem + buf * OSTAGE;
        const int k0 = c * 64;
#pragma unroll
        for (int u = tid; u < 1024; u += 128) {
            int row = u >> 3, seg = u & 7;
            uint32_t so = SWZ((uint32_t)(row * 128 + seg * 16));
            CP_ASYNC(base + so, A + (size_t)(bm + row) * DM + k0 + seg * 8, 16);
        }
#pragma unroll
        for (int u = tid; u < 512; u += 128) {
            int row = u >> 3, seg = u & 7;
            uint32_t so = SWZ((uint32_t)(row * 128 + seg * 16));
            CP_ASYNC(base + OA_ST + so, B + (size_t)(bn + row) * DM + k0 + seg * 8, 16);
        }
        CP_COMMIT();
    };

    float acc[4][4][4];
#pragma unroll
    for (int i = 0; i < 4; i++)
#pragma unroll
        for (int j = 0; j < 4; j++)
#pragma unroll
            for (int q = 0; q < 4; q++) acc[i][j][q] = 0.f;

    load_chunk(0, 0);

    for (int c = 0; c < nchunk; c++) {
        const int buf = c & 1;
        if (c + 1 < nchunk) {
            load_chunk(c + 1, buf ^ 1);
            CP_WAIT(1);
        } else {
            CP_WAIT(0);
        }
        __syncthreads();

        const uint32_t sa = smem + buf * OSTAGE;
        const uint32_t sbb = sa + OA_ST;

#pragma unroll
        for (int ks = 0; ks < 4; ks++) {
            const int kk = ks * 16;
            uint32_t ah[4][4], bh[2][4];
            {
                int r = lane & 15, ck = lane >> 4;
#pragma unroll
                for (int mt = 0; mt < 4; mt++) {
                    uint32_t off = SWZ((uint32_t)((wm + mt * 16 + r) * 128 + (kk + ck * 8) * 2));
                    ldsm4(ah[mt], sa + off);
                }
            }
            {
                int grp = lane >> 3, ln = lane & 7;
#pragma unroll
                for (int np = 0; np < 2; np++) {
                    int n = wn + np * 16 + (grp >> 1) * 8 + ln;
                    int kc = kk + (grp & 1) * 8;
                    uint32_t off = SWZ((uint32_t)(n * 128 + kc * 2));
                    ldsm4(bh[np], sbb + off);
                }
            }
#pragma unroll
            for (int mt = 0; mt < 4; mt++)
#pragma unroll
                for (int nt = 0; nt < 4; nt++)
                    mma_f16(acc[mt][nt], ah[mt], &bh[nt >> 1][(nt & 1) * 2]);
        }
        __syncthreads();
    }

#pragma unroll
    for (int mt = 0; mt < 4; mt++) {
        int r0 = bm + wm + mt * 16 + (lane >> 2);
#pragma unroll
        for (int nt = 0; nt < 4; nt++) {
            int col = bn + wn + nt * 8 + (lane & 3) * 2;
            float* c0 = C + (size_t)r0 * DM + col;
            float* c1 = C + (size_t)(r0 + 8) * DM + col;
            c0[0] = acc[mt][nt][0]; c0[1] = acc[mt][nt][1];
            c1[0] = acc[mt][nt][2]; c1[1] = acc[mt][nt][3];
        }
    }
}

// ======================================================================
// qkv: rank contraction + rotary -> fp16 hi/lo q,k; single fp16 v
// ======================================================================
__global__ __launch_bounds__(128) void qkv_kernel()
{
    const int m = blockIdx.x;
    const int b = m >> 11;
    const int t = m & (TT - 1);
    const int d = threadIdx.x;

    __shared__ float aq  [RQ][16];
    __shared__ float bq  [RQ][128];
    __shared__ float akv [RKV][16];
    __shared__ float braw[RKV][128];
    __shared__ float brot[RKV][128];

    const float* abq = g_abq + (size_t)m * NQ;
    for (int idx = d; idx < NQ; idx += 128) {
        int r = idx / CH, c = idx - r * CH;
        float v = abq[idx];
        if (c < 16) aq[r][c] = v; else bq[r][c - 16] = v;
    }
    const float* abkv = g_abkv + (size_t)m * NKV;
    for (int idx = d; idx < NKV; idx += 128) {
        int r = idx / CH, c = idx - r * CH;
        float v = abkv[idx];
        if (c < 16) akv[r][c] = v; else braw[r][c - 16] = v;
    }
    __syncthreads();

    {
        int j = d & 63;
        float inv = powf(1e-4f, (float)j * (1.f / 64.f));
        float sv, cv;
        sincosf((float)t * inv, &sv, &cv);
#pragma unroll
        for (int r = 0; r < RKV; r++) {
            float x1 = braw[r][j], x2 = braw[r][j + 64];
            brot[r][d] = (d < 64) ? (x1 * cv + x2 * sv) : (-x1 * sv + x2 * cv);
        }
    }

    const size_t base = (((size_t)b * NH) * TT + t) * DH + d;
#pragma unroll
    for (int h = 0; h < NH; h++) {
        float qv = 0.f;
#pragma unroll
        for (int r = 0; r < RQ; r++) qv += aq[r][h] * bq[r][d];
        qv *= (1.f / 6.f);
        float kv = (akv[0][h] * brot[0][d] + akv[1][h] * brot[1][d]) * 0.5f;
        float vv = (akv[2][h] * brot[2][d] + akv[3][h] * brot[3][d]) * 0.5f;
        size_t o = base + (size_t)h * TT * DH;
        __half qhh = __float2half(qv);
        __half khh = __float2half(kv);
        g_qh[o] = qhh; g_ql[o] = __float2half(qv - __half2float(qhh));
        g_kh[o] = khh; g_kl[o] = __float2half(kv - __half2float(khh));
        g_v16[o] = __float2half(vv);
    }
}

// ======================================================================
// flash attention, causal, mma.sync fp16 split.
// 128 threads (4 warps x 16 q-rows = 64-row Q tile), 32-row KV stages,
// 2-stage double buffer. KV stage = Kh 8K + Kl 8K + Vh 8K = 24KB.
// QK: 3 passes. PV: P fp16 x V fp16 single pass. smem = 32 + 48 = 81KB.
// ======================================================================
#define ATTN_SMEM (81920 + 1024)

__global__ __launch_bounds__(128) void attn_mma()
{
    extern __shared__ char smraw[];
    const uint32_t sb0 = smem_u32(smraw);
    const uint32_t sb = (sb0 + 1023) & ~1023u;

    const int tid = threadIdx.x, wid = tid >> 5, lane = tid & 31;
    const int qt = (int)gridDim.x - 1 - (int)blockIdx.x;   // heavy tiles first
    const int h = blockIdx.y, b = blockIdx.z;
    const size_t bh = ((size_t)b * NH + h) * TT;
    const int nkt = 2 * qt + 2;                            // 32-row kv tiles

    const uint32_t sQh = sb, sQl = sb + 16384;

    {
        const char* qh = (const char*)g_qh + (bh + (size_t)qt * 64) * 256;
        const char* ql = (const char*)g_ql + (bh + (size_t)qt * 64) * 256;
        for (int u = tid; u < 1024; u += 128) {
            int row = u >> 4, seg = u & 15;
            uint32_t off = ASW((uint32_t)(row * 256 + seg * 16));
            int go = row * 256 + seg * 16;
            CP_ASYNC(sQh + off, qh + go, 16);
            CP_ASYNC(sQl + off, ql + go, 16);
        }
    }
    auto load_kv = [&](int kt, int s) {
        uint32_t base = sb + 32768 + (uint32_t)s * 24576;
        const char* kh = (const char*)g_kh + (bh + (size_t)kt * 32) * 256;
        const char* kl = (const char*)g_kl + (bh + (size_t)kt * 32) * 256;
        const char* vh = (const char*)g_v16 + (bh + (size_t)kt * 32) * 256;
        for (int u = tid; u < 512; u += 128) {
            int row = u >> 4, seg = u & 15;
            uint32_t off = ASW((uint32_t)(row * 256 + seg * 16));
            int go = row * 256 + seg * 16;
            CP_ASYNC(base + off,         kh + go, 16);
            CP_ASYNC(base + 8192 + off,  kl + go, 16);
            CP_ASYNC(base + 16384 + off, vh + go, 16);
        }
        CP_COMMIT();
    };
    load_kv(0, 0);
    if (nkt > 1) load_kv(1, 1);

    float oacc[16][4];
#pragma unroll
    for (int dt = 0; dt < 16; dt++)
#pragma unroll
        for (int e = 0; e < 4; e++) oacc[dt][e] = 0.f;
    float rM0 = -1e30f, rM1 = -1e30f, rL0 = 0.f, rL1 = 0.f;

    const float scale = 0.08838834764831845f;
    const int r0g = qt * 64 + wid * 16 + (lane >> 2);

    for (int kt = 0; kt < nkt; kt++) {
        const int s = kt & 1;
        if (kt + 1 < nkt) { CP_WAIT(1); } else { CP_WAIT(0); }
        __syncthreads();
        const uint32_t base = sb + 32768 + (uint32_t)s * 24576;
        const uint32_t sKh = base, sKl = base + 8192;
        const uint32_t sVh = base + 16384;

        float sacc[4][4];
#pragma unroll
        for (int nt = 0; nt < 4; nt++)
#pragma unroll
            for (int e = 0; e < 4; e++) sacc[nt][e] = 0.f;

        // ---- S = Q K^T (64x32), 3 fp16 split passes, pass-major ----
#pragma unroll
        for (int ks = 0; ks < 8; ks++) {
            uint32_t ah[4], al[4];
            {
                int r = lane & 15, ck = lane >> 4;
                uint32_t off = ASW((uint32_t)((wid * 16 + r) * 256 + (ks * 16 + ck * 8) * 2));
                ldsm4(ah, sQh + off);
                ldsm4(al, sQl + off);
            }
            uint32_t bh4[2][4], bl4[2][4];
            {
                int grp = lane >> 3, ln = lane & 7;
#pragma unroll
                for (int ng = 0; ng < 2; ng++) {
                    int n = ng * 16 + (grp >> 1) * 8 + ln;
                    int kc = ks * 16 + (grp & 1) * 8;
                    uint32_t off = ASW((uint32_t)(n * 256 + kc * 2));
                    ldsm4(bh4[ng], sKh + off);
                    ldsm4(bl4[ng], sKl + off);
                }
            }
#pragma unroll
            for (int ng = 0; ng < 2; ng++) {
                mma_f16(sacc[ng * 2],     ah, bh4[ng]);
                mma_f16(sacc[ng * 2 + 1], ah, bh4[ng] + 2);
            }
#pragma unroll
            for (int ng = 0; ng < 2; ng++) {
                mma_f16(sacc[ng * 2],     ah, bl4[ng]);
                mma_f16(sacc[ng * 2 + 1], ah, bl4[ng] + 2);
            }
#pragma unroll
            for (int ng = 0; ng < 2; ng++) {
                mma_f16(sacc[ng * 2],     al, bh4[ng]);
                mma_f16(sacc[ng * 2 + 1], al, bh4[ng] + 2);
            }
        }

        const bool domask = (kt >= 2 * qt);
        float mx0 = -1e30f, mx1 = -1e30f;
#pragma unroll
        for (int nt = 0; nt < 4; nt++) {
            int c0 = kt * 32 + nt * 8 + (lane & 3) * 2;
#pragma unroll
            for (int e = 0; e < 4; e++) {
                float v = sacc[nt][e] * scale;
                if (domask) {
                    int cc = c0 + (e & 1);
                    int rr = r0g + ((e >> 1) << 3);
                    if (cc > rr) v = -1e30f;
                }
                sacc[nt][e] = v;
            }
            mx0 = fmaxf(mx0, fmaxf(sacc[nt][0], sacc[nt][1]));
            mx1 = fmaxf(mx1, fmaxf(sacc[nt][2], sacc[nt][3]));
        }
        mx0 = fmaxf(mx0, __shfl_xor_sync(0xffffffffu, mx0, 1));
        mx0 = fmaxf(mx0, __shfl_xor_sync(0xffffffffu, mx0, 2));
        mx1 = fmaxf(mx1, __shfl_xor_sync(0xffffffffu, mx1, 1));
        mx1 = fmaxf(mx1, __shfl_xor_sync(0xffffffffu, mx1, 2));

        float nM0 = fmaxf(rM0, mx0), nM1 = fmaxf(rM1, mx1);
        float cor0 = __expf(rM0 - nM0), cor1 = __expf(rM1 - nM1);
        rM0 = nM0; rM1 = nM1;

        float sum0 = 0.f, sum1 = 0.f;
        uint32_t pH01[4], pH23[4];
#pragma unroll
        for (int nt = 0; nt < 4; nt++) {
            float p0 = __expf(sacc[nt][0] - nM0);
            float p1 = __expf(sacc[nt][1] - nM0);
            float p2 = __expf(sacc[nt][2] - nM1);
            float p3 = __expf(sacc[nt][3] - nM1);
            sum0 += p0 + p1; sum1 += p2 + p3;
            pH01[nt] = pack_h2(__float2half(p0), __float2half(p1));
            pH23[nt] = pack_h2(__float2half(p2), __float2half(p3));
        }
        sum0 += __shfl_xor_sync(0xffffffffu, sum0, 1);
        sum0 += __shfl_xor_sync(0xffffffffu, sum0, 2);
        sum1 += __shfl_xor_sync(0xffffffffu, sum1, 1);
        sum1 += __shfl_xor_sync(0xffffffffu, sum1, 2);
        rL0 = rL0 * cor0 + sum0;
        rL1 = rL1 * cor1 + sum1;

#pragma unroll
        for (int dt = 0; dt < 16; dt++) {
            oacc[dt][0] *= cor0; oacc[dt][1] *= cor0;
            oacc[dt][2] *= cor1; oacc[dt][3] *= cor1;
        }

        // ---- O += P V: single fp16 pass ----
#pragma unroll
        for (int k2 = 0; k2 < 2; k2++) {
            uint32_t aH[4] = {pH01[2 * k2], pH23[2 * k2], pH01[2 * k2 + 1], pH23[2 * k2 + 1]};
            int krow = k2 * 16 + ((lane >> 3) & 1) * 8 + (lane & 7);
#pragma unroll
            for (int dh2 = 0; dh2 < 2; dh2++) {
                uint32_t vh4[4][4];
#pragma unroll
                for (int dq = 0; dq < 4; dq++) {
                    int dcol = (dh2 * 4 + dq) * 16 + (lane >> 4) * 8;
                    uint32_t off = ASW((uint32_t)(krow * 256 + dcol * 2));
                    ldsm4t(vh4[dq], sVh + off);
                }
#pragma unroll
                for (int dq = 0; dq < 4; dq++) {
                    int dg = dh2 * 4 + dq;
                    mma_f16(oacc[dg * 2],     aH, vh4[dq]);
                    mma_f16(oacc[dg * 2 + 1], aH, vh4[dq] + 2);
                }
            }
        }
        __syncthreads();
        if (kt + 2 < nkt) load_kv(kt + 2, s);
    }

    // ---- normalize + store single-fp16 y ----
    float il0 = 1.f / rL0, il1 = 1.f / rL1;
    size_t row0 = ((size_t)b * TT + r0g) * DM + h * DH;
    size_t row1 = row0 + (size_t)8 * DM;
#pragma unroll
    for (int dt = 0; dt < 16; dt++) {
        int c = dt * 8 + (lane & 3) * 2;
        *(uint32_t*)(g_y16 + row0 + c) = pack_h2(__float2half(oacc[dt][0] * il0),
                                                 __float2half(oacc[dt][1] * il0));
        *(uint32_t*)(g_y16 + row1 + c) = pack_h2(__float2half(oacc[dt][2] * il1),
                                                 __float2half(oacc[dt][3] * il1));
    }
}

// ======================================================================
extern "C" void kernel_launch(void* const* d_in, const int* in_sizes, int n_in,
                              void* d_out, int out_size)
{
    const float* x   = (const float*)d_in[0];
    const float* Wq  = (const float*)d_in[1];
    const float* Wkv = (const float*)d_in[2];
    const float* Wo  = (const float*)d_in[3];
    float* out = (float*)d_out;

    __nv_bfloat16 *xh, *xl, *wqh, *wql, *wkh, *wkl;
    __half *wo16, *y16;
    cudaGetSymbolAddress((void**)&xh,  g_xh);  cudaGetSymbolAddress((void**)&xl,  g_xl);
    cudaGetSymbolAddress((void**)&wqh, g_wqh); cudaGetSymbolAddress((void**)&wql, g_wql);
    cudaGetSymbolAddress((void**)&wkh, g_wkh); cudaGetSymbolAddress((void**)&wkl, g_wkl);
    cudaGetSymbolAddress((void**)&wo16, g_wo16);
    cudaGetSymbolAddress((void**)&y16,  g_y16);

    cudaFuncSetAttribute(gemm_qkv, cudaFuncAttributeMaxDynamicSharedMemorySize, GEMM_SMEM);
    cudaFuncSetAttribute(gemm_out, cudaFuncAttributeMaxDynamicSharedMemorySize, GEMM_OUT_SMEM);
    cudaFuncSetAttribute(attn_mma, cudaFuncAttributeMaxDynamicSharedMemorySize, ATTN_SMEM);

    // 0) conversions: x/Wq/Wkv -> bf16 hi/lo, Wo -> fp16 (one launch)
    {
        int n0 = BT * DM, n1 = NQ * DM, n2 = NKV * DM, n3 = DM * DM;
        conv_all<<<(n0 + n1 + n2 + n3 + 255) / 256, 256>>>(
            x, xh, xl, n0, Wq, wqh, wql, n1, Wkv, wkh, wkl, n2, Wo, wo16, n3);
    }
    // 1) fused ab_q / ab_kv projections (one launch, 736 CTAs, 2/SM)
    {
        dim3 g(QTILES + KVTILES, BT / GBM);
        gemm_qkv<<<g, 128, GEMM_SMEM>>>(xh, xl);
    }
    // 2) q,k,v (+rotary) -> fp16 (q,k hi/lo; v single)
    qkv_kernel<<<BT, 128>>>();
    // 3) causal attention (fp16 tensor cores, 2 CTAs/SM) -> y16
    {
        dim3 g(TT / 64, NH, NB);
        attn_mma<<<g, 128, ATTN_SMEM>>>();
    }
    // 4) out = y16 @ Wo16^T, single fp16 pass, 1024 CTAs
    {
        dim3 g(DM / GBN, BT / GBM);
        gemm_out<<<g, 128, GEMM_OUT_SMEM>>>(y16, wo16, out);
    }
}

// round 16
// speedup vs baseline: 2.2761x; 1.4045x over previous
#include <cuda_runtime.h>
#include <cuda_fp16.h>
#include <cstdint>
#include <math.h>

// ---------------- problem constants ----------------
#define NB     2
#define TT     2048
#define BT     4096      // NB*TT tokens
#define DM     2048
#define NH     16
#define DH     128
#define CH     144       // NH + DH
#define RQ     6
#define RKV    4
#define NQ     864       // RQ*CH
#define NKV    576       // RKV*CH

// ---------------- scratch (device globals; no allocs allowed) ----------------
__device__ float g_abq [BT * NQ];
__device__ float g_abkv[BT * NKV];

// single fp16 everything
__device__ __half g_x16 [BT * DM];
__device__ __half g_wq16[NQ * DM];
__device__ __half g_wkv16[NKV * DM];
__device__ __half g_wo16[DM * DM];
__device__ __half g_y16 [BT * DM];

#define QKV_ELEMS (NB * NH * TT * DH)
__device__ __half g_q16[QKV_ELEMS];
__device__ __half g_k16[QKV_ELEMS];
__device__ __half g_v16[QKV_ELEMS];

// ================= helpers =================
__device__ __forceinline__ uint32_t smem_u32(const void* p) {
    uint32_t a;
    asm("{ .reg .u64 t; cvta.to.shared.u64 t, %1; cvt.u32.u64 %0, t; }" : "=r"(a) : "l"(p));
    return a;
}
#define SWZ(o)  ((o) ^ (((o) >> 3) & 0x70))   // 128B-row swizzle (GEMM tiles)
#define ASW(o)  ((o) ^ (((o) >> 4) & 0x70))   // 256B-row swizzle (attn tiles)

__device__ __forceinline__ void ldsm4(uint32_t* r, uint32_t addr) {
    asm volatile("ldmatrix.sync.aligned.m8n8.x4.shared.b16 {%0,%1,%2,%3}, [%4];"
        : "=r"(r[0]), "=r"(r[1]), "=r"(r[2]), "=r"(r[3]) : "r"(addr));
}
__device__ __forceinline__ void ldsm4t(uint32_t* r, uint32_t addr) {
    asm volatile("ldmatrix.sync.aligned.m8n8.x4.trans.shared.b16 {%0,%1,%2,%3}, [%4];"
        : "=r"(r[0]), "=r"(r[1]), "=r"(r[2]), "=r"(r[3]) : "r"(addr));
}
__device__ __forceinline__ void mma_f16(float* c, const uint32_t* a, const uint32_t* b) {
    asm volatile("mma.sync.aligned.m16n8k16.row.col.f32.f16.f16.f32 "
        "{%0,%1,%2,%3}, {%4,%5,%6,%7}, {%8,%9}, {%0,%1,%2,%3};"
        : "+f"(c[0]), "+f"(c[1]), "+f"(c[2]), "+f"(c[3])
        : "r"(a[0]), "r"(a[1]), "r"(a[2]), "r"(a[3]), "r"(b[0]), "r"(b[1]));
}
#define CP_ASYNC(dst, src, sz) \
    asm volatile("cp.async.cg.shared.global [%0], [%1], 16, %2;" \
        :: "r"(dst), "l"(src), "r"(sz) : "memory")
#define CP_COMMIT() asm volatile("cp.async.commit_group;" ::: "memory")
#define CP_WAIT(n)  asm volatile("cp.async.wait_group %0;" :: "n"(n) : "memory")

__device__ __forceinline__ uint32_t pack_h2(__half lo, __half hi) {
    __half2 t; t.x = lo; t.y = hi;
    return *reinterpret_cast<uint32_t*>(&t);
}

// ======================================================================
// fused fp32 -> fp16 conversion of all four tensors (one launch)
// ======================================================================
__global__ __launch_bounds__(256) void conv_all(
    const float* __restrict__ s0, __half* __restrict__ h0, int n0,
    const float* __restrict__ s1, __half* __restrict__ h1, int n1,
    const float* __restrict__ s2, __half* __restrict__ h2, int n2,
    const float* __restrict__ s3, __half* __restrict__ h3, int n3)
{
    int i = blockIdx.x * 256 + threadIdx.x;
    if (i < n0)                     { h0[i] = __float2half(s0[i]); }
    else if (i < n0 + n1)           { int j = i - n0;           h1[j] = __float2half(s1[j]); }
    else if (i < n0 + n1 + n2)      { int j = i - n0 - n1;      h2[j] = __float2half(s2[j]); }
    else if (i < n0 + n1 + n2 + n3) { int j = i - n0 - n1 - n2; h3[j] = __float2half(s3[j]); }
}

// ======================================================================
// single-pass fp16 NT GEMM: C[M,N] = A[M,K] * B[N,K]^T
// 128x64 tile, 128 threads (4 warps, 64x32 each), 2-stage, 24KB/stage.
// N arbitrary (guarded).
// ======================================================================
#define GBM      128
#define GBN      64
#define OA_ST    16384                 // 128 x 64 fp16
#define OB_ST    8192                  // 64 x 64 fp16
#define OSTAGE   (OA_ST + OB_ST)       // 24KB
#define GEMM_SMEM (2 * OSTAGE + 1024)

__device__ __forceinline__ void gemm16_body(
    const __half* __restrict__ A, const __half* __restrict__ B,
    float* __restrict__ C, int N, int K, int bm, int bn, uint32_t smem)
{
    const int tid  = threadIdx.x;
    const int wid  = tid >> 5, lane = tid & 31;
    const int wm   = (wid >> 1) * 64;
    const int wn   = (wid & 1) * 32;
    const int nchunk = K >> 6;

    auto load_chunk = [&](int c, int buf) {
        const uint32_t base = smem + buf * OSTAGE;
        const int k0 = c * 64;
#pragma unroll
        for (int u = tid; u < 1024; u += 128) {
            int row = u >> 3, seg = u & 7;
            uint32_t so = SWZ((uint32_t)(row * 128 + seg * 16));
            CP_ASYNC(base + so, A + (size_t)(bm + row) * K + k0 + seg * 8, 16);
        }
#pragma unroll
        for (int u = tid; u < 512; u += 128) {
            int row = u >> 3, seg = u & 7;
            uint32_t so = SWZ((uint32_t)(row * 128 + seg * 16));
            int n = bn + row;
            int sz = (n < N) ? 16 : 0;
            CP_ASYNC(base + OA_ST + so, B + (size_t)(n < N ? n : 0) * K + k0 + seg * 8, sz);
        }
        CP_COMMIT();
    };

    float acc[4][4][4];
#pragma unroll
    for (int i = 0; i < 4; i++)
#pragma unroll
        for (int j = 0; j < 4; j++)
#pragma unroll
            for (int q = 0; q < 4; q++) acc[i][j][q] = 0.f;

    load_chunk(0, 0);

    for (int c = 0; c < nchunk; c++) {
        const int buf = c & 1;
        if (c + 1 < nchunk) {
            load_chunk(c + 1, buf ^ 1);
            CP_WAIT(1);
        } else {
            CP_WAIT(0);
        }
        __syncthreads();

        const uint32_t sa  = smem + buf * OSTAGE;
        const uint32_t sbb = sa + OA_ST;

#pragma unroll
        for (int ks = 0; ks < 4; ks++) {
            const int kk = ks * 16;
            uint32_t ah[4][4], bh[2][4];
            {
                int r = lane & 15, ck = lane >> 4;
#pragma unroll
                for (int mt = 0; mt < 4; mt++) {
                    uint32_t off = SWZ((uint32_t)((wm + mt * 16 + r) * 128 + (kk + ck * 8) * 2));
                    ldsm4(ah[mt], sa + off);
                }
            }
            {
                int grp = lane >> 3, ln = lane & 7;
#pragma unroll
                for (int np = 0; np < 2; np++) {
                    int n = wn + np * 16 + (grp >> 1) * 8 + ln;
                    int kc = kk + (grp & 1) * 8;
                    uint32_t off = SWZ((uint32_t)(n * 128 + kc * 2));
                    ldsm4(bh[np], sbb + off);
                }
            }
#pragma unroll
            for (int mt = 0; mt < 4; mt++)
#pragma unroll
                for (int nt = 0; nt < 4; nt++)
                    mma_f16(acc[mt][nt], ah[mt], &bh[nt >> 1][(nt & 1) * 2]);
        }
        __syncthreads();
    }

#pragma unroll
    for (int mt = 0; mt < 4; mt++) {
        int r0 = bm + wm + mt * 16 + (lane >> 2);
#pragma unroll
        for (int nt = 0; nt < 4; nt++) {
            int col = bn + wn + nt * 8 + (lane & 3) * 2;
            if (col < N) {
                float* c0 = C + (size_t)r0 * N + col;
                float* c1 = C + (size_t)(r0 + 8) * N + col;
                c0[0] = acc[mt][nt][0]; c0[1] = acc[mt][nt][1];
                c1[0] = acc[mt][nt][2]; c1[1] = acc[mt][nt][3];
            }
        }
    }
}

#define QTILES  14
#define KVTILES 9
__global__ __launch_bounds__(128) void gemm_qkv(const __half* __restrict__ A)
{
    extern __shared__ char smraw[];
    const uint32_t smem0 = smem_u32(smraw);
    const uint32_t smem  = (smem0 + 1023) & ~1023u;
    const int bx = blockIdx.x;
    if (bx < QTILES)
        gemm16_body(A, g_wq16, g_abq, NQ, DM, blockIdx.y * GBM, bx * GBN, smem);
    else
        gemm16_body(A, g_wkv16, g_abkv, NKV, DM, blockIdx.y * GBM, (bx - QTILES) * GBN, smem);
}

__global__ __launch_bounds__(128) void gemm_out(
    const __half* __restrict__ A, const __half* __restrict__ B, float* __restrict__ C)
{
    extern __shared__ char smraw[];
    const uint32_t smem0 = smem_u32(smraw);
    const uint32_t smem  = (smem0 + 1023) & ~1023u;
    gemm16_body(A, B, C, DM, DM, blockIdx.y * GBM, blockIdx.x * GBN, smem);
}

// ======================================================================
// qkv: rank contraction + rotary (fp32 trig) -> single fp16 q,k,v [b,h,t,d]
// ======================================================================
__global__ __launch_bounds__(128) void qkv_kernel()
{
    const int m = blockIdx.x;
    const int b = m >> 11;
    const int t = m & (TT - 1);
    const int d = threadIdx.x;

    __shared__ float aq  [RQ][16];
    __shared__ float bq  [RQ][128];
    __shared__ float akv [RKV][16];
    __shared__ float braw[RKV][128];
    __shared__ float brot[RKV][128];

    const float* abq = g_abq + (size_t)m * NQ;
    for (int idx = d; idx < NQ; idx += 128) {
        int r = idx / CH, c = idx - r * CH;
        float v = abq[idx];
        if (c < 16) aq[r][c] = v; else bq[r][c - 16] = v;
    }
    const float* abkv = g_abkv + (size_t)m * NKV;
    for (int idx = d; idx < NKV; idx += 128) {
        int r = idx / CH, c = idx - r * CH;
        float v = abkv[idx];
        if (c < 16) akv[r][c] = v; else braw[r][c - 16] = v;
    }
    __syncthreads();

    {
        int j = d & 63;
        float inv = powf(1e-4f, (float)j * (1.f / 64.f));
        float sv, cv;
        sincosf((float)t * inv, &sv, &cv);
#pragma unroll
        for (int r = 0; r < RKV; r++) {
            float x1 = braw[r][j], x2 = braw[r][j + 64];
            brot[r][d] = (d < 64) ? (x1 * cv + x2 * sv) : (-x1 * sv + x2 * cv);
        }
    }

    const size_t base = (((size_t)b * NH) * TT + t) * DH + d;
#pragma unroll
    for (int h = 0; h < NH; h++) {
        float qv = 0.f;
#pragma unroll
        for (int r = 0; r < RQ; r++) qv += aq[r][h] * bq[r][d];
        qv *= (1.f / 6.f);
        float kv = (akv[0][h] * brot[0][d] + akv[1][h] * brot[1][d]) * 0.5f;
        float vv = (akv[2][h] * brot[2][d] + akv[3][h] * brot[3][d]) * 0.5f;
        size_t o = base + (size_t)h * TT * DH;
        g_q16[o] = __float2half(qv);
        g_k16[o] = __float2half(kv);
        g_v16[o] = __float2half(vv);
    }
}

// ======================================================================
// flash attention, causal, single-pass fp16 mma.sync.
// 128 threads (4 warps x 16 q-rows = 64-row Q tile), 32-row KV stages,
// 2-stage double buffer. smem = Q 16KB + 2x16KB = 49KB -> 3 CTAs/SM.
// ======================================================================
#define ATTN_SMEM (49152 + 1024)

__global__ __launch_bounds__(128, 3) void attn_mma()
{
    extern __shared__ char smraw[];
    const uint32_t sb0 = smem_u32(smraw);
    const uint32_t sb = (sb0 + 1023) & ~1023u;

    const int tid = threadIdx.x, wid = tid >> 5, lane = tid & 31;
    const int qt = (int)gridDim.x - 1 - (int)blockIdx.x;   // heavy tiles first
    const int h = blockIdx.y, b = blockIdx.z;
    const size_t bh = ((size_t)b * NH + h) * TT;
    const int nkt = 2 * qt + 2;                            // 32-row kv tiles

    const uint32_t sQ = sb;

    {
        const char* qp = (const char*)g_q16 + (bh + (size_t)qt * 64) * 256;
        for (int u = tid; u < 1024; u += 128) {
            int row = u >> 4, seg = u & 15;
            uint32_t off = ASW((uint32_t)(row * 256 + seg * 16));
            CP_ASYNC(sQ + off, qp + row * 256 + seg * 16, 16);
        }
    }
    auto load_kv = [&](int kt, int s) {
        uint32_t base = sb + 16384 + (uint32_t)s * 16384;
        const char* kp = (const char*)g_k16 + (bh + (size_t)kt * 32) * 256;
        const char* vp = (const char*)g_v16 + (bh + (size_t)kt * 32) * 256;
        for (int u = tid; u < 512; u += 128) {
            int row = u >> 4, seg = u & 15;
            uint32_t off = ASW((uint32_t)(row * 256 + seg * 16));
            int go = row * 256 + seg * 16;
            CP_ASYNC(base + off,        kp + go, 16);
            CP_ASYNC(base + 8192 + off, vp + go, 16);
        }
        CP_COMMIT();
    };
    load_kv(0, 0);
    if (nkt > 1) load_kv(1, 1);

    float oacc[16][4];
#pragma unroll
    for (int dt = 0; dt < 16; dt++)
#pragma unroll
        for (int e = 0; e < 4; e++) oacc[dt][e] = 0.f;
    float rM0 = -1e30f, rM1 = -1e30f, rL0 = 0.f, rL1 = 0.f;

    const float scale = 0.08838834764831845f;
    const int r0g = qt * 64 + wid * 16 + (lane >> 2);

    for (int kt = 0; kt < nkt; kt++) {
        const int s = kt & 1;
        if (kt + 1 < nkt) { CP_WAIT(1); } else { CP_WAIT(0); }
        __syncthreads();
        const uint32_t base = sb + 16384 + (uint32_t)s * 16384;
        const uint32_t sK = base, sV = base + 8192;

        float sacc[4][4];
#pragma unroll
        for (int nt = 0; nt < 4; nt++)
#pragma unroll
            for (int e = 0; e < 4; e++) sacc[nt][e] = 0.f;

        // ---- S = Q K^T (64x32), single fp16 pass ----
#pragma unroll
        for (int ks = 0; ks < 8; ks++) {
            uint32_t ah[4];
            {
                int r = lane & 15, ck = lane >> 4;
                uint32_t off = ASW((uint32_t)((wid * 16 + r) * 256 + (ks * 16 + ck * 8) * 2));
                ldsm4(ah, sQ + off);
            }
            uint32_t bh4[2][4];
            {
                int grp = lane >> 3, ln = lane & 7;
#pragma unroll
                for (int ng = 0; ng < 2; ng++) {
                    int n = ng * 16 + (grp >> 1) * 8 + ln;
                    int kc = ks * 16 + (grp & 1) * 8;
                    uint32_t off = ASW((uint32_t)(n * 256 + kc * 2));
                    ldsm4(bh4[ng], sK + off);
                }
            }
#pragma unroll
            for (int ng = 0; ng < 2; ng++) {
                mma_f16(sacc[ng * 2],     ah, bh4[ng]);
                mma_f16(sacc[ng * 2 + 1], ah, bh4[ng] + 2);
            }
        }

        const bool domask = (kt >= 2 * qt);
        float mx0 = -1e30f, mx1 = -1e30f;
#pragma unroll
        for (int nt = 0; nt < 4; nt++) {
            int c0 = kt * 32 + nt * 8 + (lane & 3) * 2;
#pragma unroll
            for (int e = 0; e < 4; e++) {
                float v = sacc[nt][e] * scale;
                if (domask) {
                    int cc = c0 + (e & 1);
                    int rr = r0g + ((e >> 1) << 3);
                    if (cc > rr) v = -1e30f;
                }
                sacc[nt][e] = v;
            }
            mx0 = fmaxf(mx0, fmaxf(sacc[nt][0], sacc[nt][1]));
            mx1 = fmaxf(mx1, fmaxf(sacc[nt][2], sacc[nt][3]));
        }
        mx0 = fmaxf(mx0, __shfl_xor_sync(0xffffffffu, mx0, 1));
        mx0 = fmaxf(mx0, __shfl_xor_sync(0xffffffffu, mx0, 2));
        mx1 = fmaxf(mx1, __shfl_xor_sync(0xffffffffu, mx1, 1));
        mx1 = fmaxf(mx1, __shfl_xor_sync(0xffffffffu, mx1, 2));

        float nM0 = fmaxf(rM0, mx0), nM1 = fmaxf(rM1, mx1);
        float cor0 = __expf(rM0 - nM0), cor1 = __expf(rM1 - nM1);
        rM0 = nM0; rM1 = nM1;

        float sum0 = 0.f, sum1 = 0.f;
        uint32_t pH01[4], pH23[4];
#pragma unroll
        for (int nt = 0; nt < 4; nt++) {
            float p0 = __expf(sacc[nt][0] - nM0);
            float p1 = __expf(sacc[nt][1] - nM0);
            float p2 = __expf(sacc[nt][2] - nM1);
            float p3 = __expf(sacc[nt][3] - nM1);
            sum0 += p0 + p1; sum1 += p2 + p3;
            pH01[nt] = pack_h2(__float2half(p0), __float2half(p1));
            pH23[nt] = pack_h2(__float2half(p2), __float2half(p3));
        }
        sum0 += __shfl_xor_sync(0xffffffffu, sum0, 1);
        sum0 += __shfl_xor_sync(0xffffffffu, sum0, 2);
        sum1 += __shfl_xor_sync(0xffffffffu, sum1, 1);
        sum1 += __shfl_xor_sync(0xffffffffu, sum1, 2);
        rL0 = rL0 * cor0 + sum0;
        rL1 = rL1 * cor1 + sum1;

#pragma unroll
        for (int dt = 0; dt < 16; dt++) {
            oacc[dt][0] *= cor0; oacc[dt][1] *= cor0;
            oacc[dt][2] *= cor1; oacc[dt][3] *= cor1;
        }

        // ---- O += P V: single fp16 pass ----
#pragma unroll
        for (int k2 = 0; k2 < 2; k2++) {
            uint32_t aH[4] = {pH01[2 * k2], pH23[2 * k2], pH01[2 * k2 + 1], pH23[2 * k2 + 1]};
            int krow = k2 * 16 + ((lane >> 3) & 1) * 8 + (lane & 7);
#pragma unroll
            for (int dh2 = 0; dh2 < 2; dh2++) {
                uint32_t vh4[4][4];
#pragma unroll
                for (int dq = 0; dq < 4; dq++) {
                    int dcol = (dh2 * 4 + dq) * 16 + (lane >> 4) * 8;
                    uint32_t off = ASW((uint32_t)(krow * 256 + dcol * 2));
                    ldsm4t(vh4[dq], sV + off);
                }
#pragma unroll
                for (int dq = 0; dq < 4; dq++) {
                    int dg = dh2 * 4 + dq;
                    mma_f16(oacc[dg * 2],     aH, vh4[dq]);
                    mma_f16(oacc[dg * 2 + 1], aH, vh4[dq] + 2);
                }
            }
        }
        __syncthreads();
        if (kt + 2 < nkt) load_kv(kt + 2, s);
    }

    // ---- normalize + store single-fp16 y ----
    float il0 = 1.f / rL0, il1 = 1.f / rL1;
    size_t row0 = ((size_t)b * TT + r0g) * DM + h * DH;
    size_t row1 = row0 + (size_t)8 * DM;
#pragma unroll
    for (int dt = 0; dt < 16; dt++) {
        int c = dt * 8 + (lane & 3) * 2;
        *(uint32_t*)(g_y16 + row0 + c) = pack_h2(__float2half(oacc[dt][0] * il0),
                                                 __float2half(oacc[dt][1] * il0));
        *(uint32_t*)(g_y16 + row1 + c) = pack_h2(__float2half(oacc[dt][2] * il1),
                                                 __float2half(oacc[dt][3] * il1));
    }
}

// ======================================================================
extern "C" void kernel_launch(void* const* d_in, const int* in_sizes, int n_in,
                              void* d_out, int out_size)
{
    const float* x   = (const float*)d_in[0];
    const float* Wq  = (const float*)d_in[1];
    const float* Wkv = (const float*)d_in[2];
    const float* Wo  = (const float*)d_in[3];
    float* out = (float*)d_out;

    __half *x16, *wq16, *wkv16, *wo16, *y16;
    cudaGetSymbolAddress((void**)&x16,   g_x16);
    cudaGetSymbolAddress((void**)&wq16,  g_wq16);
    cudaGetSymbolAddress((void**)&wkv16, g_wkv16);
    cudaGetSymbolAddress((void**)&wo16,  g_wo16);
    cudaGetSymbolAddress((void**)&y16,   g_y16);

    cudaFuncSetAttribute(gemm_qkv, cudaFuncAttributeMaxDynamicSharedMemorySize, GEMM_SMEM);
    cudaFuncSetAttribute(gemm_out, cudaFuncAttributeMaxDynamicSharedMemorySize, GEMM_SMEM);
    cudaFuncSetAttribute(attn_mma, cudaFuncAttributeMaxDynamicSharedMemorySize, ATTN_SMEM);

    // 0) fp32 -> fp16 conversions (one launch)
    {
        int n0 = BT * DM, n1 = NQ * DM, n2 = NKV * DM, n3 = DM * DM;
        conv_all<<<(n0 + n1 + n2 + n3 + 255) / 256, 256>>>(
            x, x16, n0, Wq, wq16, n1, Wkv, wkv16, n2, Wo, wo16, n3);
    }
    // 1) fused ab_q / ab_kv projections (single fp16 pass)
    {
        dim3 g(QTILES + KVTILES, BT / GBM);
        gemm_qkv<<<g, 128, GEMM_SMEM>>>(x16);
    }
    // 2) q,k,v (+rotary) -> single fp16
    qkv_kernel<<<BT, 128>>>();
    // 3) causal attention (single-pass fp16, 3 CTAs/SM) -> y16
    {
        dim3 g(TT / 64, NH, NB);
        attn_mma<<<g, 128, ATTN_SMEM>>>();
    }
    // 4) out = y16 @ Wo16^T, single fp16 pass
    {
        dim3 g(DM / GBN, BT / GBM);
        gemm_out<<<g, 128, GEMM_SMEM>>>(y16, wo16, out);
    }
}